// round 8
// baseline (speedup 1.0000x reference)
#include <cuda_runtime.h>
#include <cstdint>

// ---------------------------------------------------------------------------
// Stage3 LSTM stack: out1 = input4
//                    out7 = LSTM1(concat(input0, input4))
//                    out11 = LSTM2(concat(out7, input4)) + out7
//                    out14 = concat(out11, input4)
// Outputs concatenated: [out1 (T*B*H)] [out11 (T*B*H)] [out14 (T*B*2H)]
// ---------------------------------------------------------------------------

#define Tt 128
#define Bb 128
#define Hh 1024
#define Ii 2048
#define G4 4096            // 4*H
#define TB 16384           // T*B
#define LDSW 36            // smem row stride in floats (32 + 4 pad)
#define NBLK 128           // persistent blocks (1 per SM)

// -------------------- device scratch (no allocs allowed) --------------------
__device__ float g_wih1[G4 * Ii];   // gate-interleaved rows + k-qperm cols, tf32
__device__ float g_whh1[G4 * Hh];   // gate-interleaved rows, natural cols, tf32
__device__ float g_b1[G4];
__device__ float g_wih2[G4 * Ii];
__device__ float g_whh2[G4 * Hh];
__device__ float g_b2[G4];
__device__ float g_aperm1[(size_t)TB * Ii];  // layer-1 A: [input0|input4], permuted+tf32
__device__ float g_aperm2[(size_t)TB * Ii];  // layer-2 A: [h1|input4], permuted+tf32
__device__ float g_xp[(size_t)TB * G4];      // input projection for current layer
__device__ float g_h1[(size_t)TB * Hh];      // layer-1 h (natural layout, = out7)
__device__ float g_hperm[4][Bb * Hh];        // 4-deep ring: h, col-permuted + tf32
__device__ unsigned g_flag[NBLK];            // per-producer step flags (t+1)

// -------------------- helpers --------------------
static __device__ __forceinline__ unsigned f2tf(float x) {
    unsigned u;
    asm("cvt.rna.tf32.f32 %0, %1;" : "=r"(u) : "f"(x));
    return u;
}

static __device__ __forceinline__ void mma_tf32(float c[4], const unsigned a[4],
                                                const unsigned b[2]) {
    asm volatile(
        "mma.sync.aligned.m16n8k8.row.col.f32.tf32.tf32.f32 "
        "{%0,%1,%2,%3}, {%4,%5,%6,%7}, {%8,%9}, {%0,%1,%2,%3};\n"
        : "+f"(c[0]), "+f"(c[1]), "+f"(c[2]), "+f"(c[3])
        : "r"(a[0]), "r"(a[1]), "r"(a[2]), "r"(a[3]), "r"(b[0]), "r"(b[1]));
}

// column permutation within a 32-wide K chunk: stored(kl) = (kl%4)*8 + kl/4
static __device__ __forceinline__ int qperm(int kl) {
    return ((kl & 3) << 3) + (kl >> 2);
}

static __device__ __forceinline__ void cpa16(unsigned dst, const float* src) {
    asm volatile("cp.async.cg.shared.global [%0], [%1], 16;\n" :: "r"(dst), "l"(src));
}

// fast activations (MUFU-backed, rel err ~1e-6)
static __device__ __forceinline__ float fsigmoid(float x) {
    return __fdividef(1.f, 1.f + __expf(-x));
}
static __device__ __forceinline__ float ftanh(float x) {
    return __fdividef(2.f, 1.f + __expf(-2.f * x)) - 1.f;
}

// -------------------- fused per-layer weight/bias permutation ----------------
template <int L>
__global__ void permute_l(const float* __restrict__ wih, const float* __restrict__ whh,
                          const float* __restrict__ bih, const float* __restrict__ bhh) {
    int idx = blockIdx.x * 256 + threadIdx.x;
    float* wo = (L == 1) ? g_wih1 : g_wih2;
    float* ho = (L == 1) ? g_whh1 : g_whh2;
    float* bo = (L == 1) ? g_b1 : g_b2;
    if (idx < G4 * Ii) {
        int n = idx >> 11, k = idx & 2047;
        int j = n >> 2, g = n & 3;
        float v = wih[((g * Hh + j) << 11) + k];
        int kp = (k & ~31) | qperm(k & 31);
        wo[(n << 11) | kp] = __uint_as_float(f2tf(v));
    } else if (idx < G4 * Ii + G4 * Hh) {
        int i2 = idx - G4 * Ii;
        int n = i2 >> 10, k = i2 & 1023;
        int j = n >> 2, g = n & 3;
        ho[(n << 10) + k] = __uint_as_float(f2tf(whh[((g * Hh + j) << 10) + k]));
    } else {
        int n = idx - G4 * Ii - G4 * Hh;
        int j = n >> 2, g = n & 3;
        bo[n] = bih[g * Hh + j] + bhh[g * Hh + j];
        if (L == 2 && n < NBLK) g_flag[n] = 0;   // reset flags for layer-2 pass
    }
}

// -------------------- A prepass: permuted + tf32-rounded ---------------------
__global__ void prepA(const float* __restrict__ in0, const float* __restrict__ in4) {
    int idx = blockIdx.x * 256 + threadIdx.x;
    if (idx < NBLK) g_flag[idx] = 0;   // reset flags for layer-1 pass
    int row = idx >> 11;
    int k = idx & 2047;
    int kp = (k & ~31) | qperm(k & 31);
    float v = (k < 1024) ? in0[(size_t)row * Hh + k]
                         : in4[(size_t)row * Hh + (k - 1024)];
    float tv = __uint_as_float(f2tf(v));
    g_aperm1[(size_t)row * Ii + kp] = tv;
    if (k >= 1024) g_aperm2[(size_t)row * Ii + kp] = tv;
}

// -------------------- out1 + out14 second-half copy --------------------
__global__ void copy_out1(const float* __restrict__ in4, float* __restrict__ out) {
    size_t i4 = (size_t)blockIdx.x * 256 + threadIdx.x;
    size_t e = i4 * 4;
    float4 v = *(const float4*)(in4 + e);
    *(float4*)(out + e) = v;                       // out1
    size_t tb = e >> 10;
    size_t j = e & (Hh - 1);
    *(float4*)(out + (size_t)2 * TB * Hh + tb * 2 * Hh + Hh + j) = v;  // out14[:,H:]
}

// -------------------- big GEMM: xp = Aperm @ W'^T + bias' -------------------
#define GXS 4608                       // floats per stage per operand (128*LDSW)
#define GEMM_SMEM_FL (6 * GXS)         // 3 stages x (A,B) = 110592 bytes

template <int L>
__global__ void __launch_bounds__(256, 2)
gemm_xp() {
    const float* Ag = (L == 1) ? g_aperm1 : g_aperm2;
    const float* Wg = (L == 1) ? g_wih1 : g_wih2;
    const float* bias = (L == 1) ? g_b1 : g_b2;

    extern __shared__ float smem[];
    const unsigned smem_u32 = (unsigned)__cvta_generic_to_shared(smem);

    const int tid = threadIdx.x;
    const int lane = tid & 31;
    const int warp = tid >> 5;
    const int wm = (warp >> 1) << 5;   // 0,32,64,96
    const int wn = (warp & 1) << 6;    // 0,64
    const int lr = lane >> 2, lc = lane & 3;
    const int m0 = blockIdx.y * 128;
    const int n0 = blockIdx.x * 128;
    const int frow = tid >> 3, fqc = (tid & 7) << 2;

    float acc[2][8][4];
#pragma unroll
    for (int i = 0; i < 2; i++)
#pragma unroll
        for (int j = 0; j < 8; j++)
#pragma unroll
            for (int k = 0; k < 4; k++) acc[i][j][k] = 0.f;

    const float* Abase = Ag + (size_t)(m0 + frow) * Ii + fqc;
    const float* Bbase = Wg + (size_t)(n0 + frow) * Ii + fqc;
    const unsigned doff = (unsigned)(frow * LDSW + fqc) * 4;

#pragma unroll
    for (int pc = 0; pc < 2; pc++) {
        unsigned sa = smem_u32 + (pc * 2 * GXS) * 4 + doff;
        unsigned sb = smem_u32 + (pc * 2 * GXS + GXS) * 4 + doff;
#pragma unroll
        for (int i = 0; i < 4; i++) {
            cpa16(sa + (unsigned)(i * 32 * LDSW) * 4, Abase + (size_t)(i * 32) * Ii + pc * 32);
            cpa16(sb + (unsigned)(i * 32 * LDSW) * 4, Bbase + (size_t)(i * 32) * Ii + pc * 32);
        }
        asm volatile("cp.async.commit_group;\n" ::: "memory");
    }

    for (int kc = 0; kc < 64; kc++) {
        if (kc < 62) {
            int nc = kc + 2;
            int st = nc % 3;
            unsigned sa = smem_u32 + (st * 2 * GXS) * 4 + doff;
            unsigned sb = smem_u32 + (st * 2 * GXS + GXS) * 4 + doff;
#pragma unroll
            for (int i = 0; i < 4; i++) {
                cpa16(sa + (unsigned)(i * 32 * LDSW) * 4, Abase + (size_t)(i * 32) * Ii + nc * 32);
                cpa16(sb + (unsigned)(i * 32 * LDSW) * 4, Bbase + (size_t)(i * 32) * Ii + nc * 32);
            }
            asm volatile("cp.async.commit_group;\n" ::: "memory");
            asm volatile("cp.async.wait_group 2;\n" ::: "memory");
        } else if (kc == 62) {
            asm volatile("cp.async.wait_group 1;\n" ::: "memory");
        } else {
            asm volatile("cp.async.wait_group 0;\n" ::: "memory");
        }
        __syncthreads();

        const float* Ast = smem + (kc % 3) * 2 * GXS;
        const float* Bst = Ast + GXS;

        unsigned a[4][8];
#pragma unroll
        for (int i = 0; i < 4; i++) {
            int r = wm + ((i >> 1) << 4) + ((i & 1) << 3) + lr;
            const float4* p = (const float4*)&Ast[r * LDSW + lc * 8];
            float4 v0 = p[0], v1 = p[1];
            a[i][0] = __float_as_uint(v0.x); a[i][1] = __float_as_uint(v0.y);
            a[i][2] = __float_as_uint(v0.z); a[i][3] = __float_as_uint(v0.w);
            a[i][4] = __float_as_uint(v1.x); a[i][5] = __float_as_uint(v1.y);
            a[i][6] = __float_as_uint(v1.z); a[i][7] = __float_as_uint(v1.w);
        }

#pragma unroll
        for (int nt2 = 0; nt2 < 4; nt2++) {
            unsigned b0[8], b1[8];
            {
                int rb = wn + (2 * nt2) * 8 + lr;
                const float4* p = (const float4*)&Bst[rb * LDSW + lc * 8];
                float4 v0 = p[0], v1 = p[1];
                b0[0] = __float_as_uint(v0.x); b0[1] = __float_as_uint(v0.y);
                b0[2] = __float_as_uint(v0.z); b0[3] = __float_as_uint(v0.w);
                b0[4] = __float_as_uint(v1.x); b0[5] = __float_as_uint(v1.y);
                b0[6] = __float_as_uint(v1.z); b0[7] = __float_as_uint(v1.w);
            }
            {
                int rb = wn + (2 * nt2 + 1) * 8 + lr;
                const float4* p = (const float4*)&Bst[rb * LDSW + lc * 8];
                float4 v0 = p[0], v1 = p[1];
                b1[0] = __float_as_uint(v0.x); b1[1] = __float_as_uint(v0.y);
                b1[2] = __float_as_uint(v0.z); b1[3] = __float_as_uint(v0.w);
                b1[4] = __float_as_uint(v1.x); b1[5] = __float_as_uint(v1.y);
                b1[6] = __float_as_uint(v1.z); b1[7] = __float_as_uint(v1.w);
            }
#pragma unroll
            for (int kk = 0; kk < 4; kk++) {
                unsigned afr0[4] = {a[0][2 * kk], a[1][2 * kk],
                                    a[0][2 * kk + 1], a[1][2 * kk + 1]};
                unsigned afr1[4] = {a[2][2 * kk], a[3][2 * kk],
                                    a[2][2 * kk + 1], a[3][2 * kk + 1]};
                unsigned bfr0[2] = {b0[2 * kk], b0[2 * kk + 1]};
                unsigned bfr1[2] = {b1[2 * kk], b1[2 * kk + 1]};
                mma_tf32(acc[0][2 * nt2], afr0, bfr0);
                mma_tf32(acc[0][2 * nt2 + 1], afr0, bfr1);
                mma_tf32(acc[1][2 * nt2], afr1, bfr0);
                mma_tf32(acc[1][2 * nt2 + 1], afr1, bfr1);
            }
        }
        __syncthreads();
    }

#pragma unroll
    for (int mt = 0; mt < 2; mt++) {
        int r = m0 + wm + mt * 16 + lr;
#pragma unroll
        for (int nt = 0; nt < 8; nt++) {
            int c = n0 + wn + nt * 8 + 2 * lc;
            float2 bv = *(const float2*)&bias[c];
            float2 v0 = make_float2(acc[mt][nt][0] + bv.x, acc[mt][nt][1] + bv.y);
            float2 v1 = make_float2(acc[mt][nt][2] + bv.x, acc[mt][nt][3] + bv.y);
            *(float2*)&g_xp[(size_t)r * G4 + c] = v0;
            *(float2*)&g_xp[(size_t)(r + 8) * G4 + c] = v1;
        }
    }
}

// -------------------- persistent recurrent layer --------------------
// 128 CTAs x 512 threads (16 warps). CTA owns 32 gate-cols (8 hidden units).
// 2-way k-split: warps 0-7 k[0,512), warps 8-15 k[512,1024).
// NO global barrier: producer CTA bid publishes its hperm slice with a
// st.release flag; consumer warps acquire-poll only the 64 producers of their
// k-half. 4-deep hperm ring makes the anti-dependency implied by the flag
// chain (epilogue(t) => all CTAs past GEMM(t-1) => past GEMM(t-3), the last
// readers of buffer t&3).
#define SM2_WS_LD 1028                  // 1028 % 32 == 4 -> conflict-free frags
#define SM2_GS  (32 * SM2_WS_LD)        // Ws: 32896 floats
#define SM2_XS  (SM2_GS + 2 * 128 * LDSW)   // 2 Gs buffers then 2 xp stages
#define SM2_FL  (SM2_XS + 2 * 128 * LDSW)   // 51328 floats = 205312 bytes

template <int L>
__global__ void __launch_bounds__(512, 1)
lstm_layer(float* __restrict__ dout) {
    extern __shared__ float smem[];
    float* Ws = smem;
    float* Gs0 = smem + SM2_GS;
    float* Gs1 = Gs0 + 128 * LDSW;
    const unsigned smem_u32 = (unsigned)__cvta_generic_to_shared(smem);

    const int tid = threadIdx.x;
    const int bid = blockIdx.x;
    const int lane = tid & 31;
    const int warp = tid >> 5;         // 0..15
    const int wk = warp >> 3;          // k-half: 0 or 1
    const int wm = (warp & 7) << 4;    // batch row base: 0,16,...,112
    const int lr = lane >> 2, lc = lane & 3;
    const int n0 = bid * 32;           // gate-col base
    float* GsW = wk ? Gs1 : Gs0;

    const float* Wg = (L == 1) ? g_whh1 : g_whh2;

    // load W slice into smem with per-chunk column permutation
    for (int idx = tid; idx < 32 * 1024; idx += 512) {
        int n = idx >> 10;
        int k = idx & 1023;
        int kc = (k & ~31) + qperm(k & 31);
        Ws[n * SM2_WS_LD + kc] = Wg[(size_t)(n0 + n) * Hh + k];
    }
    // prefetch xp tile for t=0 into stage 0
    {
        unsigned xb = smem_u32 + SM2_XS * 4;
#pragma unroll
        for (int i = 0; i < 2; i++) {
            int u = tid + (i << 9);
            int b = u >> 3, q = u & 7;
            cpa16(xb + (unsigned)(b * LDSW + q * 4) * 4,
                  g_xp + (size_t)b * G4 + n0 + q * 4);
        }
        asm volatile("cp.async.commit_group;\n" ::: "memory");
    }
    __syncthreads();

    float creg[2];
    creg[0] = 0.f; creg[1] = 0.f;

    for (int t = 0; t < Tt; t++) {
        // hoisted prefetch: next step's xp tile (independent of h dataflow)
        if (t + 1 < Tt) {
            const float* xpn = g_xp + (size_t)(t + 1) * Bb * G4;
            unsigned xb = smem_u32 + (SM2_XS + ((t + 1) & 1) * (128 * LDSW)) * 4;
#pragma unroll
            for (int i = 0; i < 2; i++) {
                int u = tid + (i << 9);
                int b = u >> 3, q = u & 7;
                cpa16(xb + (unsigned)(b * LDSW + q * 4) * 4,
                      xpn + (size_t)b * G4 + n0 + q * 4);
            }
            asm volatile("cp.async.commit_group;\n" ::: "memory");
        }

        float acc[4][4];
#pragma unroll
        for (int j = 0; j < 4; j++)
#pragma unroll
            for (int k = 0; k < 4; k++) acc[j][k] = 0.f;

        if (t > 0) {
            // acquire-wait for this k-half's 64 producers (2 flags per lane)
            {
                const unsigned* fp = g_flag + wk * 64 + (lane << 1);
                unsigned v0, v1;
                do {
                    asm volatile("ld.global.acquire.gpu.u32 %0, [%1];"
                                 : "=r"(v0) : "l"(fp) : "memory");
                    asm volatile("ld.global.acquire.gpu.u32 %0, [%1];"
                                 : "=r"(v1) : "l"(fp + 1) : "memory");
                } while (v0 < (unsigned)t || v1 < (unsigned)t);
                __syncwarp();
            }

            const float* hp = g_hperm[(t - 1) & 3] + wk * 512;
            const float* r0 = hp + (size_t)(wm + lr) * Hh + lc * 8;
            const float* r1 = hp + (size_t)(wm + 8 + lr) * Hh + lc * 8;

            float4 cur[4], nxt[4];
            cur[0] = __ldcg((const float4*)r0); cur[1] = __ldcg((const float4*)(r0 + 4));
            cur[2] = __ldcg((const float4*)r1); cur[3] = __ldcg((const float4*)(r1 + 4));

            for (int kc = 0; kc < 16; kc++) {
                if (kc < 15) {
                    int o = (kc + 1) * 32;
                    nxt[0] = __ldcg((const float4*)(r0 + o));
                    nxt[1] = __ldcg((const float4*)(r0 + o + 4));
                    nxt[2] = __ldcg((const float4*)(r1 + o));
                    nxt[3] = __ldcg((const float4*)(r1 + o + 4));
                }
                unsigned bb[4][8];
#pragma unroll
                for (int nt = 0; nt < 4; nt++) {
                    const float4* p =
                        (const float4*)&Ws[(nt * 8 + lr) * SM2_WS_LD + wk * 512 + kc * 32 + lc * 8];
                    float4 v0 = p[0], v1 = p[1];
                    bb[nt][0] = __float_as_uint(v0.x); bb[nt][1] = __float_as_uint(v0.y);
                    bb[nt][2] = __float_as_uint(v0.z); bb[nt][3] = __float_as_uint(v0.w);
                    bb[nt][4] = __float_as_uint(v1.x); bb[nt][5] = __float_as_uint(v1.y);
                    bb[nt][6] = __float_as_uint(v1.z); bb[nt][7] = __float_as_uint(v1.w);
                }
                unsigned a0[8] = {__float_as_uint(cur[0].x), __float_as_uint(cur[0].y),
                                  __float_as_uint(cur[0].z), __float_as_uint(cur[0].w),
                                  __float_as_uint(cur[1].x), __float_as_uint(cur[1].y),
                                  __float_as_uint(cur[1].z), __float_as_uint(cur[1].w)};
                unsigned a1[8] = {__float_as_uint(cur[2].x), __float_as_uint(cur[2].y),
                                  __float_as_uint(cur[2].z), __float_as_uint(cur[2].w),
                                  __float_as_uint(cur[3].x), __float_as_uint(cur[3].y),
                                  __float_as_uint(cur[3].z), __float_as_uint(cur[3].w)};
#pragma unroll
                for (int kk = 0; kk < 4; kk++) {
                    unsigned afr[4] = {a0[2 * kk], a1[2 * kk],
                                       a0[2 * kk + 1], a1[2 * kk + 1]};
#pragma unroll
                    for (int nt = 0; nt < 4; nt++) {
                        unsigned bfr[2] = {bb[nt][2 * kk], bb[nt][2 * kk + 1]};
                        mma_tf32(acc[nt], afr, bfr);
                    }
                }
                if (kc < 15) {
#pragma unroll
                    for (int i = 0; i < 4; i++) cur[i] = nxt[i];
                }
            }
        }

        // stash partial gates to this k-half's buffer (16 rows per warp)
#pragma unroll
        for (int nt = 0; nt < 4; nt++) {
            int c = nt * 8 + 2 * lc;
            *(float2*)&GsW[(wm + lr) * LDSW + c] = make_float2(acc[nt][0], acc[nt][1]);
            *(float2*)&GsW[(wm + 8 + lr) * LDSW + c] = make_float2(acc[nt][2], acc[nt][3]);
        }
        // xp(t) must be resident: allow the in-flight xp(t+1) group to pend
        if (t + 1 < Tt) {
            asm volatile("cp.async.wait_group 1;\n" ::: "memory");
        } else {
            asm volatile("cp.async.wait_group 0;\n" ::: "memory");
        }
        __syncthreads();

        // ---- epilogue phase A: cell update + hperm write (critical path) ----
        const float* Xs = smem + SM2_XS + (t & 1) * (128 * LDSW);
        float* hpw = g_hperm[t & 3];
        float hv_s[2];
        int b_s[2], j_s[2];
#pragma unroll
        for (int i = 0; i < 2; i++) {
            int u = tid + (i << 9);
            int b = u >> 3;
            int jl = u & 7;
            float4 x4 = *(const float4*)&Xs[b * LDSW + (jl << 2)];
            float4 p0 = *(const float4*)&Gs0[b * LDSW + (jl << 2)];
            float4 p1 = *(const float4*)&Gs1[b * LDSW + (jl << 2)];
            float gi = p0.x + p1.x + x4.x;
            float gf = p0.y + p1.y + x4.y;
            float gg = p0.z + p1.z + x4.z;
            float go = p0.w + p1.w + x4.w;
            float iv = fsigmoid(gi);
            float fv = fsigmoid(gf);
            float gv = ftanh(gg);
            float ov = fsigmoid(go);
            float cv = fv * creg[i] + iv * gv;
            creg[i] = cv;
            float hv = ov * ftanh(cv);
            int j = (n0 >> 2) + jl;
            int kc = (j & ~31) + qperm(j & 31);
            hpw[b * Hh + kc] = __uint_as_float(f2tf(hv));
            hv_s[i] = hv; b_s[i] = b; j_s[i] = j;
        }
        __syncthreads();   // all hperm writes done (cumulative release below)
        if (tid == 0) {
            asm volatile("st.global.release.gpu.u32 [%0], %1;"
                         :: "l"(g_flag + bid), "r"((unsigned)(t + 1)) : "memory");
        }

        // ---- epilogue phase B: non-critical writes (after flag publish) ----
#pragma unroll
        for (int i = 0; i < 2; i++) {
            int b = b_s[i], j = j_s[i];
            float hv = hv_s[i];
            size_t hi = (size_t)t * Bb * Hh + b * Hh + j;
            if (L == 1) {
                g_h1[hi] = hv;                                   // residual source
                int kc = (j & ~31) + qperm(j & 31);
                g_aperm2[(size_t)(t * Bb + b) * Ii + kc] =
                    __uint_as_float(f2tf(hv));                   // layer-2 GEMM A
            } else {
                float o11 = hv + g_h1[hi];
                dout[(size_t)TB * Hh + hi] = o11;                                   // out11
                dout[(size_t)2 * TB * Hh + ((size_t)(t * Bb + b)) * 2 * Hh + j] = o11;  // out14[:,:H]
            }
        }
    }
}

// -------------------- launch --------------------
extern "C" void kernel_launch(void* const* d_in, const int* in_sizes, int n_in,
                              void* d_out, int out_size) {
    const float* input4 = (const float*)d_in[0];
    const float* input0 = (const float*)d_in[1];
    const float* w_ih6  = (const float*)d_in[2];
    const float* w_hh6  = (const float*)d_in[3];
    const float* b_ih6  = (const float*)d_in[4];
    const float* b_hh6  = (const float*)d_in[5];
    const float* w_ih10 = (const float*)d_in[6];
    const float* w_hh10 = (const float*)d_in[7];
    const float* b_ih10 = (const float*)d_in[8];
    const float* b_hh10 = (const float*)d_in[9];
    float* out = (float*)d_out;

    cudaFuncSetAttribute(lstm_layer<1>, cudaFuncAttributeMaxDynamicSharedMemorySize,
                         SM2_FL * 4);
    cudaFuncSetAttribute(lstm_layer<2>, cudaFuncAttributeMaxDynamicSharedMemorySize,
                         SM2_FL * 4);
    cudaFuncSetAttribute(gemm_xp<1>, cudaFuncAttributeMaxDynamicSharedMemorySize,
                         GEMM_SMEM_FL * 4);
    cudaFuncSetAttribute(gemm_xp<2>, cudaFuncAttributeMaxDynamicSharedMemorySize,
                         GEMM_SMEM_FL * 4);

    dim3 gx(G4 / 128, TB / 128);  // n-tile fastest -> A reuse in L2
    const int PW_GRID = (G4 * (Ii + Hh + 1)) / 256;  // 49168

    // launch order arranged so ncu's capture window lands on lstm_layer<1> (idx 3)
    permute_l<1><<<PW_GRID, 256>>>(w_ih6, w_hh6, b_ih6, b_hh6);      // 0
    prepA<<<(TB * Ii) / 256, 256>>>(input0, input4);                  // 1 (+flag reset)
    gemm_xp<1><<<gx, 256, GEMM_SMEM_FL * 4>>>();                      // 2
    lstm_layer<1><<<NBLK, 512, SM2_FL * 4>>>(out);                    // 3 <- profile me
    permute_l<2><<<PW_GRID, 256>>>(w_ih10, w_hh10, b_ih10, b_hh10);   // 4 (+flag reset)
    gemm_xp<2><<<gx, 256, GEMM_SMEM_FL * 4>>>();                      // 5
    lstm_layer<2><<<NBLK, 512, SM2_FL * 4>>>(out);                    // 6
    copy_out1<<<(TB * Hh / 4) / 256, 256>>>(input4, out);             // 7
}

// round 9
// speedup vs baseline: 1.0990x; 1.0990x over previous
#include <cuda_runtime.h>
#include <cstdint>

// ---------------------------------------------------------------------------
// Stage3 LSTM stack: out1 = input4
//                    out7 = LSTM1(concat(input0, input4))
//                    out11 = LSTM2(concat(out7, input4)) + out7
//                    out14 = concat(out11, input4)
// Outputs concatenated: [out1 (T*B*H)] [out11 (T*B*H)] [out14 (T*B*2H)]
// ---------------------------------------------------------------------------

#define Tt 128
#define Bb 128
#define Hh 1024
#define Ii 2048
#define G4 4096            // 4*H
#define TB 16384           // T*B
#define LDSW 36            // smem row stride in floats (32 + 4 pad)
#define NBLK 128           // persistent blocks (1 per SM)

// -------------------- device scratch (no allocs allowed) --------------------
__device__ float g_wih1[G4 * Ii];   // gate-interleaved rows + k-qperm cols, tf32
__device__ float g_whh1[G4 * Hh];   // gate-interleaved rows, natural cols, tf32
__device__ float g_b1[G4];
__device__ float g_wih2[G4 * Ii];
__device__ float g_whh2[G4 * Hh];
__device__ float g_b2[G4];
__device__ float g_aperm1[(size_t)TB * Ii];  // layer-1 A: [input0|input4], permuted+tf32
__device__ float g_aperm2[(size_t)TB * Ii];  // layer-2 A: [h1|input4], permuted+tf32
__device__ float g_xp[(size_t)TB * G4];      // input projection for current layer
__device__ float g_h1[(size_t)TB * Hh];      // layer-1 h (natural layout, = out7)
__device__ float g_hperm[2][Bb * Hh];        // ping-pong h, col-permuted + tf32
__device__ unsigned g_sync;                  // grid barrier counter

// -------------------- helpers --------------------
static __device__ __forceinline__ unsigned f2tf(float x) {
    unsigned u;
    asm("cvt.rna.tf32.f32 %0, %1;" : "=r"(u) : "f"(x));
    return u;
}

static __device__ __forceinline__ void mma_tf32(float c[4], const unsigned a[4],
                                                const unsigned b[2]) {
    asm volatile(
        "mma.sync.aligned.m16n8k8.row.col.f32.tf32.tf32.f32 "
        "{%0,%1,%2,%3}, {%4,%5,%6,%7}, {%8,%9}, {%0,%1,%2,%3};\n"
        : "+f"(c[0]), "+f"(c[1]), "+f"(c[2]), "+f"(c[3])
        : "r"(a[0]), "r"(a[1]), "r"(a[2]), "r"(a[3]), "r"(b[0]), "r"(b[1]));
}

// column permutation within a 32-wide K chunk: stored(kl) = (kl%4)*8 + kl/4
static __device__ __forceinline__ int qperm(int kl) {
    return ((kl & 3) << 3) + (kl >> 2);
}

static __device__ __forceinline__ void cpa16(unsigned dst, const float* src) {
    asm volatile("cp.async.cg.shared.global [%0], [%1], 16;\n" :: "r"(dst), "l"(src));
}

// fast activations (MUFU-backed, rel err ~1e-6)
static __device__ __forceinline__ float fsigmoid(float x) {
    return __fdividef(1.f, 1.f + __expf(-x));
}
static __device__ __forceinline__ float ftanh(float x) {
    return __fdividef(2.f, 1.f + __expf(-2.f * x)) - 1.f;
}

// -------------------- fused per-layer weight/bias permutation ----------------
template <int L>
__global__ void permute_l(const float* __restrict__ wih, const float* __restrict__ whh,
                          const float* __restrict__ bih, const float* __restrict__ bhh) {
    int idx = blockIdx.x * 256 + threadIdx.x;
    float* wo = (L == 1) ? g_wih1 : g_wih2;
    float* ho = (L == 1) ? g_whh1 : g_whh2;
    float* bo = (L == 1) ? g_b1 : g_b2;
    if (idx < G4 * Ii) {
        int n = idx >> 11, k = idx & 2047;
        int j = n >> 2, g = n & 3;
        float v = wih[((g * Hh + j) << 11) + k];
        int kp = (k & ~31) | qperm(k & 31);
        wo[(n << 11) | kp] = __uint_as_float(f2tf(v));
    } else if (idx < G4 * Ii + G4 * Hh) {
        int i2 = idx - G4 * Ii;
        int n = i2 >> 10, k = i2 & 1023;
        int j = n >> 2, g = n & 3;
        ho[(n << 10) + k] = __uint_as_float(f2tf(whh[((g * Hh + j) << 10) + k]));
    } else {
        int n = idx - G4 * Ii - G4 * Hh;
        int j = n >> 2, g = n & 3;
        bo[n] = bih[g * Hh + j] + bhh[g * Hh + j];
        if (L == 2 && n == 0) g_sync = 0;   // reset barrier for layer-2 pass
    }
}

// -------------------- A prepass: permuted + tf32-rounded ---------------------
__global__ void prepA(const float* __restrict__ in0, const float* __restrict__ in4) {
    int idx = blockIdx.x * 256 + threadIdx.x;
    if (idx == 0) g_sync = 0;  // reset barrier counter for layer 1
    int row = idx >> 11;
    int k = idx & 2047;
    int kp = (k & ~31) | qperm(k & 31);
    float v = (k < 1024) ? in0[(size_t)row * Hh + k]
                         : in4[(size_t)row * Hh + (k - 1024)];
    float tv = __uint_as_float(f2tf(v));
    g_aperm1[(size_t)row * Ii + kp] = tv;
    if (k >= 1024) g_aperm2[(size_t)row * Ii + kp] = tv;
}

// -------------------- out1 + out14 second-half copy --------------------
__global__ void copy_out1(const float* __restrict__ in4, float* __restrict__ out) {
    size_t i4 = (size_t)blockIdx.x * 256 + threadIdx.x;
    size_t e = i4 * 4;
    float4 v = *(const float4*)(in4 + e);
    *(float4*)(out + e) = v;                       // out1
    size_t tb = e >> 10;
    size_t j = e & (Hh - 1);
    *(float4*)(out + (size_t)2 * TB * Hh + tb * 2 * Hh + Hh + j) = v;  // out14[:,H:]
}

// -------------------- big GEMM: xp = Aperm @ W'^T + bias' -------------------
#define GXS 4608                       // floats per stage per operand (128*LDSW)
#define GEMM_SMEM_FL (6 * GXS)         // 3 stages x (A,B) = 110592 bytes

template <int L>
__global__ void __launch_bounds__(256, 2)
gemm_xp() {
    const float* Ag = (L == 1) ? g_aperm1 : g_aperm2;
    const float* Wg = (L == 1) ? g_wih1 : g_wih2;
    const float* bias = (L == 1) ? g_b1 : g_b2;

    extern __shared__ float smem[];
    const unsigned smem_u32 = (unsigned)__cvta_generic_to_shared(smem);

    const int tid = threadIdx.x;
    const int lane = tid & 31;
    const int warp = tid >> 5;
    const int wm = (warp >> 1) << 5;   // 0,32,64,96
    const int wn = (warp & 1) << 6;    // 0,64
    const int lr = lane >> 2, lc = lane & 3;
    const int m0 = blockIdx.y * 128;
    const int n0 = blockIdx.x * 128;
    const int frow = tid >> 3, fqc = (tid & 7) << 2;

    float acc[2][8][4];
#pragma unroll
    for (int i = 0; i < 2; i++)
#pragma unroll
        for (int j = 0; j < 8; j++)
#pragma unroll
            for (int k = 0; k < 4; k++) acc[i][j][k] = 0.f;

    const float* Abase = Ag + (size_t)(m0 + frow) * Ii + fqc;
    const float* Bbase = Wg + (size_t)(n0 + frow) * Ii + fqc;
    const unsigned doff = (unsigned)(frow * LDSW + fqc) * 4;

#pragma unroll
    for (int pc = 0; pc < 2; pc++) {
        unsigned sa = smem_u32 + (pc * 2 * GXS) * 4 + doff;
        unsigned sb = smem_u32 + (pc * 2 * GXS + GXS) * 4 + doff;
#pragma unroll
        for (int i = 0; i < 4; i++) {
            cpa16(sa + (unsigned)(i * 32 * LDSW) * 4, Abase + (size_t)(i * 32) * Ii + pc * 32);
            cpa16(sb + (unsigned)(i * 32 * LDSW) * 4, Bbase + (size_t)(i * 32) * Ii + pc * 32);
        }
        asm volatile("cp.async.commit_group;\n" ::: "memory");
    }

    for (int kc = 0; kc < 64; kc++) {
        if (kc < 62) {
            int nc = kc + 2;
            int st = nc % 3;
            unsigned sa = smem_u32 + (st * 2 * GXS) * 4 + doff;
            unsigned sb = smem_u32 + (st * 2 * GXS + GXS) * 4 + doff;
#pragma unroll
            for (int i = 0; i < 4; i++) {
                cpa16(sa + (unsigned)(i * 32 * LDSW) * 4, Abase + (size_t)(i * 32) * Ii + nc * 32);
                cpa16(sb + (unsigned)(i * 32 * LDSW) * 4, Bbase + (size_t)(i * 32) * Ii + nc * 32);
            }
            asm volatile("cp.async.commit_group;\n" ::: "memory");
            asm volatile("cp.async.wait_group 2;\n" ::: "memory");
        } else if (kc == 62) {
            asm volatile("cp.async.wait_group 1;\n" ::: "memory");
        } else {
            asm volatile("cp.async.wait_group 0;\n" ::: "memory");
        }
        __syncthreads();

        const float* Ast = smem + (kc % 3) * 2 * GXS;
        const float* Bst = Ast + GXS;

        unsigned a[4][8];
#pragma unroll
        for (int i = 0; i < 4; i++) {
            int r = wm + ((i >> 1) << 4) + ((i & 1) << 3) + lr;
            const float4* p = (const float4*)&Ast[r * LDSW + lc * 8];
            float4 v0 = p[0], v1 = p[1];
            a[i][0] = __float_as_uint(v0.x); a[i][1] = __float_as_uint(v0.y);
            a[i][2] = __float_as_uint(v0.z); a[i][3] = __float_as_uint(v0.w);
            a[i][4] = __float_as_uint(v1.x); a[i][5] = __float_as_uint(v1.y);
            a[i][6] = __float_as_uint(v1.z); a[i][7] = __float_as_uint(v1.w);
        }

#pragma unroll
        for (int nt2 = 0; nt2 < 4; nt2++) {
            unsigned b0[8], b1[8];
            {
                int rb = wn + (2 * nt2) * 8 + lr;
                const float4* p = (const float4*)&Bst[rb * LDSW + lc * 8];
                float4 v0 = p[0], v1 = p[1];
                b0[0] = __float_as_uint(v0.x); b0[1] = __float_as_uint(v0.y);
                b0[2] = __float_as_uint(v0.z); b0[3] = __float_as_uint(v0.w);
                b0[4] = __float_as_uint(v1.x); b0[5] = __float_as_uint(v1.y);
                b0[6] = __float_as_uint(v1.z); b0[7] = __float_as_uint(v1.w);
            }
            {
                int rb = wn + (2 * nt2 + 1) * 8 + lr;
                const float4* p = (const float4*)&Bst[rb * LDSW + lc * 8];
                float4 v0 = p[0], v1 = p[1];
                b1[0] = __float_as_uint(v0.x); b1[1] = __float_as_uint(v0.y);
                b1[2] = __float_as_uint(v0.z); b1[3] = __float_as_uint(v0.w);
                b1[4] = __float_as_uint(v1.x); b1[5] = __float_as_uint(v1.y);
                b1[6] = __float_as_uint(v1.z); b1[7] = __float_as_uint(v1.w);
            }
#pragma unroll
            for (int kk = 0; kk < 4; kk++) {
                unsigned afr0[4] = {a[0][2 * kk], a[1][2 * kk],
                                    a[0][2 * kk + 1], a[1][2 * kk + 1]};
                unsigned afr1[4] = {a[2][2 * kk], a[3][2 * kk],
                                    a[2][2 * kk + 1], a[3][2 * kk + 1]};
                unsigned bfr0[2] = {b0[2 * kk], b0[2 * kk + 1]};
                unsigned bfr1[2] = {b1[2 * kk], b1[2 * kk + 1]};
                mma_tf32(acc[0][2 * nt2], afr0, bfr0);
                mma_tf32(acc[0][2 * nt2 + 1], afr0, bfr1);
                mma_tf32(acc[1][2 * nt2], afr1, bfr0);
                mma_tf32(acc[1][2 * nt2 + 1], afr1, bfr1);
            }
        }
        __syncthreads();
    }

#pragma unroll
    for (int mt = 0; mt < 2; mt++) {
        int r = m0 + wm + mt * 16 + lr;
#pragma unroll
        for (int nt = 0; nt < 8; nt++) {
            int c = n0 + wn + nt * 8 + 2 * lc;
            float2 bv = *(const float2*)&bias[c];
            float2 v0 = make_float2(acc[mt][nt][0] + bv.x, acc[mt][nt][1] + bv.y);
            float2 v1 = make_float2(acc[mt][nt][2] + bv.x, acc[mt][nt][3] + bv.y);
            *(float2*)&g_xp[(size_t)r * G4 + c] = v0;
            *(float2*)&g_xp[(size_t)(r + 8) * G4 + c] = v1;
        }
    }
}

// -------------------- persistent recurrent layer --------------------
// 128 CTAs x 512 threads (16 warps). CTA owns 32 gate-cols (8 hidden units).
// 2-way k-split: warps 0-7 k[0,512), warps 8-15 k[512,1024).
// Single-counter grid barrier (1 spinner/CTA), split arrive-early/wait-late:
// arrive right after the hperm write; phase-B writes + xp prefetch overlap
// with other CTAs' arrivals; spin only at the very end of the step.
#define SM2_WS_LD 1028                  // 1028 % 32 == 4 -> conflict-free frags
#define SM2_GS  (32 * SM2_WS_LD)        // Ws: 32896 floats
#define SM2_XS  (SM2_GS + 2 * 128 * LDSW)   // 2 Gs buffers then 2 xp stages
#define SM2_FL  (SM2_XS + 2 * 128 * LDSW)   // 51328 floats = 205312 bytes

template <int L>
__global__ void __launch_bounds__(512, 1)
lstm_layer(float* __restrict__ dout) {
    extern __shared__ float smem[];
    float* Ws = smem;
    float* Gs0 = smem + SM2_GS;
    float* Gs1 = Gs0 + 128 * LDSW;
    const unsigned smem_u32 = (unsigned)__cvta_generic_to_shared(smem);

    const int tid = threadIdx.x;
    const int bid = blockIdx.x;
    const int lane = tid & 31;
    const int warp = tid >> 5;         // 0..15
    const int wk = warp >> 3;          // k-half: 0 or 1
    const int wm = (warp & 7) << 4;    // batch row base: 0,16,...,112
    const int lr = lane >> 2, lc = lane & 3;
    const int n0 = bid * 32;           // gate-col base
    float* GsW = wk ? Gs1 : Gs0;

    const float* Wg = (L == 1) ? g_whh1 : g_whh2;

    // load W slice into smem with per-chunk column permutation
    for (int idx = tid; idx < 32 * 1024; idx += 512) {
        int n = idx >> 10;
        int k = idx & 1023;
        int kc = (k & ~31) + qperm(k & 31);
        Ws[n * SM2_WS_LD + kc] = Wg[(size_t)(n0 + n) * Hh + k];
    }
    // prefetch xp tile for t=0 into stage 0
    {
        unsigned xb = smem_u32 + SM2_XS * 4;
#pragma unroll
        for (int i = 0; i < 2; i++) {
            int u = tid + (i << 9);
            int b = u >> 3, q = u & 7;
            cpa16(xb + (unsigned)(b * LDSW + q * 4) * 4,
                  g_xp + (size_t)b * G4 + n0 + q * 4);
        }
        asm volatile("cp.async.commit_group;\n" ::: "memory");
    }
    __syncthreads();

    float creg[2];
    creg[0] = 0.f; creg[1] = 0.f;

    for (int t = 0; t < Tt; t++) {
        float acc[4][4];
#pragma unroll
        for (int j = 0; j < 4; j++)
#pragma unroll
            for (int k = 0; k < 4; k++) acc[j][k] = 0.f;

        if (t > 0) {
            const float* hp = g_hperm[(t - 1) & 1] + wk * 512;
            const float* r0 = hp + (size_t)(wm + lr) * Hh + lc * 8;
            const float* r1 = hp + (size_t)(wm + 8 + lr) * Hh + lc * 8;

            float4 cur[4], nxt[4];
            cur[0] = __ldcg((const float4*)r0); cur[1] = __ldcg((const float4*)(r0 + 4));
            cur[2] = __ldcg((const float4*)r1); cur[3] = __ldcg((const float4*)(r1 + 4));

            for (int kc = 0; kc < 16; kc++) {
                if (kc < 15) {
                    int o = (kc + 1) * 32;
                    nxt[0] = __ldcg((const float4*)(r0 + o));
                    nxt[1] = __ldcg((const float4*)(r0 + o + 4));
                    nxt[2] = __ldcg((const float4*)(r1 + o));
                    nxt[3] = __ldcg((const float4*)(r1 + o + 4));
                }
                unsigned bb[4][8];
#pragma unroll
                for (int nt = 0; nt < 4; nt++) {
                    const float4* p =
                        (const float4*)&Ws[(nt * 8 + lr) * SM2_WS_LD + wk * 512 + kc * 32 + lc * 8];
                    float4 v0 = p[0], v1 = p[1];
                    bb[nt][0] = __float_as_uint(v0.x); bb[nt][1] = __float_as_uint(v0.y);
                    bb[nt][2] = __float_as_uint(v0.z); bb[nt][3] = __float_as_uint(v0.w);
                    bb[nt][4] = __float_as_uint(v1.x); bb[nt][5] = __float_as_uint(v1.y);
                    bb[nt][6] = __float_as_uint(v1.z); bb[nt][7] = __float_as_uint(v1.w);
                }
                unsigned a0[8] = {__float_as_uint(cur[0].x), __float_as_uint(cur[0].y),
                                  __float_as_uint(cur[0].z), __float_as_uint(cur[0].w),
                                  __float_as_uint(cur[1].x), __float_as_uint(cur[1].y),
                                  __float_as_uint(cur[1].z), __float_as_uint(cur[1].w)};
                unsigned a1[8] = {__float_as_uint(cur[2].x), __float_as_uint(cur[2].y),
                                  __float_as_uint(cur[2].z), __float_as_uint(cur[2].w),
                                  __float_as_uint(cur[3].x), __float_as_uint(cur[3].y),
                                  __float_as_uint(cur[3].z), __float_as_uint(cur[3].w)};
#pragma unroll
                for (int kk = 0; kk < 4; kk++) {
                    unsigned afr[4] = {a0[2 * kk], a1[2 * kk],
                                       a0[2 * kk + 1], a1[2 * kk + 1]};
#pragma unroll
                    for (int nt = 0; nt < 4; nt++) {
                        unsigned bfr[2] = {bb[nt][2 * kk], bb[nt][2 * kk + 1]};
                        mma_tf32(acc[nt], afr, bfr);
                    }
                }
                if (kc < 15) {
#pragma unroll
                    for (int i = 0; i < 4; i++) cur[i] = nxt[i];
                }
            }
        }

        // stash partial gates to this k-half's buffer (16 rows per warp)
#pragma unroll
        for (int nt = 0; nt < 4; nt++) {
            int c = nt * 8 + 2 * lc;
            *(float2*)&GsW[(wm + lr) * LDSW + c] = make_float2(acc[nt][0], acc[nt][1]);
            *(float2*)&GsW[(wm + 8 + lr) * LDSW + c] = make_float2(acc[nt][2], acc[nt][3]);
        }
        asm volatile("cp.async.wait_group 0;\n" ::: "memory");  // xp(t) resident
        __syncthreads();

        // ---- epilogue phase A: cell update + hperm write (critical path) ----
        const float* Xs = smem + SM2_XS + (t & 1) * (128 * LDSW);
        float* hpw = g_hperm[t & 1];
        float hv_s[2];
        int b_s[2], j_s[2];
#pragma unroll
        for (int i = 0; i < 2; i++) {
            int u = tid + (i << 9);
            int b = u >> 3;
            int jl = u & 7;
            float4 x4 = *(const float4*)&Xs[b * LDSW + (jl << 2)];
            float4 p0 = *(const float4*)&Gs0[b * LDSW + (jl << 2)];
            float4 p1 = *(const float4*)&Gs1[b * LDSW + (jl << 2)];
            float gi = p0.x + p1.x + x4.x;
            float gf = p0.y + p1.y + x4.y;
            float gg = p0.z + p1.z + x4.z;
            float go = p0.w + p1.w + x4.w;
            float iv = fsigmoid(gi);
            float fv = fsigmoid(gf);
            float gv = ftanh(gg);
            float ov = fsigmoid(go);
            float cv = fv * creg[i] + iv * gv;
            creg[i] = cv;
            float hv = ov * ftanh(cv);
            int j = (n0 >> 2) + jl;
            int kc = (j & ~31) + qperm(j & 31);
            hpw[b * Hh + kc] = __uint_as_float(f2tf(hv));
            hv_s[i] = hv; b_s[i] = b; j_s[i] = j;
        }

        // ---- arrive EARLY: publish this CTA's step completion ----
        if (t < Tt - 1) {
            __syncthreads();           // all hperm writes issued
            if (tid == 0) {
                __threadfence();       // make them visible gpu-wide
                atomicAdd(&g_sync, 1u);
            }
        }

        // ---- phase B: non-critical writes + xp(t+1) prefetch (overlap) ----
#pragma unroll
        for (int i = 0; i < 2; i++) {
            int b = b_s[i], j = j_s[i];
            float hv = hv_s[i];
            size_t hi = (size_t)t * Bb * Hh + b * Hh + j;
            if (L == 1) {
                g_h1[hi] = hv;                                   // residual source
                int kc = (j & ~31) + qperm(j & 31);
                g_aperm2[(size_t)(t * Bb + b) * Ii + kc] =
                    __uint_as_float(f2tf(hv));                   // layer-2 GEMM A
            } else {
                float o11 = hv + g_h1[hi];
                dout[(size_t)TB * Hh + hi] = o11;                                   // out11
                dout[(size_t)2 * TB * Hh + ((size_t)(t * Bb + b)) * 2 * Hh + j] = o11;  // out14[:,:H]
            }
        }

        if (t < Tt - 1) {
            // prefetch next step's xp tile (overlaps the barrier wait)
            const float* xpn = g_xp + (size_t)(t + 1) * Bb * G4;
            unsigned xb = smem_u32 + (SM2_XS + ((t + 1) & 1) * (128 * LDSW)) * 4;
#pragma unroll
            for (int i = 0; i < 2; i++) {
                int u = tid + (i << 9);
                int b = u >> 3, q = u & 7;
                cpa16(xb + (unsigned)(b * LDSW + q * 4) * 4,
                      xpn + (size_t)b * G4 + n0 + q * 4);
            }
            asm volatile("cp.async.commit_group;\n" ::: "memory");

            // ---- wait LATE: spin until all CTAs arrived for step t ----
            if (tid == 0) {
                unsigned tgt = (unsigned)(t + 1) * NBLK;
                while (*(volatile unsigned*)&g_sync < tgt) {}
                __threadfence();
            }
            __syncthreads();
        }
    }
}

// -------------------- launch --------------------
extern "C" void kernel_launch(void* const* d_in, const int* in_sizes, int n_in,
                              void* d_out, int out_size) {
    const float* input4 = (const float*)d_in[0];
    const float* input0 = (const float*)d_in[1];
    const float* w_ih6  = (const float*)d_in[2];
    const float* w_hh6  = (const float*)d_in[3];
    const float* b_ih6  = (const float*)d_in[4];
    const float* b_hh6  = (const float*)d_in[5];
    const float* w_ih10 = (const float*)d_in[6];
    const float* w_hh10 = (const float*)d_in[7];
    const float* b_ih10 = (const float*)d_in[8];
    const float* b_hh10 = (const float*)d_in[9];
    float* out = (float*)d_out;

    cudaFuncSetAttribute(lstm_layer<1>, cudaFuncAttributeMaxDynamicSharedMemorySize,
                         SM2_FL * 4);
    cudaFuncSetAttribute(lstm_layer<2>, cudaFuncAttributeMaxDynamicSharedMemorySize,
                         SM2_FL * 4);
    cudaFuncSetAttribute(gemm_xp<1>, cudaFuncAttributeMaxDynamicSharedMemorySize,
                         GEMM_SMEM_FL * 4);
    cudaFuncSetAttribute(gemm_xp<2>, cudaFuncAttributeMaxDynamicSharedMemorySize,
                         GEMM_SMEM_FL * 4);

    dim3 gx(G4 / 128, TB / 128);  // n-tile fastest -> A reuse in L2
    const int PW_GRID = (G4 * (Ii + Hh + 1)) / 256;  // 49168

    // launch order arranged so ncu's capture window lands on lstm_layer<1> (idx 3)
    permute_l<1><<<PW_GRID, 256>>>(w_ih6, w_hh6, b_ih6, b_hh6);      // 0
    prepA<<<(TB * Ii) / 256, 256>>>(input0, input4);                  // 1 (+sync reset)
    gemm_xp<1><<<gx, 256, GEMM_SMEM_FL * 4>>>();                      // 2
    lstm_layer<1><<<NBLK, 512, SM2_FL * 4>>>(out);                    // 3 <- profile me
    permute_l<2><<<PW_GRID, 256>>>(w_ih10, w_hh10, b_ih10, b_hh10);   // 4 (+sync reset)
    gemm_xp<2><<<gx, 256, GEMM_SMEM_FL * 4>>>();                      // 5
    lstm_layer<2><<<NBLK, 512, SM2_FL * 4>>>(out);                    // 6
    copy_out1<<<(TB * Hh / 4) / 256, 256>>>(input4, out);             // 7
}

// round 10
// speedup vs baseline: 1.1361x; 1.0338x over previous
#include <cuda_runtime.h>
#include <cstdint>

// ---------------------------------------------------------------------------
// Stage3 LSTM stack: out1 = input4
//                    out7 = LSTM1(concat(input0, input4))
//                    out11 = LSTM2(concat(out7, input4)) + out7
//                    out14 = concat(out11, input4)
// Outputs concatenated: [out1 (T*B*H)] [out11 (T*B*H)] [out14 (T*B*2H)]
// ---------------------------------------------------------------------------

#define Tt 128
#define Bb 128
#define Hh 1024
#define Ii 2048
#define G4 4096            // 4*H
#define TB 16384           // T*B
#define LDSW 36            // smem row stride in floats (32 + 4 pad)
#define NBLK 128           // persistent blocks (1 per SM)

// -------------------- device scratch (no allocs allowed) --------------------
__device__ float g_wih1[G4 * Ii];   // gate-interleaved rows + k-qperm cols, tf32
__device__ float g_whh1[G4 * Hh];   // gate-interleaved rows, natural cols, tf32
__device__ float g_b1[G4];
__device__ float g_wih2[G4 * Ii];
__device__ float g_whh2[G4 * Hh];
__device__ float g_b2[G4];
__device__ float g_aperm1[(size_t)TB * Ii];  // layer-1 A: [input0|input4], permuted+tf32
__device__ float g_aperm2[(size_t)TB * Ii];  // layer-2 A: [h1|input4], permuted+tf32
__device__ float g_xp[(size_t)TB * G4];      // input projection for current layer
__device__ float g_h1[(size_t)TB * Hh];      // layer-1 h (natural layout, = out7)
__device__ float g_hperm[2][Bb * Hh];        // ping-pong h, col-permuted + tf32
__device__ unsigned g_sync;                  // grid barrier counter

// -------------------- helpers --------------------
static __device__ __forceinline__ unsigned f2tf(float x) {
    unsigned u;
    asm("cvt.rna.tf32.f32 %0, %1;" : "=r"(u) : "f"(x));
    return u;
}

static __device__ __forceinline__ void mma_tf32(float c[4], const unsigned a[4],
                                                const unsigned b[2]) {
    asm volatile(
        "mma.sync.aligned.m16n8k8.row.col.f32.tf32.tf32.f32 "
        "{%0,%1,%2,%3}, {%4,%5,%6,%7}, {%8,%9}, {%0,%1,%2,%3};\n"
        : "+f"(c[0]), "+f"(c[1]), "+f"(c[2]), "+f"(c[3])
        : "r"(a[0]), "r"(a[1]), "r"(a[2]), "r"(a[3]), "r"(b[0]), "r"(b[1]));
}

// column permutation within a 32-wide K chunk: stored(kl) = (kl%4)*8 + kl/4
static __device__ __forceinline__ int qperm(int kl) {
    return ((kl & 3) << 3) + (kl >> 2);
}

static __device__ __forceinline__ void cpa16(unsigned dst, const float* src) {
    asm volatile("cp.async.cg.shared.global [%0], [%1], 16;\n" :: "r"(dst), "l"(src));
}

// fast activations (MUFU-backed, rel err ~1e-6)
static __device__ __forceinline__ float fsigmoid(float x) {
    return __fdividef(1.f, 1.f + __expf(-x));
}
static __device__ __forceinline__ float ftanh(float x) {
    return __fdividef(2.f, 1.f + __expf(-2.f * x)) - 1.f;
}

// -------------------- fused per-layer weight/bias permutation ----------------
template <int L>
__global__ void permute_l(const float* __restrict__ wih, const float* __restrict__ whh,
                          const float* __restrict__ bih, const float* __restrict__ bhh) {
    int idx = blockIdx.x * 256 + threadIdx.x;
    float* wo = (L == 1) ? g_wih1 : g_wih2;
    float* ho = (L == 1) ? g_whh1 : g_whh2;
    float* bo = (L == 1) ? g_b1 : g_b2;
    if (idx < G4 * Ii) {
        int n = idx >> 11, k = idx & 2047;
        int j = n >> 2, g = n & 3;
        float v = wih[((g * Hh + j) << 11) + k];
        int kp = (k & ~31) | qperm(k & 31);
        wo[(n << 11) | kp] = __uint_as_float(f2tf(v));
    } else if (idx < G4 * Ii + G4 * Hh) {
        int i2 = idx - G4 * Ii;
        int n = i2 >> 10, k = i2 & 1023;
        int j = n >> 2, g = n & 3;
        ho[(n << 10) + k] = __uint_as_float(f2tf(whh[((g * Hh + j) << 10) + k]));
    } else {
        int n = idx - G4 * Ii - G4 * Hh;
        int j = n >> 2, g = n & 3;
        bo[n] = bih[g * Hh + j] + bhh[g * Hh + j];
        if (L == 2 && n == 0) g_sync = 0;   // reset barrier for layer-2 pass
    }
}

// -------------------- A prepass: permuted + tf32-rounded ---------------------
__global__ void prepA(const float* __restrict__ in0, const float* __restrict__ in4) {
    int idx = blockIdx.x * 256 + threadIdx.x;
    if (idx == 0) g_sync = 0;  // reset barrier counter for layer 1
    int row = idx >> 11;
    int k = idx & 2047;
    int kp = (k & ~31) | qperm(k & 31);
    float v = (k < 1024) ? in0[(size_t)row * Hh + k]
                         : in4[(size_t)row * Hh + (k - 1024)];
    float tv = __uint_as_float(f2tf(v));
    g_aperm1[(size_t)row * Ii + kp] = tv;
    if (k >= 1024) g_aperm2[(size_t)row * Ii + kp] = tv;
}

// -------------------- out1 + out14 second-half copy --------------------
__global__ void copy_out1(const float* __restrict__ in4, float* __restrict__ out) {
    size_t i4 = (size_t)blockIdx.x * 256 + threadIdx.x;
    size_t e = i4 * 4;
    float4 v = *(const float4*)(in4 + e);
    *(float4*)(out + e) = v;                       // out1
    size_t tb = e >> 10;
    size_t j = e & (Hh - 1);
    *(float4*)(out + (size_t)2 * TB * Hh + tb * 2 * Hh + Hh + j) = v;  // out14[:,H:]
}

// -------------------- big GEMM: xp = Aperm @ W'^T + bias' -------------------
#define GXS 4608                       // floats per stage per operand (128*LDSW)
#define GEMM_SMEM_FL (6 * GXS)         // 3 stages x (A,B) = 110592 bytes

template <int L>
__global__ void __launch_bounds__(256, 2)
gemm_xp() {
    const float* Ag = (L == 1) ? g_aperm1 : g_aperm2;
    const float* Wg = (L == 1) ? g_wih1 : g_wih2;
    const float* bias = (L == 1) ? g_b1 : g_b2;

    extern __shared__ float smem[];
    const unsigned smem_u32 = (unsigned)__cvta_generic_to_shared(smem);

    const int tid = threadIdx.x;
    const int lane = tid & 31;
    const int warp = tid >> 5;
    const int wm = (warp >> 1) << 5;   // 0,32,64,96
    const int wn = (warp & 1) << 6;    // 0,64
    const int lr = lane >> 2, lc = lane & 3;
    const int m0 = blockIdx.y * 128;
    const int n0 = blockIdx.x * 128;
    const int frow = tid >> 3, fqc = (tid & 7) << 2;

    float acc[2][8][4];
#pragma unroll
    for (int i = 0; i < 2; i++)
#pragma unroll
        for (int j = 0; j < 8; j++)
#pragma unroll
            for (int k = 0; k < 4; k++) acc[i][j][k] = 0.f;

    const float* Abase = Ag + (size_t)(m0 + frow) * Ii + fqc;
    const float* Bbase = Wg + (size_t)(n0 + frow) * Ii + fqc;
    const unsigned doff = (unsigned)(frow * LDSW + fqc) * 4;

#pragma unroll
    for (int pc = 0; pc < 2; pc++) {
        unsigned sa = smem_u32 + (pc * 2 * GXS) * 4 + doff;
        unsigned sb = smem_u32 + (pc * 2 * GXS + GXS) * 4 + doff;
#pragma unroll
        for (int i = 0; i < 4; i++) {
            cpa16(sa + (unsigned)(i * 32 * LDSW) * 4, Abase + (size_t)(i * 32) * Ii + pc * 32);
            cpa16(sb + (unsigned)(i * 32 * LDSW) * 4, Bbase + (size_t)(i * 32) * Ii + pc * 32);
        }
        asm volatile("cp.async.commit_group;\n" ::: "memory");
    }

    for (int kc = 0; kc < 64; kc++) {
        if (kc < 62) {
            int nc = kc + 2;
            int st = nc % 3;
            unsigned sa = smem_u32 + (st * 2 * GXS) * 4 + doff;
            unsigned sb = smem_u32 + (st * 2 * GXS + GXS) * 4 + doff;
#pragma unroll
            for (int i = 0; i < 4; i++) {
                cpa16(sa + (unsigned)(i * 32 * LDSW) * 4, Abase + (size_t)(i * 32) * Ii + nc * 32);
                cpa16(sb + (unsigned)(i * 32 * LDSW) * 4, Bbase + (size_t)(i * 32) * Ii + nc * 32);
            }
            asm volatile("cp.async.commit_group;\n" ::: "memory");
            asm volatile("cp.async.wait_group 2;\n" ::: "memory");
        } else if (kc == 62) {
            asm volatile("cp.async.wait_group 1;\n" ::: "memory");
        } else {
            asm volatile("cp.async.wait_group 0;\n" ::: "memory");
        }
        __syncthreads();

        const float* Ast = smem + (kc % 3) * 2 * GXS;
        const float* Bst = Ast + GXS;

        unsigned a[4][8];
#pragma unroll
        for (int i = 0; i < 4; i++) {
            int r = wm + ((i >> 1) << 4) + ((i & 1) << 3) + lr;
            const float4* p = (const float4*)&Ast[r * LDSW + lc * 8];
            float4 v0 = p[0], v1 = p[1];
            a[i][0] = __float_as_uint(v0.x); a[i][1] = __float_as_uint(v0.y);
            a[i][2] = __float_as_uint(v0.z); a[i][3] = __float_as_uint(v0.w);
            a[i][4] = __float_as_uint(v1.x); a[i][5] = __float_as_uint(v1.y);
            a[i][6] = __float_as_uint(v1.z); a[i][7] = __float_as_uint(v1.w);
        }

#pragma unroll
        for (int nt2 = 0; nt2 < 4; nt2++) {
            unsigned b0[8], b1[8];
            {
                int rb = wn + (2 * nt2) * 8 + lr;
                const float4* p = (const float4*)&Bst[rb * LDSW + lc * 8];
                float4 v0 = p[0], v1 = p[1];
                b0[0] = __float_as_uint(v0.x); b0[1] = __float_as_uint(v0.y);
                b0[2] = __float_as_uint(v0.z); b0[3] = __float_as_uint(v0.w);
                b0[4] = __float_as_uint(v1.x); b0[5] = __float_as_uint(v1.y);
                b0[6] = __float_as_uint(v1.z); b0[7] = __float_as_uint(v1.w);
            }
            {
                int rb = wn + (2 * nt2 + 1) * 8 + lr;
                const float4* p = (const float4*)&Bst[rb * LDSW + lc * 8];
                float4 v0 = p[0], v1 = p[1];
                b1[0] = __float_as_uint(v0.x); b1[1] = __float_as_uint(v0.y);
                b1[2] = __float_as_uint(v0.z); b1[3] = __float_as_uint(v0.w);
                b1[4] = __float_as_uint(v1.x); b1[5] = __float_as_uint(v1.y);
                b1[6] = __float_as_uint(v1.z); b1[7] = __float_as_uint(v1.w);
            }
#pragma unroll
            for (int kk = 0; kk < 4; kk++) {
                unsigned afr0[4] = {a[0][2 * kk], a[1][2 * kk],
                                    a[0][2 * kk + 1], a[1][2 * kk + 1]};
                unsigned afr1[4] = {a[2][2 * kk], a[3][2 * kk],
                                    a[2][2 * kk + 1], a[3][2 * kk + 1]};
                unsigned bfr0[2] = {b0[2 * kk], b0[2 * kk + 1]};
                unsigned bfr1[2] = {b1[2 * kk], b1[2 * kk + 1]};
                mma_tf32(acc[0][2 * nt2], afr0, bfr0);
                mma_tf32(acc[0][2 * nt2 + 1], afr0, bfr1);
                mma_tf32(acc[1][2 * nt2], afr1, bfr0);
                mma_tf32(acc[1][2 * nt2 + 1], afr1, bfr1);
            }
        }
        __syncthreads();
    }

#pragma unroll
    for (int mt = 0; mt < 2; mt++) {
        int r = m0 + wm + mt * 16 + lr;
#pragma unroll
        for (int nt = 0; nt < 8; nt++) {
            int c = n0 + wn + nt * 8 + 2 * lc;
            float2 bv = *(const float2*)&bias[c];
            float2 v0 = make_float2(acc[mt][nt][0] + bv.x, acc[mt][nt][1] + bv.y);
            float2 v1 = make_float2(acc[mt][nt][2] + bv.x, acc[mt][nt][3] + bv.y);
            *(float2*)&g_xp[(size_t)r * G4 + c] = v0;
            *(float2*)&g_xp[(size_t)(r + 8) * G4 + c] = v1;
        }
    }
}

// -------------------- persistent recurrent layer --------------------
// 128 CTAs x 512 threads (16 warps). CTA owns 32 gate-cols (8 hidden units).
// 2-way k-split: warps 0-7 k[0,512), warps 8-15 k[512,1024).
// Fully-unrolled 16-chunk GEMM with A-prefetch distance 2 (L2 latency hidden);
// B fragments in nt-pairs to bound live registers. Single-counter grid
// barrier, arrive-early / wait-late with phase-B writes + xp prefetch in the
// overlap window.
#define SM2_WS_LD 1028                  // 1028 % 32 == 4 -> conflict-free frags
#define SM2_GS  (32 * SM2_WS_LD)        // Ws: 32896 floats
#define SM2_XS  (SM2_GS + 2 * 128 * LDSW)   // 2 Gs buffers then 2 xp stages
#define SM2_FL  (SM2_XS + 2 * 128 * LDSW)   // 51328 floats = 205312 bytes

template <int L>
__global__ void __launch_bounds__(512, 1)
lstm_layer(float* __restrict__ dout) {
    extern __shared__ float smem[];
    float* Ws = smem;
    float* Gs0 = smem + SM2_GS;
    float* Gs1 = Gs0 + 128 * LDSW;
    const unsigned smem_u32 = (unsigned)__cvta_generic_to_shared(smem);

    const int tid = threadIdx.x;
    const int bid = blockIdx.x;
    const int lane = tid & 31;
    const int warp = tid >> 5;         // 0..15
    const int wk = warp >> 3;          // k-half: 0 or 1
    const int wm = (warp & 7) << 4;    // batch row base: 0,16,...,112
    const int lr = lane >> 2, lc = lane & 3;
    const int n0 = bid * 32;           // gate-col base
    float* GsW = wk ? Gs1 : Gs0;

    const float* Wg = (L == 1) ? g_whh1 : g_whh2;

    // load W slice into smem with per-chunk column permutation
    for (int idx = tid; idx < 32 * 1024; idx += 512) {
        int n = idx >> 10;
        int k = idx & 1023;
        int kc = (k & ~31) + qperm(k & 31);
        Ws[n * SM2_WS_LD + kc] = Wg[(size_t)(n0 + n) * Hh + k];
    }
    // prefetch xp tile for t=0 into stage 0
    {
        unsigned xb = smem_u32 + SM2_XS * 4;
#pragma unroll
        for (int i = 0; i < 2; i++) {
            int u = tid + (i << 9);
            int b = u >> 3, q = u & 7;
            cpa16(xb + (unsigned)(b * LDSW + q * 4) * 4,
                  g_xp + (size_t)b * G4 + n0 + q * 4);
        }
        asm volatile("cp.async.commit_group;\n" ::: "memory");
    }
    __syncthreads();

    float creg[2];
    creg[0] = 0.f; creg[1] = 0.f;

    for (int t = 0; t < Tt; t++) {
        float acc[4][4];
#pragma unroll
        for (int j = 0; j < 4; j++)
#pragma unroll
            for (int k = 0; k < 4; k++) acc[j][k] = 0.f;

        if (t > 0) {
            const float* hp = g_hperm[(t - 1) & 1] + wk * 512;
            const float* r0 = hp + (size_t)(wm + lr) * Hh + lc * 8;
            const float* r1 = hp + (size_t)(wm + 8 + lr) * Hh + lc * 8;

            // software pipeline, A-prefetch distance 2
            float4 A0[4], A1[4];
            A0[0] = __ldcg((const float4*)r0); A0[1] = __ldcg((const float4*)(r0 + 4));
            A0[2] = __ldcg((const float4*)r1); A0[3] = __ldcg((const float4*)(r1 + 4));
            A1[0] = __ldcg((const float4*)(r0 + 32)); A1[1] = __ldcg((const float4*)(r0 + 36));
            A1[2] = __ldcg((const float4*)(r1 + 32)); A1[3] = __ldcg((const float4*)(r1 + 36));

#pragma unroll
            for (int kc = 0; kc < 16; kc++) {
                float4 An[4];
                if (kc < 14) {
                    int o = (kc + 2) * 32;
                    An[0] = __ldcg((const float4*)(r0 + o));
                    An[1] = __ldcg((const float4*)(r0 + o + 4));
                    An[2] = __ldcg((const float4*)(r1 + o));
                    An[3] = __ldcg((const float4*)(r1 + o + 4));
                }
                unsigned a0[8] = {__float_as_uint(A0[0].x), __float_as_uint(A0[0].y),
                                  __float_as_uint(A0[0].z), __float_as_uint(A0[0].w),
                                  __float_as_uint(A0[1].x), __float_as_uint(A0[1].y),
                                  __float_as_uint(A0[1].z), __float_as_uint(A0[1].w)};
                unsigned a1[8] = {__float_as_uint(A0[2].x), __float_as_uint(A0[2].y),
                                  __float_as_uint(A0[2].z), __float_as_uint(A0[2].w),
                                  __float_as_uint(A0[3].x), __float_as_uint(A0[3].y),
                                  __float_as_uint(A0[3].z), __float_as_uint(A0[3].w)};
                // B fragments in nt-pairs (live B regs = 16)
#pragma unroll
                for (int np = 0; np < 2; np++) {
                    unsigned b0[8], b1[8];
                    {
                        const float4* p = (const float4*)
                            &Ws[((2 * np) * 8 + lr) * SM2_WS_LD + wk * 512 + kc * 32 + lc * 8];
                        float4 v0 = p[0], v1 = p[1];
                        b0[0] = __float_as_uint(v0.x); b0[1] = __float_as_uint(v0.y);
                        b0[2] = __float_as_uint(v0.z); b0[3] = __float_as_uint(v0.w);
                        b0[4] = __float_as_uint(v1.x); b0[5] = __float_as_uint(v1.y);
                        b0[6] = __float_as_uint(v1.z); b0[7] = __float_as_uint(v1.w);
                    }
                    {
                        const float4* p = (const float4*)
                            &Ws[((2 * np + 1) * 8 + lr) * SM2_WS_LD + wk * 512 + kc * 32 + lc * 8];
                        float4 v0 = p[0], v1 = p[1];
                        b1[0] = __float_as_uint(v0.x); b1[1] = __float_as_uint(v0.y);
                        b1[2] = __float_as_uint(v0.z); b1[3] = __float_as_uint(v0.w);
                        b1[4] = __float_as_uint(v1.x); b1[5] = __float_as_uint(v1.y);
                        b1[6] = __float_as_uint(v1.z); b1[7] = __float_as_uint(v1.w);
                    }
#pragma unroll
                    for (int kk = 0; kk < 4; kk++) {
                        unsigned afr[4] = {a0[2 * kk], a1[2 * kk],
                                           a0[2 * kk + 1], a1[2 * kk + 1]};
                        unsigned bfr0[2] = {b0[2 * kk], b0[2 * kk + 1]};
                        unsigned bfr1[2] = {b1[2 * kk], b1[2 * kk + 1]};
                        mma_tf32(acc[2 * np], afr, bfr0);
                        mma_tf32(acc[2 * np + 1], afr, bfr1);
                    }
                }
                // rotate pipeline (register renaming under full unroll)
#pragma unroll
                for (int i = 0; i < 4; i++) { A0[i] = A1[i]; A1[i] = An[i]; }
            }
        }

        // stash partial gates to this k-half's buffer (16 rows per warp)
#pragma unroll
        for (int nt = 0; nt < 4; nt++) {
            int c = nt * 8 + 2 * lc;
            *(float2*)&GsW[(wm + lr) * LDSW + c] = make_float2(acc[nt][0], acc[nt][1]);
            *(float2*)&GsW[(wm + 8 + lr) * LDSW + c] = make_float2(acc[nt][2], acc[nt][3]);
        }
        asm volatile("cp.async.wait_group 0;\n" ::: "memory");  // xp(t) resident
        __syncthreads();

        // ---- epilogue phase A: cell update + hperm write (critical path) ----
        const float* Xs = smem + SM2_XS + (t & 1) * (128 * LDSW);
        float* hpw = g_hperm[t & 1];
        float hv_s[2];
        int b_s[2], j_s[2];
#pragma unroll
        for (int i = 0; i < 2; i++) {
            int u = tid + (i << 9);
            int b = u >> 3;
            int jl = u & 7;
            float4 x4 = *(const float4*)&Xs[b * LDSW + (jl << 2)];
            float4 p0 = *(const float4*)&Gs0[b * LDSW + (jl << 2)];
            float4 p1 = *(const float4*)&Gs1[b * LDSW + (jl << 2)];
            float gi = p0.x + p1.x + x4.x;
            float gf = p0.y + p1.y + x4.y;
            float gg = p0.z + p1.z + x4.z;
            float go = p0.w + p1.w + x4.w;
            float iv = fsigmoid(gi);
            float fv = fsigmoid(gf);
            float gv = ftanh(gg);
            float ov = fsigmoid(go);
            float cv = fv * creg[i] + iv * gv;
            creg[i] = cv;
            float hv = ov * ftanh(cv);
            int j = (n0 >> 2) + jl;
            int kc = (j & ~31) + qperm(j & 31);
            hpw[b * Hh + kc] = __uint_as_float(f2tf(hv));
            hv_s[i] = hv; b_s[i] = b; j_s[i] = j;
        }

        // ---- arrive EARLY: publish this CTA's step completion ----
        if (t < Tt - 1) {
            __syncthreads();           // all hperm writes issued
            if (tid == 0) {
                __threadfence();       // make them visible gpu-wide
                atomicAdd(&g_sync, 1u);
            }
        }

        // ---- phase B: non-critical writes + xp(t+1) prefetch (overlap) ----
#pragma unroll
        for (int i = 0; i < 2; i++) {
            int b = b_s[i], j = j_s[i];
            float hv = hv_s[i];
            size_t hi = (size_t)t * Bb * Hh + b * Hh + j;
            if (L == 1) {
                g_h1[hi] = hv;                                   // residual source
                int kc = (j & ~31) + qperm(j & 31);
                g_aperm2[(size_t)(t * Bb + b) * Ii + kc] =
                    __uint_as_float(f2tf(hv));                   // layer-2 GEMM A
            } else {
                float o11 = hv + g_h1[hi];
                dout[(size_t)TB * Hh + hi] = o11;                                   // out11
                dout[(size_t)2 * TB * Hh + ((size_t)(t * Bb + b)) * 2 * Hh + j] = o11;  // out14[:,:H]
            }
        }

        if (t < Tt - 1) {
            // prefetch next step's xp tile (overlaps the barrier wait)
            const float* xpn = g_xp + (size_t)(t + 1) * Bb * G4;
            unsigned xb = smem_u32 + (SM2_XS + ((t + 1) & 1) * (128 * LDSW)) * 4;
#pragma unroll
            for (int i = 0; i < 2; i++) {
                int u = tid + (i << 9);
                int b = u >> 3, q = u & 7;
                cpa16(xb + (unsigned)(b * LDSW + q * 4) * 4,
                      xpn + (size_t)b * G4 + n0 + q * 4);
            }
            asm volatile("cp.async.commit_group;\n" ::: "memory");

            // ---- wait LATE: spin until all CTAs arrived for step t ----
            if (tid == 0) {
                unsigned tgt = (unsigned)(t + 1) * NBLK;
                while (*(volatile unsigned*)&g_sync < tgt) {}
                __threadfence();
            }
            __syncthreads();
        }
    }
}

// -------------------- launch --------------------
extern "C" void kernel_launch(void* const* d_in, const int* in_sizes, int n_in,
                              void* d_out, int out_size) {
    const float* input4 = (const float*)d_in[0];
    const float* input0 = (const float*)d_in[1];
    const float* w_ih6  = (const float*)d_in[2];
    const float* w_hh6  = (const float*)d_in[3];
    const float* b_ih6  = (const float*)d_in[4];
    const float* b_hh6  = (const float*)d_in[5];
    const float* w_ih10 = (const float*)d_in[6];
    const float* w_hh10 = (const float*)d_in[7];
    const float* b_ih10 = (const float*)d_in[8];
    const float* b_hh10 = (const float*)d_in[9];
    float* out = (float*)d_out;

    cudaFuncSetAttribute(lstm_layer<1>, cudaFuncAttributeMaxDynamicSharedMemorySize,
                         SM2_FL * 4);
    cudaFuncSetAttribute(lstm_layer<2>, cudaFuncAttributeMaxDynamicSharedMemorySize,
                         SM2_FL * 4);
    cudaFuncSetAttribute(gemm_xp<1>, cudaFuncAttributeMaxDynamicSharedMemorySize,
                         GEMM_SMEM_FL * 4);
    cudaFuncSetAttribute(gemm_xp<2>, cudaFuncAttributeMaxDynamicSharedMemorySize,
                         GEMM_SMEM_FL * 4);

    dim3 gx(G4 / 128, TB / 128);  // n-tile fastest -> A reuse in L2
    const int PW_GRID = (G4 * (Ii + Hh + 1)) / 256;  // 49168

    // launch order arranged so ncu's capture window lands on lstm_layer<1> (idx 3)
    permute_l<1><<<PW_GRID, 256>>>(w_ih6, w_hh6, b_ih6, b_hh6);      // 0
    prepA<<<(TB * Ii) / 256, 256>>>(input0, input4);                  // 1 (+sync reset)
    gemm_xp<1><<<gx, 256, GEMM_SMEM_FL * 4>>>();                      // 2
    lstm_layer<1><<<NBLK, 512, SM2_FL * 4>>>(out);                    // 3 <- profile me
    permute_l<2><<<PW_GRID, 256>>>(w_ih10, w_hh10, b_ih10, b_hh10);   // 4 (+sync reset)
    gemm_xp<2><<<gx, 256, GEMM_SMEM_FL * 4>>>();                      // 5
    lstm_layer<2><<<NBLK, 512, SM2_FL * 4>>>(out);                    // 6
    copy_out1<<<(TB * Hh / 4) / 256, 256>>>(input4, out);             // 7
}

// round 12
// speedup vs baseline: 1.1870x; 1.0448x over previous
#include <cuda_runtime.h>
#include <cstdint>

// ---------------------------------------------------------------------------
// Stage3 LSTM stack: out1 = input4
//                    out7 = LSTM1(concat(input0, input4))
//                    out11 = LSTM2(concat(out7, input4)) + out7
//                    out14 = concat(out11, input4)
// Outputs concatenated: [out1 (T*B*H)] [out11 (T*B*H)] [out14 (T*B*2H)]
// ---------------------------------------------------------------------------

#define Tt 128
#define Bb 128
#define Hh 1024
#define Ii 2048
#define G4 4096            // 4*H
#define TB 16384           // T*B
#define LDSW 36            // smem row stride in floats (32 + 4 pad)
#define NBLK 128           // persistent blocks (1 per SM)

// -------------------- device scratch (no allocs allowed) --------------------
__device__ float g_wih1[G4 * Ii];   // gate-interleaved rows + k-qperm cols, tf32
__device__ float g_whh1[G4 * Hh];   // gate-interleaved rows, natural cols, tf32
__device__ float g_b1[G4];
__device__ float g_wih2[G4 * Ii];
__device__ float g_whh2[G4 * Hh];
__device__ float g_b2[G4];
__device__ float g_aperm1[(size_t)TB * Ii];  // layer-1 A: [input0|input4], permuted+tf32
__device__ float g_aperm2[(size_t)TB * Ii];  // layer-2 A: [h1|input4], permuted+tf32
__device__ float g_xp[(size_t)TB * G4];      // input projection for current layer
__device__ float g_h1[(size_t)TB * Hh];      // layer-1 h (natural layout, = out7)
__device__ float g_hperm[2][Bb * Hh];        // ping-pong h, col-permuted + tf32
__device__ unsigned g_sync;                  // grid barrier counter

// -------------------- helpers --------------------
static __device__ __forceinline__ unsigned f2tf(float x) {
    unsigned u;
    asm("cvt.rna.tf32.f32 %0, %1;" : "=r"(u) : "f"(x));
    return u;
}

static __device__ __forceinline__ void mma_tf32(float c[4], const unsigned a[4],
                                                const unsigned b[2]) {
    asm volatile(
        "mma.sync.aligned.m16n8k8.row.col.f32.tf32.tf32.f32 "
        "{%0,%1,%2,%3}, {%4,%5,%6,%7}, {%8,%9}, {%0,%1,%2,%3};\n"
        : "+f"(c[0]), "+f"(c[1]), "+f"(c[2]), "+f"(c[3])
        : "r"(a[0]), "r"(a[1]), "r"(a[2]), "r"(a[3]), "r"(b[0]), "r"(b[1]));
}

// column permutation within a 32-wide K chunk: stored(kl) = (kl%4)*8 + kl/4
static __device__ __forceinline__ int qperm(int kl) {
    return ((kl & 3) << 3) + (kl >> 2);
}

static __device__ __forceinline__ void cpa16(unsigned dst, const float* src) {
    asm volatile("cp.async.cg.shared.global [%0], [%1], 16;\n" :: "r"(dst), "l"(src));
}

// fast activations (MUFU-backed, rel err ~1e-6)
static __device__ __forceinline__ float fsigmoid(float x) {
    return __fdividef(1.f, 1.f + __expf(-x));
}
static __device__ __forceinline__ float ftanh(float x) {
    return __fdividef(2.f, 1.f + __expf(-2.f * x)) - 1.f;
}

// -------------------- fused per-layer weight/bias permutation ----------------
template <int L>
__global__ void permute_l(const float* __restrict__ wih, const float* __restrict__ whh,
                          const float* __restrict__ bih, const float* __restrict__ bhh) {
    int idx = blockIdx.x * 256 + threadIdx.x;
    float* wo = (L == 1) ? g_wih1 : g_wih2;
    float* ho = (L == 1) ? g_whh1 : g_whh2;
    float* bo = (L == 1) ? g_b1 : g_b2;
    if (idx < G4 * Ii) {
        int n = idx >> 11, k = idx & 2047;
        int j = n >> 2, g = n & 3;
        float v = wih[((g * Hh + j) << 11) + k];
        int kp = (k & ~31) | qperm(k & 31);
        wo[(n << 11) | kp] = __uint_as_float(f2tf(v));
    } else if (idx < G4 * Ii + G4 * Hh) {
        int i2 = idx - G4 * Ii;
        int n = i2 >> 10, k = i2 & 1023;
        int j = n >> 2, g = n & 3;
        ho[(n << 10) + k] = __uint_as_float(f2tf(whh[((g * Hh + j) << 10) + k]));
    } else {
        int n = idx - G4 * Ii - G4 * Hh;
        int j = n >> 2, g = n & 3;
        bo[n] = bih[g * Hh + j] + bhh[g * Hh + j];
        if (L == 2 && n == 0) g_sync = 0;   // reset barrier for layer-2 pass
    }
}

// -------------------- A prepass: permuted + tf32-rounded ---------------------
__global__ void prepA(const float* __restrict__ in0, const float* __restrict__ in4) {
    int idx = blockIdx.x * 256 + threadIdx.x;
    if (idx == 0) g_sync = 0;  // reset barrier counter for layer 1
    int row = idx >> 11;
    int k = idx & 2047;
    int kp = (k & ~31) | qperm(k & 31);
    float v = (k < 1024) ? in0[(size_t)row * Hh + k]
                         : in4[(size_t)row * Hh + (k - 1024)];
    float tv = __uint_as_float(f2tf(v));
    g_aperm1[(size_t)row * Ii + kp] = tv;
    if (k >= 1024) g_aperm2[(size_t)row * Ii + kp] = tv;
}

// -------------------- out1 + out14 second-half copy --------------------
__global__ void copy_out1(const float* __restrict__ in4, float* __restrict__ out) {
    size_t i4 = (size_t)blockIdx.x * 256 + threadIdx.x;
    size_t e = i4 * 4;
    float4 v = *(const float4*)(in4 + e);
    *(float4*)(out + e) = v;                       // out1
    size_t tb = e >> 10;
    size_t j = e & (Hh - 1);
    *(float4*)(out + (size_t)2 * TB * Hh + tb * 2 * Hh + Hh + j) = v;  // out14[:,H:]
}

// -------------------- big GEMM: xp = Aperm @ W'^T + bias' -------------------
#define GXS 4608                       // floats per stage per operand (128*LDSW)
#define GEMM_SMEM_FL (6 * GXS)         // 3 stages x (A,B) = 110592 bytes

template <int L>
__global__ void __launch_bounds__(256, 2)
gemm_xp() {
    const float* Ag = (L == 1) ? g_aperm1 : g_aperm2;
    const float* Wg = (L == 1) ? g_wih1 : g_wih2;
    const float* bias = (L == 1) ? g_b1 : g_b2;

    extern __shared__ float smem[];
    const unsigned smem_u32 = (unsigned)__cvta_generic_to_shared(smem);

    const int tid = threadIdx.x;
    const int lane = tid & 31;
    const int warp = tid >> 5;
    const int wm = (warp >> 1) << 5;   // 0,32,64,96
    const int wn = (warp & 1) << 6;    // 0,64
    const int lr = lane >> 2, lc = lane & 3;
    const int m0 = blockIdx.y * 128;
    const int n0 = blockIdx.x * 128;
    const int frow = tid >> 3, fqc = (tid & 7) << 2;

    float acc[2][8][4];
#pragma unroll
    for (int i = 0; i < 2; i++)
#pragma unroll
        for (int j = 0; j < 8; j++)
#pragma unroll
            for (int k = 0; k < 4; k++) acc[i][j][k] = 0.f;

    const float* Abase = Ag + (size_t)(m0 + frow) * Ii + fqc;
    const float* Bbase = Wg + (size_t)(n0 + frow) * Ii + fqc;
    const unsigned doff = (unsigned)(frow * LDSW + fqc) * 4;

#pragma unroll
    for (int pc = 0; pc < 2; pc++) {
        unsigned sa = smem_u32 + (pc * 2 * GXS) * 4 + doff;
        unsigned sb = smem_u32 + (pc * 2 * GXS + GXS) * 4 + doff;
#pragma unroll
        for (int i = 0; i < 4; i++) {
            cpa16(sa + (unsigned)(i * 32 * LDSW) * 4, Abase + (size_t)(i * 32) * Ii + pc * 32);
            cpa16(sb + (unsigned)(i * 32 * LDSW) * 4, Bbase + (size_t)(i * 32) * Ii + pc * 32);
        }
        asm volatile("cp.async.commit_group;\n" ::: "memory");
    }

    for (int kc = 0; kc < 64; kc++) {
        if (kc < 62) {
            int nc = kc + 2;
            int st = nc % 3;
            unsigned sa = smem_u32 + (st * 2 * GXS) * 4 + doff;
            unsigned sb = smem_u32 + (st * 2 * GXS + GXS) * 4 + doff;
#pragma unroll
            for (int i = 0; i < 4; i++) {
                cpa16(sa + (unsigned)(i * 32 * LDSW) * 4, Abase + (size_t)(i * 32) * Ii + nc * 32);
                cpa16(sb + (unsigned)(i * 32 * LDSW) * 4, Bbase + (size_t)(i * 32) * Ii + nc * 32);
            }
            asm volatile("cp.async.commit_group;\n" ::: "memory");
            asm volatile("cp.async.wait_group 2;\n" ::: "memory");
        } else if (kc == 62) {
            asm volatile("cp.async.wait_group 1;\n" ::: "memory");
        } else {
            asm volatile("cp.async.wait_group 0;\n" ::: "memory");
        }
        __syncthreads();

        const float* Ast = smem + (kc % 3) * 2 * GXS;
        const float* Bst = Ast + GXS;

        unsigned a[4][8];
#pragma unroll
        for (int i = 0; i < 4; i++) {
            int r = wm + ((i >> 1) << 4) + ((i & 1) << 3) + lr;
            const float4* p = (const float4*)&Ast[r * LDSW + lc * 8];
            float4 v0 = p[0], v1 = p[1];
            a[i][0] = __float_as_uint(v0.x); a[i][1] = __float_as_uint(v0.y);
            a[i][2] = __float_as_uint(v0.z); a[i][3] = __float_as_uint(v0.w);
            a[i][4] = __float_as_uint(v1.x); a[i][5] = __float_as_uint(v1.y);
            a[i][6] = __float_as_uint(v1.z); a[i][7] = __float_as_uint(v1.w);
        }

#pragma unroll
        for (int nt2 = 0; nt2 < 4; nt2++) {
            unsigned b0[8], b1[8];
            {
                int rb = wn + (2 * nt2) * 8 + lr;
                const float4* p = (const float4*)&Bst[rb * LDSW + lc * 8];
                float4 v0 = p[0], v1 = p[1];
                b0[0] = __float_as_uint(v0.x); b0[1] = __float_as_uint(v0.y);
                b0[2] = __float_as_uint(v0.z); b0[3] = __float_as_uint(v0.w);
                b0[4] = __float_as_uint(v1.x); b0[5] = __float_as_uint(v1.y);
                b0[6] = __float_as_uint(v1.z); b0[7] = __float_as_uint(v1.w);
            }
            {
                int rb = wn + (2 * nt2 + 1) * 8 + lr;
                const float4* p = (const float4*)&Bst[rb * LDSW + lc * 8];
                float4 v0 = p[0], v1 = p[1];
                b1[0] = __float_as_uint(v0.x); b1[1] = __float_as_uint(v0.y);
                b1[2] = __float_as_uint(v0.z); b1[3] = __float_as_uint(v0.w);
                b1[4] = __float_as_uint(v1.x); b1[5] = __float_as_uint(v1.y);
                b1[6] = __float_as_uint(v1.z); b1[7] = __float_as_uint(v1.w);
            }
#pragma unroll
            for (int kk = 0; kk < 4; kk++) {
                unsigned afr0[4] = {a[0][2 * kk], a[1][2 * kk],
                                    a[0][2 * kk + 1], a[1][2 * kk + 1]};
                unsigned afr1[4] = {a[2][2 * kk], a[3][2 * kk],
                                    a[2][2 * kk + 1], a[3][2 * kk + 1]};
                unsigned bfr0[2] = {b0[2 * kk], b0[2 * kk + 1]};
                unsigned bfr1[2] = {b1[2 * kk], b1[2 * kk + 1]};
                mma_tf32(acc[0][2 * nt2], afr0, bfr0);
                mma_tf32(acc[0][2 * nt2 + 1], afr0, bfr1);
                mma_tf32(acc[1][2 * nt2], afr1, bfr0);
                mma_tf32(acc[1][2 * nt2 + 1], afr1, bfr1);
            }
        }
        __syncthreads();
    }

#pragma unroll
    for (int mt = 0; mt < 2; mt++) {
        int r = m0 + wm + mt * 16 + lr;
#pragma unroll
        for (int nt = 0; nt < 8; nt++) {
            int c = n0 + wn + nt * 8 + 2 * lc;
            float2 bv = *(const float2*)&bias[c];
            float2 v0 = make_float2(acc[mt][nt][0] + bv.x, acc[mt][nt][1] + bv.y);
            float2 v1 = make_float2(acc[mt][nt][2] + bv.x, acc[mt][nt][3] + bv.y);
            *(float2*)&g_xp[(size_t)r * G4 + c] = v0;
            *(float2*)&g_xp[(size_t)(r + 8) * G4 + c] = v1;
        }
    }
}

// -------------------- persistent recurrent layer --------------------
// 128 CTAs x 512 threads (16 warps). CTA owns 32 gate-cols (8 hidden units).
// 4-way k-split: warp = 32 batch rows x 32 gate cols x 256 k (16 warps =
// 4 m-groups x 4 k-quarters). Halves smem B traffic vs 2-way split.
// 16-k chunks (one float4 in qperm layout), A prefetch distance 2.
// Four Gs partial buffers (16B-aligned strides); single xp buffer (the
// arrive-early __syncthreads orders xp(t) reads before the xp(t+1) prefetch).
#define SM3_WS_LD 1028                  // 1028 % 32 == 4 -> conflict-free frags
#define SM3_WS_SZ (32 * SM3_WS_LD)      // 32896 floats
#define SM3_LDSG 36                     // Gs row stride (144 B, 16B-aligned)
#define SM3_GS_STRIDE (128 * SM3_LDSG)  // 4608 floats per Gs buffer
#define SM3_LDSX 32                     // xp row stride (128 B, 16B-aligned)
#define SM3_XS_OFF (SM3_WS_SZ + 4 * SM3_GS_STRIDE)      // 51328
#define SM3_FL (SM3_XS_OFF + 128 * SM3_LDSX)            // 55424 fl = 221696 B

template <int L>
__global__ void __launch_bounds__(512, 1)
lstm_layer(float* __restrict__ dout) {
    extern __shared__ float smem[];
    float* Ws = smem;
    float* Gs = smem + SM3_WS_SZ;
    float* Xs = smem + SM3_XS_OFF;
    const unsigned smem_u32 = (unsigned)__cvta_generic_to_shared(smem);

    const int tid = threadIdx.x;
    const int bid = blockIdx.x;
    const int lane = tid & 31;
    const int warp = tid >> 5;         // 0..15
    const int mq = warp >> 2;          // m-group 0..3 (32 batch rows each)
    const int kq = warp & 3;           // k-quarter 0..3 (256 k each)
    const int wm = mq << 5;            // batch row base
    const int kb = kq << 8;            // k base
    const int lr = lane >> 2, lc = lane & 3;
    const int n0 = bid * 32;           // gate-col base
    float* GsW = Gs + kq * SM3_GS_STRIDE;

    const float* Wg = (L == 1) ? g_whh1 : g_whh2;

    // load W slice into smem with per-chunk column permutation
    for (int idx = tid; idx < 32 * 1024; idx += 512) {
        int n = idx >> 10;
        int k = idx & 1023;
        int kc = (k & ~31) + qperm(k & 31);
        Ws[n * SM3_WS_LD + kc] = Wg[(size_t)(n0 + n) * Hh + k];
    }
    // prefetch xp tile for t=0
    {
        unsigned xb = smem_u32 + SM3_XS_OFF * 4;
#pragma unroll
        for (int i = 0; i < 2; i++) {
            int u = tid + (i << 9);
            int b = u >> 3, q = u & 7;
            cpa16(xb + (unsigned)(b * SM3_LDSX + q * 4) * 4,
                  g_xp + (size_t)b * G4 + n0 + q * 4);
        }
        asm volatile("cp.async.commit_group;\n" ::: "memory");
    }
    __syncthreads();

    float creg[2];
    creg[0] = 0.f; creg[1] = 0.f;

    for (int t = 0; t < Tt; t++) {
        float acc[2][4][4];
#pragma unroll
        for (int i = 0; i < 2; i++)
#pragma unroll
            for (int j = 0; j < 4; j++)
#pragma unroll
                for (int k = 0; k < 4; k++) acc[i][j][k] = 0.f;

        if (t > 0) {
            const float* hp = g_hperm[(t - 1) & 1];
            // 4 row-group pointers (8-row groups within the 32-row m-block)
            const float* rp0 = hp + (size_t)(wm + lr) * Hh + kb + lc * 8;
            const float* rp1 = hp + (size_t)(wm + 8 + lr) * Hh + kb + lc * 8;
            const float* rp2 = hp + (size_t)(wm + 16 + lr) * Hh + kb + lc * 8;
            const float* rp3 = hp + (size_t)(wm + 24 + lr) * Hh + kb + lc * 8;
            // chunk c (16 k): float4 at offset (c>>1)*32 + (c&1)*4
#define AOFF(c) (((c) >> 1) * 32 + ((c) & 1) * 4)
            float4 A0[4], A1[4];
            A0[0] = __ldcg((const float4*)(rp0 + AOFF(0)));
            A0[1] = __ldcg((const float4*)(rp1 + AOFF(0)));
            A0[2] = __ldcg((const float4*)(rp2 + AOFF(0)));
            A0[3] = __ldcg((const float4*)(rp3 + AOFF(0)));
            A1[0] = __ldcg((const float4*)(rp0 + AOFF(1)));
            A1[1] = __ldcg((const float4*)(rp1 + AOFF(1)));
            A1[2] = __ldcg((const float4*)(rp2 + AOFF(1)));
            A1[3] = __ldcg((const float4*)(rp3 + AOFF(1)));

#pragma unroll
            for (int c = 0; c < 16; c++) {
                float4 An[4];
                if (c < 14) {
                    int o = AOFF(c + 2);
                    An[0] = __ldcg((const float4*)(rp0 + o));
                    An[1] = __ldcg((const float4*)(rp1 + o));
                    An[2] = __ldcg((const float4*)(rp2 + o));
                    An[3] = __ldcg((const float4*)(rp3 + o));
                }
                unsigned ax[4][4];
#pragma unroll
                for (int i = 0; i < 4; i++) {
                    ax[i][0] = __float_as_uint(A0[i].x);
                    ax[i][1] = __float_as_uint(A0[i].y);
                    ax[i][2] = __float_as_uint(A0[i].z);
                    ax[i][3] = __float_as_uint(A0[i].w);
                }
                // B in nt-pairs (live B regs = 8)
#pragma unroll
                for (int np = 0; np < 2; np++) {
                    const int boff = kb + AOFF(c) + lc * 8;
                    float4 Bv0 = *(const float4*)
                        &Ws[((2 * np) * 8 + lr) * SM3_WS_LD + boff];
                    float4 Bv1 = *(const float4*)
                        &Ws[((2 * np + 1) * 8 + lr) * SM3_WS_LD + boff];
                    unsigned b0[4] = {__float_as_uint(Bv0.x), __float_as_uint(Bv0.y),
                                      __float_as_uint(Bv0.z), __float_as_uint(Bv0.w)};
                    unsigned b1[4] = {__float_as_uint(Bv1.x), __float_as_uint(Bv1.y),
                                      __float_as_uint(Bv1.z), __float_as_uint(Bv1.w)};
#pragma unroll
                    for (int kk = 0; kk < 2; kk++) {
#pragma unroll
                        for (int mt = 0; mt < 2; mt++) {
                            unsigned afr[4] = {ax[2 * mt][2 * kk], ax[2 * mt + 1][2 * kk],
                                               ax[2 * mt][2 * kk + 1], ax[2 * mt + 1][2 * kk + 1]};
                            unsigned bfr0[2] = {b0[2 * kk], b0[2 * kk + 1]};
                            unsigned bfr1[2] = {b1[2 * kk], b1[2 * kk + 1]};
                            mma_tf32(acc[mt][2 * np], afr, bfr0);
                            mma_tf32(acc[mt][2 * np + 1], afr, bfr1);
                        }
                    }
                }
                // rotate pipeline
#pragma unroll
                for (int i = 0; i < 4; i++) { A0[i] = A1[i]; A1[i] = An[i]; }
            }
#undef AOFF
        }

        // stash partial gates to this k-quarter's buffer (32 rows per warp)
#pragma unroll
        for (int mt = 0; mt < 2; mt++) {
#pragma unroll
            for (int nt = 0; nt < 4; nt++) {
                int c = nt * 8 + 2 * lc;
                *(float2*)&GsW[(wm + mt * 16 + lr) * SM3_LDSG + c] =
                    make_float2(acc[mt][nt][0], acc[mt][nt][1]);
                *(float2*)&GsW[(wm + mt * 16 + 8 + lr) * SM3_LDSG + c] =
                    make_float2(acc[mt][nt][2], acc[mt][nt][3]);
            }
        }
        asm volatile("cp.async.wait_group 0;\n" ::: "memory");  // xp(t) resident
        __syncthreads();

        // ---- epilogue phase A: cell update + hperm write (critical path) ----
        float* hpw = g_hperm[t & 1];
        float hv_s[2];
        int b_s[2], j_s[2];
#pragma unroll
        for (int i = 0; i < 2; i++) {
            int u = tid + (i << 9);
            int b = u >> 3;
            int jl = u & 7;
            float4 x4 = *(const float4*)&Xs[b * SM3_LDSX + (jl << 2)];
            float4 p0 = *(const float4*)&Gs[b * SM3_LDSG + (jl << 2)];
            float4 p1 = *(const float4*)&Gs[SM3_GS_STRIDE + b * SM3_LDSG + (jl << 2)];
            float4 p2 = *(const float4*)&Gs[2 * SM3_GS_STRIDE + b * SM3_LDSG + (jl << 2)];
            float4 p3 = *(const float4*)&Gs[3 * SM3_GS_STRIDE + b * SM3_LDSG + (jl << 2)];
            float gi = (p0.x + p1.x) + (p2.x + p3.x) + x4.x;
            float gf = (p0.y + p1.y) + (p2.y + p3.y) + x4.y;
            float gg = (p0.z + p1.z) + (p2.z + p3.z) + x4.z;
            float go = (p0.w + p1.w) + (p2.w + p3.w) + x4.w;
            float iv = fsigmoid(gi);
            float fv = fsigmoid(gf);
            float gv = ftanh(gg);
            float ov = fsigmoid(go);
            float cv = fv * creg[i] + iv * gv;
            creg[i] = cv;
            float hv = ov * ftanh(cv);
            int j = (n0 >> 2) + jl;
            int kc = (j & ~31) + qperm(j & 31);
            hpw[b * Hh + kc] = __uint_as_float(f2tf(hv));
            hv_s[i] = hv; b_s[i] = b; j_s[i] = j;
        }

        // ---- arrive EARLY: publish this CTA's step completion ----
        // (this __syncthreads also orders all xp(t) reads before the
        //  xp(t+1) prefetch below reuses the single Xs buffer)
        if (t < Tt - 1) {
            __syncthreads();           // all hperm writes issued, xp reads done
            if (tid == 0) {
                __threadfence();       // make them visible gpu-wide
                atomicAdd(&g_sync, 1u);
            }
        }

        // ---- phase B: non-critical writes + xp(t+1) prefetch (overlap) ----
#pragma unroll
        for (int i = 0; i < 2; i++) {
            int b = b_s[i], j = j_s[i];
            float hv = hv_s[i];
            size_t hi = (size_t)t * Bb * Hh + b * Hh + j;
            if (L == 1) {
                g_h1[hi] = hv;                                   // residual source
                int kc = (j & ~31) + qperm(j & 31);
                g_aperm2[(size_t)(t * Bb + b) * Ii + kc] =
                    __uint_as_float(f2tf(hv));                   // layer-2 GEMM A
            } else {
                float o11 = hv + g_h1[hi];
                dout[(size_t)TB * Hh + hi] = o11;                                   // out11
                dout[(size_t)2 * TB * Hh + ((size_t)(t * Bb + b)) * 2 * Hh + j] = o11;  // out14[:,:H]
            }
        }

        if (t < Tt - 1) {
            // prefetch next step's xp tile into the single Xs buffer
            const float* xpn = g_xp + (size_t)(t + 1) * Bb * G4;
            unsigned xb = smem_u32 + SM3_XS_OFF * 4;
#pragma unroll
            for (int i = 0; i < 2; i++) {
                int u = tid + (i << 9);
                int b = u >> 3, q = u & 7;
                cpa16(xb + (unsigned)(b * SM3_LDSX + q * 4) * 4,
                      xpn + (size_t)b * G4 + n0 + q * 4);
            }
            asm volatile("cp.async.commit_group;\n" ::: "memory");

            // ---- wait LATE: spin until all CTAs arrived for step t ----
            if (tid == 0) {
                unsigned tgt = (unsigned)(t + 1) * NBLK;
                while (*(volatile unsigned*)&g_sync < tgt) {}
                __threadfence();
            }
            __syncthreads();
        }
    }
}

// -------------------- launch --------------------
extern "C" void kernel_launch(void* const* d_in, const int* in_sizes, int n_in,
                              void* d_out, int out_size) {
    const float* input4 = (const float*)d_in[0];
    const float* input0 = (const float*)d_in[1];
    const float* w_ih6  = (const float*)d_in[2];
    const float* w_hh6  = (const float*)d_in[3];
    const float* b_ih6  = (const float*)d_in[4];
    const float* b_hh6  = (const float*)d_in[5];
    const float* w_ih10 = (const float*)d_in[6];
    const float* w_hh10 = (const float*)d_in[7];
    const float* b_ih10 = (const float*)d_in[8];
    const float* b_hh10 = (const float*)d_in[9];
    float* out = (float*)d_out;

    cudaFuncSetAttribute(lstm_layer<1>, cudaFuncAttributeMaxDynamicSharedMemorySize,
                         SM3_FL * 4);
    cudaFuncSetAttribute(lstm_layer<2>, cudaFuncAttributeMaxDynamicSharedMemorySize,
                         SM3_FL * 4);
    cudaFuncSetAttribute(gemm_xp<1>, cudaFuncAttributeMaxDynamicSharedMemorySize,
                         GEMM_SMEM_FL * 4);
    cudaFuncSetAttribute(gemm_xp<2>, cudaFuncAttributeMaxDynamicSharedMemorySize,
                         GEMM_SMEM_FL * 4);

    dim3 gx(G4 / 128, TB / 128);  // n-tile fastest -> A reuse in L2
    const int PW_GRID = (G4 * (Ii + Hh + 1)) / 256;  // 49168

    // launch order arranged so ncu's capture window lands on lstm_layer<1> (idx 3)
    permute_l<1><<<PW_GRID, 256>>>(w_ih6, w_hh6, b_ih6, b_hh6);      // 0
    prepA<<<(TB * Ii) / 256, 256>>>(input0, input4);                  // 1 (+sync reset)
    gemm_xp<1><<<gx, 256, GEMM_SMEM_FL * 4>>>();                      // 2
    lstm_layer<1><<<NBLK, 512, SM3_FL * 4>>>(out);                    // 3 <- profile me
    permute_l<2><<<PW_GRID, 256>>>(w_ih10, w_hh10, b_ih10, b_hh10);   // 4 (+sync reset)
    gemm_xp<2><<<gx, 256, GEMM_SMEM_FL * 4>>>();                      // 5
    lstm_layer<2><<<NBLK, 512, SM3_FL * 4>>>(out);                    // 6
    copy_out1<<<(TB * Hh / 4) / 256, 256>>>(input4, out);             // 7
}

// round 13
// speedup vs baseline: 1.2174x; 1.0256x over previous
#include <cuda_runtime.h>
#include <cstdint>

// ---------------------------------------------------------------------------
// Stage3 LSTM stack: out1 = input4
//                    out7 = LSTM1(concat(input0, input4))
//                    out11 = LSTM2(concat(out7, input4)) + out7
//                    out14 = concat(out11, input4)
// Outputs concatenated: [out1 (T*B*H)] [out11 (T*B*H)] [out14 (T*B*2H)]
// ---------------------------------------------------------------------------

#define Tt 128
#define Bb 128
#define Hh 1024
#define Ii 2048
#define G4 4096            // 4*H
#define TB 16384           // T*B
#define LDSW 36            // smem row stride in floats (32 + 4 pad)
#define NBLK 128           // persistent blocks (1 per SM)

// -------------------- device scratch (no allocs allowed) --------------------
__device__ float g_wih1[G4 * Ii];   // gate-interleaved rows + k-qperm cols, tf32
__device__ float g_whh1[G4 * Hh];   // gate-interleaved rows, natural cols, tf32
__device__ float g_b1[G4];
__device__ float g_wih2[G4 * Ii];
__device__ float g_whh2[G4 * Hh];
__device__ float g_b2[G4];
__device__ float g_aperm1[(size_t)TB * Ii];  // layer-1 A: [input0|input4], permuted+tf32
__device__ float g_aperm2[(size_t)TB * Ii];  // layer-2 A: [h1|input4], permuted+tf32
__device__ float g_xp[(size_t)TB * G4];      // input projection for current layer
__device__ float g_h1[(size_t)TB * Hh];      // layer-1 h (natural layout, = out7)
__device__ float g_hperm[2][Bb * Hh];        // ping-pong h, col-permuted + tf32
__device__ unsigned g_sync;                  // grid barrier counter

// -------------------- helpers --------------------
static __device__ __forceinline__ unsigned f2tf(float x) {
    unsigned u;
    asm("cvt.rna.tf32.f32 %0, %1;" : "=r"(u) : "f"(x));
    return u;
}

static __device__ __forceinline__ void mma_tf32(float c[4], const unsigned a[4],
                                                const unsigned b[2]) {
    asm volatile(
        "mma.sync.aligned.m16n8k8.row.col.f32.tf32.tf32.f32 "
        "{%0,%1,%2,%3}, {%4,%5,%6,%7}, {%8,%9}, {%0,%1,%2,%3};\n"
        : "+f"(c[0]), "+f"(c[1]), "+f"(c[2]), "+f"(c[3])
        : "r"(a[0]), "r"(a[1]), "r"(a[2]), "r"(a[3]), "r"(b[0]), "r"(b[1]));
}

// column permutation within a 32-wide K chunk: stored(kl) = (kl%4)*8 + kl/4
static __device__ __forceinline__ int qperm(int kl) {
    return ((kl & 3) << 3) + (kl >> 2);
}

static __device__ __forceinline__ void cpa16(unsigned dst, const float* src) {
    asm volatile("cp.async.cg.shared.global [%0], [%1], 16;\n" :: "r"(dst), "l"(src));
}

// fast activations (MUFU-backed, rel err ~1e-6)
static __device__ __forceinline__ float fsigmoid(float x) {
    return __fdividef(1.f, 1.f + __expf(-x));
}
static __device__ __forceinline__ float ftanh(float x) {
    return __fdividef(2.f, 1.f + __expf(-2.f * x)) - 1.f;
}

// -------------------- fused per-layer weight/bias permutation ----------------
template <int L>
__global__ void permute_l(const float* __restrict__ wih, const float* __restrict__ whh,
                          const float* __restrict__ bih, const float* __restrict__ bhh) {
    int idx = blockIdx.x * 256 + threadIdx.x;
    float* wo = (L == 1) ? g_wih1 : g_wih2;
    float* ho = (L == 1) ? g_whh1 : g_whh2;
    float* bo = (L == 1) ? g_b1 : g_b2;
    if (idx < G4 * Ii) {
        int n = idx >> 11, k = idx & 2047;
        int j = n >> 2, g = n & 3;
        float v = wih[((g * Hh + j) << 11) + k];
        int kp = (k & ~31) | qperm(k & 31);
        wo[(n << 11) | kp] = __uint_as_float(f2tf(v));
    } else if (idx < G4 * Ii + G4 * Hh) {
        int i2 = idx - G4 * Ii;
        int n = i2 >> 10, k = i2 & 1023;
        int j = n >> 2, g = n & 3;
        ho[(n << 10) + k] = __uint_as_float(f2tf(whh[((g * Hh + j) << 10) + k]));
    } else {
        int n = idx - G4 * Ii - G4 * Hh;
        int j = n >> 2, g = n & 3;
        bo[n] = bih[g * Hh + j] + bhh[g * Hh + j];
        if (L == 2 && n == 0) g_sync = 0;   // reset barrier for layer-2 pass
    }
}

// -------------------- A prepass: permuted + tf32-rounded ---------------------
__global__ void prepA(const float* __restrict__ in0, const float* __restrict__ in4) {
    int idx = blockIdx.x * 256 + threadIdx.x;
    if (idx == 0) g_sync = 0;  // reset barrier counter for layer 1
    int row = idx >> 11;
    int k = idx & 2047;
    int kp = (k & ~31) | qperm(k & 31);
    float v = (k < 1024) ? in0[(size_t)row * Hh + k]
                         : in4[(size_t)row * Hh + (k - 1024)];
    float tv = __uint_as_float(f2tf(v));
    g_aperm1[(size_t)row * Ii + kp] = tv;
    if (k >= 1024) g_aperm2[(size_t)row * Ii + kp] = tv;
}

// -------------------- out1 + out14 second-half copy --------------------
__global__ void copy_out1(const float* __restrict__ in4, float* __restrict__ out) {
    size_t i4 = (size_t)blockIdx.x * 256 + threadIdx.x;
    size_t e = i4 * 4;
    float4 v = *(const float4*)(in4 + e);
    *(float4*)(out + e) = v;                       // out1
    size_t tb = e >> 10;
    size_t j = e & (Hh - 1);
    *(float4*)(out + (size_t)2 * TB * Hh + tb * 2 * Hh + Hh + j) = v;  // out14[:,H:]
}

// -------------------- big GEMM: xp = Aperm @ W'^T + bias' -------------------
// 3-stage cp.async pipeline, ONE __syncthreads per k-iteration:
// wait(stage kc) -> sync -> issue cp(kc+2) into buffer (kc-1)%3 -> compute(kc)
#define GXS 4608                       // floats per stage per operand (128*LDSW)
#define GEMM_SMEM_FL (6 * GXS)         // 3 stages x (A,B) = 110592 bytes

template <int L>
__global__ void __launch_bounds__(256, 2)
gemm_xp() {
    const float* Ag = (L == 1) ? g_aperm1 : g_aperm2;
    const float* Wg = (L == 1) ? g_wih1 : g_wih2;
    const float* bias = (L == 1) ? g_b1 : g_b2;

    extern __shared__ float smem[];
    const unsigned smem_u32 = (unsigned)__cvta_generic_to_shared(smem);

    const int tid = threadIdx.x;
    const int lane = tid & 31;
    const int warp = tid >> 5;
    const int wm = (warp >> 1) << 5;   // 0,32,64,96
    const int wn = (warp & 1) << 6;    // 0,64
    const int lr = lane >> 2, lc = lane & 3;
    const int m0 = blockIdx.y * 128;
    const int n0 = blockIdx.x * 128;
    const int frow = tid >> 3, fqc = (tid & 7) << 2;

    float acc[2][8][4];
#pragma unroll
    for (int i = 0; i < 2; i++)
#pragma unroll
        for (int j = 0; j < 8; j++)
#pragma unroll
            for (int k = 0; k < 4; k++) acc[i][j][k] = 0.f;

    const float* Abase = Ag + (size_t)(m0 + frow) * Ii + fqc;
    const float* Bbase = Wg + (size_t)(n0 + frow) * Ii + fqc;
    const unsigned doff = (unsigned)(frow * LDSW + fqc) * 4;

#pragma unroll
    for (int pc = 0; pc < 2; pc++) {
        unsigned sa = smem_u32 + (pc * 2 * GXS) * 4 + doff;
        unsigned sb = smem_u32 + (pc * 2 * GXS + GXS) * 4 + doff;
#pragma unroll
        for (int i = 0; i < 4; i++) {
            cpa16(sa + (unsigned)(i * 32 * LDSW) * 4, Abase + (size_t)(i * 32) * Ii + pc * 32);
            cpa16(sb + (unsigned)(i * 32 * LDSW) * 4, Bbase + (size_t)(i * 32) * Ii + pc * 32);
        }
        asm volatile("cp.async.commit_group;\n" ::: "memory");
    }

    for (int kc = 0; kc < 64; kc++) {
        // wait for stage kc's data
        if (kc < 62) {
            asm volatile("cp.async.wait_group 1;\n" ::: "memory");
        } else {
            asm volatile("cp.async.wait_group 0;\n" ::: "memory");
        }
        __syncthreads();   // also separates compute(kc-1) reads from cp below

        // issue cp for stage kc+2 into buffer (kc+2)%3 == (kc-1)%3 (now free)
        if (kc < 62) {
            int nc = kc + 2;
            int st = nc % 3;
            unsigned sa = smem_u32 + (st * 2 * GXS) * 4 + doff;
            unsigned sb = smem_u32 + (st * 2 * GXS + GXS) * 4 + doff;
#pragma unroll
            for (int i = 0; i < 4; i++) {
                cpa16(sa + (unsigned)(i * 32 * LDSW) * 4, Abase + (size_t)(i * 32) * Ii + nc * 32);
                cpa16(sb + (unsigned)(i * 32 * LDSW) * 4, Bbase + (size_t)(i * 32) * Ii + nc * 32);
            }
            asm volatile("cp.async.commit_group;\n" ::: "memory");
        }

        const float* Ast = smem + (kc % 3) * 2 * GXS;
        const float* Bst = Ast + GXS;

        unsigned a[4][8];
#pragma unroll
        for (int i = 0; i < 4; i++) {
            int r = wm + ((i >> 1) << 4) + ((i & 1) << 3) + lr;
            const float4* p = (const float4*)&Ast[r * LDSW + lc * 8];
            float4 v0 = p[0], v1 = p[1];
            a[i][0] = __float_as_uint(v0.x); a[i][1] = __float_as_uint(v0.y);
            a[i][2] = __float_as_uint(v0.z); a[i][3] = __float_as_uint(v0.w);
            a[i][4] = __float_as_uint(v1.x); a[i][5] = __float_as_uint(v1.y);
            a[i][6] = __float_as_uint(v1.z); a[i][7] = __float_as_uint(v1.w);
        }

#pragma unroll
        for (int nt2 = 0; nt2 < 4; nt2++) {
            unsigned b0[8], b1[8];
            {
                int rb = wn + (2 * nt2) * 8 + lr;
                const float4* p = (const float4*)&Bst[rb * LDSW + lc * 8];
                float4 v0 = p[0], v1 = p[1];
                b0[0] = __float_as_uint(v0.x); b0[1] = __float_as_uint(v0.y);
                b0[2] = __float_as_uint(v0.z); b0[3] = __float_as_uint(v0.w);
                b0[4] = __float_as_uint(v1.x); b0[5] = __float_as_uint(v1.y);
                b0[6] = __float_as_uint(v1.z); b0[7] = __float_as_uint(v1.w);
            }
            {
                int rb = wn + (2 * nt2 + 1) * 8 + lr;
                const float4* p = (const float4*)&Bst[rb * LDSW + lc * 8];
                float4 v0 = p[0], v1 = p[1];
                b1[0] = __float_as_uint(v0.x); b1[1] = __float_as_uint(v0.y);
                b1[2] = __float_as_uint(v0.z); b1[3] = __float_as_uint(v0.w);
                b1[4] = __float_as_uint(v1.x); b1[5] = __float_as_uint(v1.y);
                b1[6] = __float_as_uint(v1.z); b1[7] = __float_as_uint(v1.w);
            }
#pragma unroll
            for (int kk = 0; kk < 4; kk++) {
                unsigned afr0[4] = {a[0][2 * kk], a[1][2 * kk],
                                    a[0][2 * kk + 1], a[1][2 * kk + 1]};
                unsigned afr1[4] = {a[2][2 * kk], a[3][2 * kk],
                                    a[2][2 * kk + 1], a[3][2 * kk + 1]};
                unsigned bfr0[2] = {b0[2 * kk], b0[2 * kk + 1]};
                unsigned bfr1[2] = {b1[2 * kk], b1[2 * kk + 1]};
                mma_tf32(acc[0][2 * nt2], afr0, bfr0);
                mma_tf32(acc[0][2 * nt2 + 1], afr0, bfr1);
                mma_tf32(acc[1][2 * nt2], afr1, bfr0);
                mma_tf32(acc[1][2 * nt2 + 1], afr1, bfr1);
            }
        }
    }

#pragma unroll
    for (int mt = 0; mt < 2; mt++) {
        int r = m0 + wm + mt * 16 + lr;
#pragma unroll
        for (int nt = 0; nt < 8; nt++) {
            int c = n0 + wn + nt * 8 + 2 * lc;
            float2 bv = *(const float2*)&bias[c];
            float2 v0 = make_float2(acc[mt][nt][0] + bv.x, acc[mt][nt][1] + bv.y);
            float2 v1 = make_float2(acc[mt][nt][2] + bv.x, acc[mt][nt][3] + bv.y);
            *(float2*)&g_xp[(size_t)r * G4 + c] = v0;
            *(float2*)&g_xp[(size_t)(r + 8) * G4 + c] = v1;
        }
    }
}

// -------------------- persistent recurrent layer --------------------
// 128 CTAs x 512 threads (16 warps). CTA owns 32 gate-cols (8 hidden units).
// 4-way k-split: warp = 32 batch rows x 32 gate cols x 256 k.
// 16-k chunks, A prefetch distance 2. Four Gs partial buffers; single xp
// buffer. Arrive-early / wait-late barrier with nanosleep-backed spin;
// streaming stores for phase-B outputs.
#define SM3_WS_LD 1028                  // 1028 % 32 == 4 -> conflict-free frags
#define SM3_WS_SZ (32 * SM3_WS_LD)      // 32896 floats
#define SM3_LDSG 36                     // Gs row stride (144 B, 16B-aligned)
#define SM3_GS_STRIDE (128 * SM3_LDSG)  // 4608 floats per Gs buffer
#define SM3_LDSX 32                     // xp row stride (128 B, 16B-aligned)
#define SM3_XS_OFF (SM3_WS_SZ + 4 * SM3_GS_STRIDE)      // 51328
#define SM3_FL (SM3_XS_OFF + 128 * SM3_LDSX)            // 55424 fl = 221696 B

template <int L>
__global__ void __launch_bounds__(512, 1)
lstm_layer(float* __restrict__ dout) {
    extern __shared__ float smem[];
    float* Ws = smem;
    float* Gs = smem + SM3_WS_SZ;
    float* Xs = smem + SM3_XS_OFF;
    const unsigned smem_u32 = (unsigned)__cvta_generic_to_shared(smem);

    const int tid = threadIdx.x;
    const int bid = blockIdx.x;
    const int lane = tid & 31;
    const int warp = tid >> 5;         // 0..15
    const int mq = warp >> 2;          // m-group 0..3 (32 batch rows each)
    const int kq = warp & 3;           // k-quarter 0..3 (256 k each)
    const int wm = mq << 5;            // batch row base
    const int kb = kq << 8;            // k base
    const int lr = lane >> 2, lc = lane & 3;
    const int n0 = bid * 32;           // gate-col base
    float* GsW = Gs + kq * SM3_GS_STRIDE;

    const float* Wg = (L == 1) ? g_whh1 : g_whh2;

    // load W slice into smem with per-chunk column permutation
    for (int idx = tid; idx < 32 * 1024; idx += 512) {
        int n = idx >> 10;
        int k = idx & 1023;
        int kc = (k & ~31) + qperm(k & 31);
        Ws[n * SM3_WS_LD + kc] = Wg[(size_t)(n0 + n) * Hh + k];
    }
    // prefetch xp tile for t=0
    {
        unsigned xb = smem_u32 + SM3_XS_OFF * 4;
#pragma unroll
        for (int i = 0; i < 2; i++) {
            int u = tid + (i << 9);
            int b = u >> 3, q = u & 7;
            cpa16(xb + (unsigned)(b * SM3_LDSX + q * 4) * 4,
                  g_xp + (size_t)b * G4 + n0 + q * 4);
        }
        asm volatile("cp.async.commit_group;\n" ::: "memory");
    }
    __syncthreads();

    float creg[2];
    creg[0] = 0.f; creg[1] = 0.f;

    for (int t = 0; t < Tt; t++) {
        float acc[2][4][4];
#pragma unroll
        for (int i = 0; i < 2; i++)
#pragma unroll
            for (int j = 0; j < 4; j++)
#pragma unroll
                for (int k = 0; k < 4; k++) acc[i][j][k] = 0.f;

        if (t > 0) {
            const float* hp = g_hperm[(t - 1) & 1];
            const float* rp0 = hp + (size_t)(wm + lr) * Hh + kb + lc * 8;
            const float* rp1 = hp + (size_t)(wm + 8 + lr) * Hh + kb + lc * 8;
            const float* rp2 = hp + (size_t)(wm + 16 + lr) * Hh + kb + lc * 8;
            const float* rp3 = hp + (size_t)(wm + 24 + lr) * Hh + kb + lc * 8;
#define AOFF(c) (((c) >> 1) * 32 + ((c) & 1) * 4)
            float4 A0[4], A1[4];
            A0[0] = __ldcg((const float4*)(rp0 + AOFF(0)));
            A0[1] = __ldcg((const float4*)(rp1 + AOFF(0)));
            A0[2] = __ldcg((const float4*)(rp2 + AOFF(0)));
            A0[3] = __ldcg((const float4*)(rp3 + AOFF(0)));
            A1[0] = __ldcg((const float4*)(rp0 + AOFF(1)));
            A1[1] = __ldcg((const float4*)(rp1 + AOFF(1)));
            A1[2] = __ldcg((const float4*)(rp2 + AOFF(1)));
            A1[3] = __ldcg((const float4*)(rp3 + AOFF(1)));

#pragma unroll
            for (int c = 0; c < 16; c++) {
                float4 An[4];
                if (c < 14) {
                    int o = AOFF(c + 2);
                    An[0] = __ldcg((const float4*)(rp0 + o));
                    An[1] = __ldcg((const float4*)(rp1 + o));
                    An[2] = __ldcg((const float4*)(rp2 + o));
                    An[3] = __ldcg((const float4*)(rp3 + o));
                }
                unsigned ax[4][4];
#pragma unroll
                for (int i = 0; i < 4; i++) {
                    ax[i][0] = __float_as_uint(A0[i].x);
                    ax[i][1] = __float_as_uint(A0[i].y);
                    ax[i][2] = __float_as_uint(A0[i].z);
                    ax[i][3] = __float_as_uint(A0[i].w);
                }
#pragma unroll
                for (int np = 0; np < 2; np++) {
                    const int boff = kb + AOFF(c) + lc * 8;
                    float4 Bv0 = *(const float4*)
                        &Ws[((2 * np) * 8 + lr) * SM3_WS_LD + boff];
                    float4 Bv1 = *(const float4*)
                        &Ws[((2 * np + 1) * 8 + lr) * SM3_WS_LD + boff];
                    unsigned b0[4] = {__float_as_uint(Bv0.x), __float_as_uint(Bv0.y),
                                      __float_as_uint(Bv0.z), __float_as_uint(Bv0.w)};
                    unsigned b1[4] = {__float_as_uint(Bv1.x), __float_as_uint(Bv1.y),
                                      __float_as_uint(Bv1.z), __float_as_uint(Bv1.w)};
#pragma unroll
                    for (int kk = 0; kk < 2; kk++) {
#pragma unroll
                        for (int mt = 0; mt < 2; mt++) {
                            unsigned afr[4] = {ax[2 * mt][2 * kk], ax[2 * mt + 1][2 * kk],
                                               ax[2 * mt][2 * kk + 1], ax[2 * mt + 1][2 * kk + 1]};
                            unsigned bfr0[2] = {b0[2 * kk], b0[2 * kk + 1]};
                            unsigned bfr1[2] = {b1[2 * kk], b1[2 * kk + 1]};
                            mma_tf32(acc[mt][2 * np], afr, bfr0);
                            mma_tf32(acc[mt][2 * np + 1], afr, bfr1);
                        }
                    }
                }
#pragma unroll
                for (int i = 0; i < 4; i++) { A0[i] = A1[i]; A1[i] = An[i]; }
            }
#undef AOFF
        }

        // stash partial gates to this k-quarter's buffer (32 rows per warp)
#pragma unroll
        for (int mt = 0; mt < 2; mt++) {
#pragma unroll
            for (int nt = 0; nt < 4; nt++) {
                int c = nt * 8 + 2 * lc;
                *(float2*)&GsW[(wm + mt * 16 + lr) * SM3_LDSG + c] =
                    make_float2(acc[mt][nt][0], acc[mt][nt][1]);
                *(float2*)&GsW[(wm + mt * 16 + 8 + lr) * SM3_LDSG + c] =
                    make_float2(acc[mt][nt][2], acc[mt][nt][3]);
            }
        }
        asm volatile("cp.async.wait_group 0;\n" ::: "memory");  // xp(t) resident
        __syncthreads();

        // ---- epilogue phase A: cell update + hperm write (critical path) ----
        float* hpw = g_hperm[t & 1];
        float hv_s[2];
        int b_s[2], j_s[2];
#pragma unroll
        for (int i = 0; i < 2; i++) {
            int u = tid + (i << 9);
            int b = u >> 3;
            int jl = u & 7;
            float4 x4 = *(const float4*)&Xs[b * SM3_LDSX + (jl << 2)];
            float4 p0 = *(const float4*)&Gs[b * SM3_LDSG + (jl << 2)];
            float4 p1 = *(const float4*)&Gs[SM3_GS_STRIDE + b * SM3_LDSG + (jl << 2)];
            float4 p2 = *(const float4*)&Gs[2 * SM3_GS_STRIDE + b * SM3_LDSG + (jl << 2)];
            float4 p3 = *(const float4*)&Gs[3 * SM3_GS_STRIDE + b * SM3_LDSG + (jl << 2)];
            float gi = (p0.x + p1.x) + (p2.x + p3.x) + x4.x;
            float gf = (p0.y + p1.y) + (p2.y + p3.y) + x4.y;
            float gg = (p0.z + p1.z) + (p2.z + p3.z) + x4.z;
            float go = (p0.w + p1.w) + (p2.w + p3.w) + x4.w;
            float iv = fsigmoid(gi);
            float fv = fsigmoid(gf);
            float gv = ftanh(gg);
            float ov = fsigmoid(go);
            float cv = fv * creg[i] + iv * gv;
            creg[i] = cv;
            float hv = ov * ftanh(cv);
            int j = (n0 >> 2) + jl;
            int kc = (j & ~31) + qperm(j & 31);
            hpw[b * Hh + kc] = __uint_as_float(f2tf(hv));
            hv_s[i] = hv; b_s[i] = b; j_s[i] = j;
        }

        // ---- arrive EARLY: publish this CTA's step completion ----
        // (this __syncthreads also orders all xp(t) reads before the
        //  xp(t+1) prefetch below reuses the single Xs buffer)
        if (t < Tt - 1) {
            __syncthreads();           // all hperm writes issued, xp reads done
            if (tid == 0) {
                __threadfence();       // make them visible gpu-wide
                atomicAdd(&g_sync, 1u);
            }

            // xp(t+1) prefetch first: maximize cp.async lead time
            const float* xpn = g_xp + (size_t)(t + 1) * Bb * G4;
            unsigned xb = smem_u32 + SM3_XS_OFF * 4;
#pragma unroll
            for (int i = 0; i < 2; i++) {
                int u = tid + (i << 9);
                int b = u >> 3, q = u & 7;
                cpa16(xb + (unsigned)(b * SM3_LDSX + q * 4) * 4,
                      xpn + (size_t)b * G4 + n0 + q * 4);
            }
            asm volatile("cp.async.commit_group;\n" ::: "memory");
        }

        // ---- phase B: non-critical writes (streaming stores, overlap) ----
#pragma unroll
        for (int i = 0; i < 2; i++) {
            int b = b_s[i], j = j_s[i];
            float hv = hv_s[i];
            size_t hi = (size_t)t * Bb * Hh + b * Hh + j;
            if (L == 1) {
                __stcs(&g_h1[hi], hv);                           // residual source
                int kc = (j & ~31) + qperm(j & 31);
                __stcs(&g_aperm2[(size_t)(t * Bb + b) * Ii + kc],
                       __uint_as_float(f2tf(hv)));               // layer-2 GEMM A
            } else {
                float o11 = hv + g_h1[hi];
                __stcs(&dout[(size_t)TB * Hh + hi], o11);                            // out11
                __stcs(&dout[(size_t)2 * TB * Hh + ((size_t)(t * Bb + b)) * 2 * Hh + j],
                       o11);                                                          // out14[:,:H]
            }
        }

        if (t < Tt - 1) {
            // ---- wait LATE: spin until all CTAs arrived for step t ----
            if (tid == 0) {
                unsigned tgt = (unsigned)(t + 1) * NBLK;
                while (*(volatile unsigned*)&g_sync < tgt) { __nanosleep(32); }
                __threadfence();
            }
            __syncthreads();
        }
    }
}

// -------------------- launch --------------------
extern "C" void kernel_launch(void* const* d_in, const int* in_sizes, int n_in,
                              void* d_out, int out_size) {
    const float* input4 = (const float*)d_in[0];
    const float* input0 = (const float*)d_in[1];
    const float* w_ih6  = (const float*)d_in[2];
    const float* w_hh6  = (const float*)d_in[3];
    const float* b_ih6  = (const float*)d_in[4];
    const float* b_hh6  = (const float*)d_in[5];
    const float* w_ih10 = (const float*)d_in[6];
    const float* w_hh10 = (const float*)d_in[7];
    const float* b_ih10 = (const float*)d_in[8];
    const float* b_hh10 = (const float*)d_in[9];
    float* out = (float*)d_out;

    cudaFuncSetAttribute(lstm_layer<1>, cudaFuncAttributeMaxDynamicSharedMemorySize,
                         SM3_FL * 4);
    cudaFuncSetAttribute(lstm_layer<2>, cudaFuncAttributeMaxDynamicSharedMemorySize,
                         SM3_FL * 4);
    cudaFuncSetAttribute(gemm_xp<1>, cudaFuncAttributeMaxDynamicSharedMemorySize,
                         GEMM_SMEM_FL * 4);
    cudaFuncSetAttribute(gemm_xp<2>, cudaFuncAttributeMaxDynamicSharedMemorySize,
                         GEMM_SMEM_FL * 4);

    dim3 gx(G4 / 128, TB / 128);  // n-tile fastest -> A reuse in L2
    const int PW_GRID = (G4 * (Ii + Hh + 1)) / 256;  // 49168

    // launch order arranged so ncu's capture window lands on lstm_layer<1> (idx 3)
    permute_l<1><<<PW_GRID, 256>>>(w_ih6, w_hh6, b_ih6, b_hh6);      // 0
    prepA<<<(TB * Ii) / 256, 256>>>(input0, input4);                  // 1 (+sync reset)
    gemm_xp<1><<<gx, 256, GEMM_SMEM_FL * 4>>>();                      // 2
    lstm_layer<1><<<NBLK, 512, SM3_FL * 4>>>(out);                    // 3 <- profile me
    permute_l<2><<<PW_GRID, 256>>>(w_ih10, w_hh10, b_ih10, b_hh10);   // 4 (+sync reset)
    gemm_xp<2><<<gx, 256, GEMM_SMEM_FL * 4>>>();                      // 5
    lstm_layer<2><<<NBLK, 512, SM3_FL * 4>>>(out);                    // 6
    copy_out1<<<(TB * Hh / 4) / 256, 256>>>(input4, out);             // 7
}

// round 14
// speedup vs baseline: 1.2355x; 1.0149x over previous
#include <cuda_runtime.h>
#include <cstdint>

// ---------------------------------------------------------------------------
// Stage3 LSTM stack: out1 = input4
//                    out7 = LSTM1(concat(input0, input4))
//                    out11 = LSTM2(concat(out7, input4)) + out7
//                    out14 = concat(out11, input4)
// Outputs concatenated: [out1 (T*B*H)] [out11 (T*B*H)] [out14 (T*B*2H)]
// ---------------------------------------------------------------------------

#define Tt 128
#define Bb 128
#define Hh 1024
#define Ii 2048
#define G4 4096            // 4*H
#define TB 16384           // T*B
#define LDSW 36            // smem row stride in floats (32 + 4 pad)
#define NBLK 128           // persistent blocks (1 per SM)

// -------------------- device scratch (no allocs allowed) --------------------
__device__ float g_wih1[G4 * Ii];   // gate-interleaved rows + k-qperm cols, tf32
__device__ float g_whh1[G4 * Hh];   // gate-interleaved rows, natural cols, tf32
__device__ float g_b1[G4];
__device__ float g_wih2[G4 * Ii];
__device__ float g_whh2[G4 * Hh];
__device__ float g_b2[G4];
__device__ float g_aperm1[(size_t)TB * Ii];  // layer-1 A: [input0|input4], permuted+tf32
__device__ float g_aperm2[(size_t)TB * Ii];  // layer-2 A: [h1|input4], permuted+tf32
__device__ float g_xp[(size_t)TB * G4];      // input projection for current layer
__device__ float g_h1[(size_t)TB * Hh];      // layer-1 h (natural layout, = out7)
__device__ float g_hperm[2][Bb * Hh];        // ping-pong h, col-permuted + tf32
__device__ unsigned g_syncq[4];              // per-k-quarter arrival counters

// -------------------- helpers --------------------
static __device__ __forceinline__ unsigned f2tf(float x) {
    unsigned u;
    asm("cvt.rna.tf32.f32 %0, %1;" : "=r"(u) : "f"(x));
    return u;
}

static __device__ __forceinline__ void mma_tf32(float c[4], const unsigned a[4],
                                                const unsigned b[2]) {
    asm volatile(
        "mma.sync.aligned.m16n8k8.row.col.f32.tf32.tf32.f32 "
        "{%0,%1,%2,%3}, {%4,%5,%6,%7}, {%8,%9}, {%0,%1,%2,%3};\n"
        : "+f"(c[0]), "+f"(c[1]), "+f"(c[2]), "+f"(c[3])
        : "r"(a[0]), "r"(a[1]), "r"(a[2]), "r"(a[3]), "r"(b[0]), "r"(b[1]));
}

// column permutation within a 32-wide K chunk: stored(kl) = (kl%4)*8 + kl/4
static __device__ __forceinline__ int qperm(int kl) {
    return ((kl & 3) << 3) + (kl >> 2);
}

static __device__ __forceinline__ void cpa16(unsigned dst, const float* src) {
    asm volatile("cp.async.cg.shared.global [%0], [%1], 16;\n" :: "r"(dst), "l"(src));
}

// fast activations (MUFU-backed, rel err ~1e-6)
static __device__ __forceinline__ float fsigmoid(float x) {
    return __fdividef(1.f, 1.f + __expf(-x));
}
static __device__ __forceinline__ float ftanh(float x) {
    return __fdividef(2.f, 1.f + __expf(-2.f * x)) - 1.f;
}

// -------------------- fused per-layer weight/bias permutation ----------------
template <int L>
__global__ void permute_l(const float* __restrict__ wih, const float* __restrict__ whh,
                          const float* __restrict__ bih, const float* __restrict__ bhh) {
    int idx = blockIdx.x * 256 + threadIdx.x;
    float* wo = (L == 1) ? g_wih1 : g_wih2;
    float* ho = (L == 1) ? g_whh1 : g_whh2;
    float* bo = (L == 1) ? g_b1 : g_b2;
    if (idx < G4 * Ii) {
        int n = idx >> 11, k = idx & 2047;
        int j = n >> 2, g = n & 3;
        float v = wih[((g * Hh + j) << 11) + k];
        int kp = (k & ~31) | qperm(k & 31);
        wo[(n << 11) | kp] = __uint_as_float(f2tf(v));
    } else if (idx < G4 * Ii + G4 * Hh) {
        int i2 = idx - G4 * Ii;
        int n = i2 >> 10, k = i2 & 1023;
        int j = n >> 2, g = n & 3;
        ho[(n << 10) + k] = __uint_as_float(f2tf(whh[((g * Hh + j) << 10) + k]));
    } else {
        int n = idx - G4 * Ii - G4 * Hh;
        int j = n >> 2, g = n & 3;
        bo[n] = bih[g * Hh + j] + bhh[g * Hh + j];
        if (L == 2 && n < 4) g_syncq[n] = 0;   // reset counters for layer-2 pass
    }
}

// -------------------- A prepass: permuted + tf32-rounded ---------------------
__global__ void prepA(const float* __restrict__ in0, const float* __restrict__ in4) {
    int idx = blockIdx.x * 256 + threadIdx.x;
    if (idx < 4) g_syncq[idx] = 0;  // reset counters for layer-1 pass
    int row = idx >> 11;
    int k = idx & 2047;
    int kp = (k & ~31) | qperm(k & 31);
    float v = (k < 1024) ? in0[(size_t)row * Hh + k]
                         : in4[(size_t)row * Hh + (k - 1024)];
    float tv = __uint_as_float(f2tf(v));
    g_aperm1[(size_t)row * Ii + kp] = tv;
    if (k >= 1024) g_aperm2[(size_t)row * Ii + kp] = tv;
}

// -------------------- out1 + out14 second-half copy --------------------
__global__ void copy_out1(const float* __restrict__ in4, float* __restrict__ out) {
    size_t i4 = (size_t)blockIdx.x * 256 + threadIdx.x;
    size_t e = i4 * 4;
    float4 v = *(const float4*)(in4 + e);
    *(float4*)(out + e) = v;                       // out1
    size_t tb = e >> 10;
    size_t j = e & (Hh - 1);
    *(float4*)(out + (size_t)2 * TB * Hh + tb * 2 * Hh + Hh + j) = v;  // out14[:,H:]
}

// -------------------- big GEMM: xp = Aperm @ W'^T + bias' -------------------
// 3-stage cp.async pipeline, ONE __syncthreads per k-iteration.
#define GXS 4608                       // floats per stage per operand (128*LDSW)
#define GEMM_SMEM_FL (6 * GXS)         // 3 stages x (A,B) = 110592 bytes

template <int L>
__global__ void __launch_bounds__(256, 2)
gemm_xp() {
    const float* Ag = (L == 1) ? g_aperm1 : g_aperm2;
    const float* Wg = (L == 1) ? g_wih1 : g_wih2;
    const float* bias = (L == 1) ? g_b1 : g_b2;

    extern __shared__ float smem[];
    const unsigned smem_u32 = (unsigned)__cvta_generic_to_shared(smem);

    const int tid = threadIdx.x;
    const int lane = tid & 31;
    const int warp = tid >> 5;
    const int wm = (warp >> 1) << 5;   // 0,32,64,96
    const int wn = (warp & 1) << 6;    // 0,64
    const int lr = lane >> 2, lc = lane & 3;
    const int m0 = blockIdx.y * 128;
    const int n0 = blockIdx.x * 128;
    const int frow = tid >> 3, fqc = (tid & 7) << 2;

    float acc[2][8][4];
#pragma unroll
    for (int i = 0; i < 2; i++)
#pragma unroll
        for (int j = 0; j < 8; j++)
#pragma unroll
            for (int k = 0; k < 4; k++) acc[i][j][k] = 0.f;

    const float* Abase = Ag + (size_t)(m0 + frow) * Ii + fqc;
    const float* Bbase = Wg + (size_t)(n0 + frow) * Ii + fqc;
    const unsigned doff = (unsigned)(frow * LDSW + fqc) * 4;

#pragma unroll
    for (int pc = 0; pc < 2; pc++) {
        unsigned sa = smem_u32 + (pc * 2 * GXS) * 4 + doff;
        unsigned sb = smem_u32 + (pc * 2 * GXS + GXS) * 4 + doff;
#pragma unroll
        for (int i = 0; i < 4; i++) {
            cpa16(sa + (unsigned)(i * 32 * LDSW) * 4, Abase + (size_t)(i * 32) * Ii + pc * 32);
            cpa16(sb + (unsigned)(i * 32 * LDSW) * 4, Bbase + (size_t)(i * 32) * Ii + pc * 32);
        }
        asm volatile("cp.async.commit_group;\n" ::: "memory");
    }

    for (int kc = 0; kc < 64; kc++) {
        if (kc < 62) {
            asm volatile("cp.async.wait_group 1;\n" ::: "memory");
        } else {
            asm volatile("cp.async.wait_group 0;\n" ::: "memory");
        }
        __syncthreads();   // also separates compute(kc-1) reads from cp below

        if (kc < 62) {
            int nc = kc + 2;
            int st = nc % 3;
            unsigned sa = smem_u32 + (st * 2 * GXS) * 4 + doff;
            unsigned sb = smem_u32 + (st * 2 * GXS + GXS) * 4 + doff;
#pragma unroll
            for (int i = 0; i < 4; i++) {
                cpa16(sa + (unsigned)(i * 32 * LDSW) * 4, Abase + (size_t)(i * 32) * Ii + nc * 32);
                cpa16(sb + (unsigned)(i * 32 * LDSW) * 4, Bbase + (size_t)(i * 32) * Ii + nc * 32);
            }
            asm volatile("cp.async.commit_group;\n" ::: "memory");
        }

        const float* Ast = smem + (kc % 3) * 2 * GXS;
        const float* Bst = Ast + GXS;

        unsigned a[4][8];
#pragma unroll
        for (int i = 0; i < 4; i++) {
            int r = wm + ((i >> 1) << 4) + ((i & 1) << 3) + lr;
            const float4* p = (const float4*)&Ast[r * LDSW + lc * 8];
            float4 v0 = p[0], v1 = p[1];
            a[i][0] = __float_as_uint(v0.x); a[i][1] = __float_as_uint(v0.y);
            a[i][2] = __float_as_uint(v0.z); a[i][3] = __float_as_uint(v0.w);
            a[i][4] = __float_as_uint(v1.x); a[i][5] = __float_as_uint(v1.y);
            a[i][6] = __float_as_uint(v1.z); a[i][7] = __float_as_uint(v1.w);
        }

#pragma unroll
        for (int nt2 = 0; nt2 < 4; nt2++) {
            unsigned b0[8], b1[8];
            {
                int rb = wn + (2 * nt2) * 8 + lr;
                const float4* p = (const float4*)&Bst[rb * LDSW + lc * 8];
                float4 v0 = p[0], v1 = p[1];
                b0[0] = __float_as_uint(v0.x); b0[1] = __float_as_uint(v0.y);
                b0[2] = __float_as_uint(v0.z); b0[3] = __float_as_uint(v0.w);
                b0[4] = __float_as_uint(v1.x); b0[5] = __float_as_uint(v1.y);
                b0[6] = __float_as_uint(v1.z); b0[7] = __float_as_uint(v1.w);
            }
            {
                int rb = wn + (2 * nt2 + 1) * 8 + lr;
                const float4* p = (const float4*)&Bst[rb * LDSW + lc * 8];
                float4 v0 = p[0], v1 = p[1];
                b1[0] = __float_as_uint(v0.x); b1[1] = __float_as_uint(v0.y);
                b1[2] = __float_as_uint(v0.z); b1[3] = __float_as_uint(v0.w);
                b1[4] = __float_as_uint(v1.x); b1[5] = __float_as_uint(v1.y);
                b1[6] = __float_as_uint(v1.z); b1[7] = __float_as_uint(v1.w);
            }
#pragma unroll
            for (int kk = 0; kk < 4; kk++) {
                unsigned afr0[4] = {a[0][2 * kk], a[1][2 * kk],
                                    a[0][2 * kk + 1], a[1][2 * kk + 1]};
                unsigned afr1[4] = {a[2][2 * kk], a[3][2 * kk],
                                    a[2][2 * kk + 1], a[3][2 * kk + 1]};
                unsigned bfr0[2] = {b0[2 * kk], b0[2 * kk + 1]};
                unsigned bfr1[2] = {b1[2 * kk], b1[2 * kk + 1]};
                mma_tf32(acc[0][2 * nt2], afr0, bfr0);
                mma_tf32(acc[0][2 * nt2 + 1], afr0, bfr1);
                mma_tf32(acc[1][2 * nt2], afr1, bfr0);
                mma_tf32(acc[1][2 * nt2 + 1], afr1, bfr1);
            }
        }
    }

#pragma unroll
    for (int mt = 0; mt < 2; mt++) {
        int r = m0 + wm + mt * 16 + lr;
#pragma unroll
        for (int nt = 0; nt < 8; nt++) {
            int c = n0 + wn + nt * 8 + 2 * lc;
            float2 bv = *(const float2*)&bias[c];
            float2 v0 = make_float2(acc[mt][nt][0] + bv.x, acc[mt][nt][1] + bv.y);
            float2 v1 = make_float2(acc[mt][nt][2] + bv.x, acc[mt][nt][3] + bv.y);
            *(float2*)&g_xp[(size_t)r * G4 + c] = v0;
            *(float2*)&g_xp[(size_t)(r + 8) * G4 + c] = v1;
        }
    }
}

// -------------------- persistent recurrent layer --------------------
// 128 CTAs x 512 threads (16 warps). CTA owns 32 gate-cols (8 hidden units).
// 4-way k-split: warp = 32 batch rows x 32 gate cols x 256 k.
// Hierarchical sync: CTA bid produces h cols in k-quarter bid>>5; after its
// hperm writes it does ONE red.release.gpu.add on g_syncq[bid>>5]. Each GEMM
// warp acquire-polls only its quarter's counter (lane 0, nanosleep backoff)
// -> no threadfence, no global single-counter contention, no tail barrier.
#define SM3_WS_LD 1028                  // 1028 % 32 == 4 -> conflict-free frags
#define SM3_WS_SZ (32 * SM3_WS_LD)      // 32896 floats
#define SM3_LDSG 36                     // Gs row stride (144 B, 16B-aligned)
#define SM3_GS_STRIDE (128 * SM3_LDSG)  // 4608 floats per Gs buffer
#define SM3_LDSX 32                     // xp row stride (128 B, 16B-aligned)
#define SM3_XS_OFF (SM3_WS_SZ + 4 * SM3_GS_STRIDE)      // 51328
#define SM3_FL (SM3_XS_OFF + 128 * SM3_LDSX)            // 55424 fl = 221696 B

template <int L>
__global__ void __launch_bounds__(512, 1)
lstm_layer(float* __restrict__ dout) {
    extern __shared__ float smem[];
    float* Ws = smem;
    float* Gs = smem + SM3_WS_SZ;
    float* Xs = smem + SM3_XS_OFF;
    const unsigned smem_u32 = (unsigned)__cvta_generic_to_shared(smem);

    const int tid = threadIdx.x;
    const int bid = blockIdx.x;
    const int lane = tid & 31;
    const int warp = tid >> 5;         // 0..15
    const int mq = warp >> 2;          // m-group 0..3 (32 batch rows each)
    const int kq = warp & 3;           // k-quarter 0..3 (256 k each)
    const int wm = mq << 5;            // batch row base
    const int kb = kq << 8;            // k base
    const int lr = lane >> 2, lc = lane & 3;
    const int n0 = bid * 32;           // gate-col base
    float* GsW = Gs + kq * SM3_GS_STRIDE;

    const float* Wg = (L == 1) ? g_whh1 : g_whh2;

    // load W slice into smem with per-chunk column permutation
    for (int idx = tid; idx < 32 * 1024; idx += 512) {
        int n = idx >> 10;
        int k = idx & 1023;
        int kc = (k & ~31) + qperm(k & 31);
        Ws[n * SM3_WS_LD + kc] = Wg[(size_t)(n0 + n) * Hh + k];
    }
    // prefetch xp tile for t=0
    {
        unsigned xb = smem_u32 + SM3_XS_OFF * 4;
#pragma unroll
        for (int i = 0; i < 2; i++) {
            int u = tid + (i << 9);
            int b = u >> 3, q = u & 7;
            cpa16(xb + (unsigned)(b * SM3_LDSX + q * 4) * 4,
                  g_xp + (size_t)b * G4 + n0 + q * 4);
        }
        asm volatile("cp.async.commit_group;\n" ::: "memory");
    }
    __syncthreads();

    float creg[2];
    creg[0] = 0.f; creg[1] = 0.f;

    for (int t = 0; t < Tt; t++) {
        float acc[2][4][4];
#pragma unroll
        for (int i = 0; i < 2; i++)
#pragma unroll
            for (int j = 0; j < 4; j++)
#pragma unroll
                for (int k = 0; k < 4; k++) acc[i][j][k] = 0.f;

        if (t > 0) {
            // ---- per-warp acquire-wait on this k-quarter's 32 producers ----
            if (lane == 0) {
                const unsigned* cp = &g_syncq[kq];
                unsigned v;
                for (;;) {
                    asm volatile("ld.acquire.gpu.global.u32 %0, [%1];"
                                 : "=r"(v) : "l"(cp) : "memory");
                    if (v >= (unsigned)(32 * t)) break;
                    __nanosleep(32);
                }
            }
            __syncwarp();

            const float* hp = g_hperm[(t - 1) & 1];
            const float* rp0 = hp + (size_t)(wm + lr) * Hh + kb + lc * 8;
            const float* rp1 = hp + (size_t)(wm + 8 + lr) * Hh + kb + lc * 8;
            const float* rp2 = hp + (size_t)(wm + 16 + lr) * Hh + kb + lc * 8;
            const float* rp3 = hp + (size_t)(wm + 24 + lr) * Hh + kb + lc * 8;
#define AOFF(c) (((c) >> 1) * 32 + ((c) & 1) * 4)
            float4 A0[4], A1[4];
            A0[0] = __ldcg((const float4*)(rp0 + AOFF(0)));
            A0[1] = __ldcg((const float4*)(rp1 + AOFF(0)));
            A0[2] = __ldcg((const float4*)(rp2 + AOFF(0)));
            A0[3] = __ldcg((const float4*)(rp3 + AOFF(0)));
            A1[0] = __ldcg((const float4*)(rp0 + AOFF(1)));
            A1[1] = __ldcg((const float4*)(rp1 + AOFF(1)));
            A1[2] = __ldcg((const float4*)(rp2 + AOFF(1)));
            A1[3] = __ldcg((const float4*)(rp3 + AOFF(1)));

#pragma unroll
            for (int c = 0; c < 16; c++) {
                float4 An[4];
                if (c < 14) {
                    int o = AOFF(c + 2);
                    An[0] = __ldcg((const float4*)(rp0 + o));
                    An[1] = __ldcg((const float4*)(rp1 + o));
                    An[2] = __ldcg((const float4*)(rp2 + o));
                    An[3] = __ldcg((const float4*)(rp3 + o));
                }
                unsigned ax[4][4];
#pragma unroll
                for (int i = 0; i < 4; i++) {
                    ax[i][0] = __float_as_uint(A0[i].x);
                    ax[i][1] = __float_as_uint(A0[i].y);
                    ax[i][2] = __float_as_uint(A0[i].z);
                    ax[i][3] = __float_as_uint(A0[i].w);
                }
#pragma unroll
                for (int np = 0; np < 2; np++) {
                    const int boff = kb + AOFF(c) + lc * 8;
                    float4 Bv0 = *(const float4*)
                        &Ws[((2 * np) * 8 + lr) * SM3_WS_LD + boff];
                    float4 Bv1 = *(const float4*)
                        &Ws[((2 * np + 1) * 8 + lr) * SM3_WS_LD + boff];
                    unsigned b0[4] = {__float_as_uint(Bv0.x), __float_as_uint(Bv0.y),
                                      __float_as_uint(Bv0.z), __float_as_uint(Bv0.w)};
                    unsigned b1[4] = {__float_as_uint(Bv1.x), __float_as_uint(Bv1.y),
                                      __float_as_uint(Bv1.z), __float_as_uint(Bv1.w)};
#pragma unroll
                    for (int kk = 0; kk < 2; kk++) {
#pragma unroll
                        for (int mt = 0; mt < 2; mt++) {
                            unsigned afr[4] = {ax[2 * mt][2 * kk], ax[2 * mt + 1][2 * kk],
                                               ax[2 * mt][2 * kk + 1], ax[2 * mt + 1][2 * kk + 1]};
                            unsigned bfr0[2] = {b0[2 * kk], b0[2 * kk + 1]};
                            unsigned bfr1[2] = {b1[2 * kk], b1[2 * kk + 1]};
                            mma_tf32(acc[mt][2 * np], afr, bfr0);
                            mma_tf32(acc[mt][2 * np + 1], afr, bfr1);
                        }
                    }
                }
#pragma unroll
                for (int i = 0; i < 4; i++) { A0[i] = A1[i]; A1[i] = An[i]; }
            }
#undef AOFF
        }

        // stash partial gates to this k-quarter's buffer (32 rows per warp)
#pragma unroll
        for (int mt = 0; mt < 2; mt++) {
#pragma unroll
            for (int nt = 0; nt < 4; nt++) {
                int c = nt * 8 + 2 * lc;
                *(float2*)&GsW[(wm + mt * 16 + lr) * SM3_LDSG + c] =
                    make_float2(acc[mt][nt][0], acc[mt][nt][1]);
                *(float2*)&GsW[(wm + mt * 16 + 8 + lr) * SM3_LDSG + c] =
                    make_float2(acc[mt][nt][2], acc[mt][nt][3]);
            }
        }
        asm volatile("cp.async.wait_group 0;\n" ::: "memory");  // xp(t) resident
        __syncthreads();

        // ---- epilogue phase A: cell update + hperm write (critical path) ----
        float* hpw = g_hperm[t & 1];
        float hv_s[2];
        int b_s[2], j_s[2];
#pragma unroll
        for (int i = 0; i < 2; i++) {
            int u = tid + (i << 9);
            int b = u >> 3;
            int jl = u & 7;
            float4 x4 = *(const float4*)&Xs[b * SM3_LDSX + (jl << 2)];
            float4 p0 = *(const float4*)&Gs[b * SM3_LDSG + (jl << 2)];
            float4 p1 = *(const float4*)&Gs[SM3_GS_STRIDE + b * SM3_LDSG + (jl << 2)];
            float4 p2 = *(const float4*)&Gs[2 * SM3_GS_STRIDE + b * SM3_LDSG + (jl << 2)];
            float4 p3 = *(const float4*)&Gs[3 * SM3_GS_STRIDE + b * SM3_LDSG + (jl << 2)];
            float gi = (p0.x + p1.x) + (p2.x + p3.x) + x4.x;
            float gf = (p0.y + p1.y) + (p2.y + p3.y) + x4.y;
            float gg = (p0.z + p1.z) + (p2.z + p3.z) + x4.z;
            float go = (p0.w + p1.w) + (p2.w + p3.w) + x4.w;
            float iv = fsigmoid(gi);
            float fv = fsigmoid(gf);
            float gv = ftanh(gg);
            float ov = fsigmoid(go);
            float cv = fv * creg[i] + iv * gv;
            creg[i] = cv;
            float hv = ov * ftanh(cv);
            int j = (n0 >> 2) + jl;
            int kc = (j & ~31) + qperm(j & 31);
            hpw[b * Hh + kc] = __uint_as_float(f2tf(hv));
            hv_s[i] = hv; b_s[i] = b; j_s[i] = j;
        }

        // ---- arrive: one release-atomic on this CTA's quarter counter ----
        // (the __syncthreads also orders all xp(t) reads before the
        //  xp(t+1) prefetch below reuses the single Xs buffer)
        if (t < Tt - 1) {
            __syncthreads();           // all hperm writes issued, xp reads done
            if (tid == 0) {
                asm volatile("red.release.gpu.global.add.u32 [%0], %1;"
                             :: "l"(&g_syncq[bid >> 5]), "r"(1u) : "memory");
            }

            // xp(t+1) prefetch: maximize cp.async lead time
            const float* xpn = g_xp + (size_t)(t + 1) * Bb * G4;
            unsigned xb = smem_u32 + SM3_XS_OFF * 4;
#pragma unroll
            for (int i = 0; i < 2; i++) {
                int u = tid + (i << 9);
                int b = u >> 3, q = u & 7;
                cpa16(xb + (unsigned)(b * SM3_LDSX + q * 4) * 4,
                      xpn + (size_t)b * G4 + n0 + q * 4);
            }
            asm volatile("cp.async.commit_group;\n" ::: "memory");
        }

        // ---- phase B: non-critical writes (streaming stores, overlap) ----
#pragma unroll
        for (int i = 0; i < 2; i++) {
            int b = b_s[i], j = j_s[i];
            float hv = hv_s[i];
            size_t hi = (size_t)t * Bb * Hh + b * Hh + j;
            if (L == 1) {
                __stcs(&g_h1[hi], hv);                           // residual source
                int kc = (j & ~31) + qperm(j & 31);
                __stcs(&g_aperm2[(size_t)(t * Bb + b) * Ii + kc],
                       __uint_as_float(f2tf(hv)));               // layer-2 GEMM A
            } else {
                float o11 = hv + g_h1[hi];
                __stcs(&dout[(size_t)TB * Hh + hi], o11);                            // out11
                __stcs(&dout[(size_t)2 * TB * Hh + ((size_t)(t * Bb + b)) * 2 * Hh + j],
                       o11);                                                          // out14[:,:H]
            }
        }
        // no tail barrier: next iteration's per-warp quarter-wait gates the GEMM
    }
}

// -------------------- launch --------------------
extern "C" void kernel_launch(void* const* d_in, const int* in_sizes, int n_in,
                              void* d_out, int out_size) {
    const float* input4 = (const float*)d_in[0];
    const float* input0 = (const float*)d_in[1];
    const float* w_ih6  = (const float*)d_in[2];
    const float* w_hh6  = (const float*)d_in[3];
    const float* b_ih6  = (const float*)d_in[4];
    const float* b_hh6  = (const float*)d_in[5];
    const float* w_ih10 = (const float*)d_in[6];
    const float* w_hh10 = (const float*)d_in[7];
    const float* b_ih10 = (const float*)d_in[8];
    const float* b_hh10 = (const float*)d_in[9];
    float* out = (float*)d_out;

    cudaFuncSetAttribute(lstm_layer<1>, cudaFuncAttributeMaxDynamicSharedMemorySize,
                         SM3_FL * 4);
    cudaFuncSetAttribute(lstm_layer<2>, cudaFuncAttributeMaxDynamicSharedMemorySize,
                         SM3_FL * 4);
    cudaFuncSetAttribute(gemm_xp<1>, cudaFuncAttributeMaxDynamicSharedMemorySize,
                         GEMM_SMEM_FL * 4);
    cudaFuncSetAttribute(gemm_xp<2>, cudaFuncAttributeMaxDynamicSharedMemorySize,
                         GEMM_SMEM_FL * 4);

    dim3 gx(G4 / 128, TB / 128);  // n-tile fastest -> A reuse in L2
    const int PW_GRID = (G4 * (Ii + Hh + 1)) / 256;  // 49168

    // launch order arranged so ncu's capture window lands on lstm_layer<1> (idx 3)
    permute_l<1><<<PW_GRID, 256>>>(w_ih6, w_hh6, b_ih6, b_hh6);      // 0
    prepA<<<(TB * Ii) / 256, 256>>>(input0, input4);                  // 1 (+ctr reset)
    gemm_xp<1><<<gx, 256, GEMM_SMEM_FL * 4>>>();                      // 2
    lstm_layer<1><<<NBLK, 512, SM3_FL * 4>>>(out);                    // 3 <- profile me
    permute_l<2><<<PW_GRID, 256>>>(w_ih10, w_hh10, b_ih10, b_hh10);   // 4 (+ctr reset)
    gemm_xp<2><<<gx, 256, GEMM_SMEM_FL * 4>>>();                      // 5
    lstm_layer<2><<<NBLK, 512, SM3_FL * 4>>>(out);                    // 6
    copy_out1<<<(TB * Hh / 4) / 256, 256>>>(input4, out);             // 7
}

// round 15
// speedup vs baseline: 1.2534x; 1.0145x over previous
#include <cuda_runtime.h>
#include <cstdint>

// ---------------------------------------------------------------------------
// Stage3 LSTM stack: out1 = input4
//                    out7 = LSTM1(concat(input0, input4))
//                    out11 = LSTM2(concat(out7, input4)) + out7
//                    out14 = concat(out11, input4)
// Outputs concatenated: [out1 (T*B*H)] [out11 (T*B*H)] [out14 (T*B*2H)]
// ---------------------------------------------------------------------------

#define Tt 128
#define Bb 128
#define Hh 1024
#define Ii 2048
#define G4 4096            // 4*H
#define TB 16384           // T*B
#define LDSW 36            // smem row stride in floats (32 + 4 pad)
#define NBLK 128           // persistent blocks (1 per SM)

// -------------------- device scratch (no allocs allowed) --------------------
__device__ float g_wih1[G4 * Ii];   // gate-interleaved rows + k-qperm cols, tf32
__device__ float g_whh1[G4 * Hh];   // gate-interleaved rows, natural cols, tf32
__device__ float g_b1[G4];
__device__ float g_wih2[G4 * Ii];
__device__ float g_whh2[G4 * Hh];
__device__ float g_b2[G4];
__device__ float g_aperm1[(size_t)TB * Ii];  // layer-1 A: [input0|input4], permuted+tf32
__device__ float g_aperm2[(size_t)TB * Ii];  // layer-2 A: [h1|input4], permuted+tf32
__device__ float g_xp[(size_t)TB * G4];      // input projection for current layer
__device__ float g_h1[(size_t)TB * Hh];      // layer-1 h (natural layout, = out7)
__device__ float g_hperm[2][Bb * Hh];        // ping-pong h, col-permuted + tf32
__device__ unsigned g_syncq[4];              // per-k-quarter arrival counters

// -------------------- helpers --------------------
static __device__ __forceinline__ unsigned f2tf(float x) {
    unsigned u;
    asm("cvt.rna.tf32.f32 %0, %1;" : "=r"(u) : "f"(x));
    return u;
}

static __device__ __forceinline__ void mma_tf32(float c[4], const unsigned a[4],
                                                const unsigned b[2]) {
    asm volatile(
        "mma.sync.aligned.m16n8k8.row.col.f32.tf32.tf32.f32 "
        "{%0,%1,%2,%3}, {%4,%5,%6,%7}, {%8,%9}, {%0,%1,%2,%3};\n"
        : "+f"(c[0]), "+f"(c[1]), "+f"(c[2]), "+f"(c[3])
        : "r"(a[0]), "r"(a[1]), "r"(a[2]), "r"(a[3]), "r"(b[0]), "r"(b[1]));
}

// column permutation within a 32-wide K chunk: stored(kl) = (kl%4)*8 + kl/4
static __device__ __forceinline__ int qperm(int kl) {
    return ((kl & 3) << 3) + (kl >> 2);
}

static __device__ __forceinline__ void cpa16(unsigned dst, const float* src) {
    asm volatile("cp.async.cg.shared.global [%0], [%1], 16;\n" :: "r"(dst), "l"(src));
}

// HW tanh (sm_75+ MUFU.TANH): 1 MUFU per activation
static __device__ __forceinline__ float htanh(float x) {
    float y;
    asm("tanh.approx.f32 %0, %1;" : "=f"(y) : "f"(x));
    return y;
}
static __device__ __forceinline__ float fsigmoid(float x) {
    return fmaf(htanh(0.5f * x), 0.5f, 0.5f);   // 1 MUFU + 1 FMA
}
static __device__ __forceinline__ float ftanh(float x) { return htanh(x); }

// -------------------- fused per-layer weight/bias permutation ----------------
template <int L>
__global__ void permute_l(const float* __restrict__ wih, const float* __restrict__ whh,
                          const float* __restrict__ bih, const float* __restrict__ bhh) {
    int idx = blockIdx.x * 256 + threadIdx.x;
    float* wo = (L == 1) ? g_wih1 : g_wih2;
    float* ho = (L == 1) ? g_whh1 : g_whh2;
    float* bo = (L == 1) ? g_b1 : g_b2;
    if (idx < G4 * Ii) {
        int n = idx >> 11, k = idx & 2047;
        int j = n >> 2, g = n & 3;
        float v = wih[((g * Hh + j) << 11) + k];
        int kp = (k & ~31) | qperm(k & 31);
        wo[(n << 11) | kp] = __uint_as_float(f2tf(v));
    } else if (idx < G4 * Ii + G4 * Hh) {
        int i2 = idx - G4 * Ii;
        int n = i2 >> 10, k = i2 & 1023;
        int j = n >> 2, g = n & 3;
        ho[(n << 10) + k] = __uint_as_float(f2tf(whh[((g * Hh + j) << 10) + k]));
    } else {
        int n = idx - G4 * Ii - G4 * Hh;
        int j = n >> 2, g = n & 3;
        bo[n] = bih[g * Hh + j] + bhh[g * Hh + j];
        if (L == 2 && n < 4) g_syncq[n] = 0;   // reset counters for layer-2 pass
    }
}

// -------------------- A prepass: permuted + tf32-rounded ---------------------
__global__ void prepA(const float* __restrict__ in0, const float* __restrict__ in4) {
    int idx = blockIdx.x * 256 + threadIdx.x;
    if (idx < 4) g_syncq[idx] = 0;  // reset counters for layer-1 pass
    int row = idx >> 11;
    int k = idx & 2047;
    int kp = (k & ~31) | qperm(k & 31);
    float v = (k < 1024) ? in0[(size_t)row * Hh + k]
                         : in4[(size_t)row * Hh + (k - 1024)];
    float tv = __uint_as_float(f2tf(v));
    g_aperm1[(size_t)row * Ii + kp] = tv;
    if (k >= 1024) g_aperm2[(size_t)row * Ii + kp] = tv;
}

// -------------------- out1 + out14 second-half copy --------------------
__global__ void copy_out1(const float* __restrict__ in4, float* __restrict__ out) {
    size_t i4 = (size_t)blockIdx.x * 256 + threadIdx.x;
    size_t e = i4 * 4;
    float4 v = *(const float4*)(in4 + e);
    *(float4*)(out + e) = v;                       // out1
    size_t tb = e >> 10;
    size_t j = e & (Hh - 1);
    *(float4*)(out + (size_t)2 * TB * Hh + tb * 2 * Hh + Hh + j) = v;  // out14[:,H:]
}

// -------------------- big GEMM: xp = Aperm @ W'^T + bias' -------------------
// 3-stage cp.async pipeline, ONE __syncthreads per k-iteration.
#define GXS 4608                       // floats per stage per operand (128*LDSW)
#define GEMM_SMEM_FL (6 * GXS)         // 3 stages x (A,B) = 110592 bytes

template <int L>
__global__ void __launch_bounds__(256, 2)
gemm_xp() {
    const float* Ag = (L == 1) ? g_aperm1 : g_aperm2;
    const float* Wg = (L == 1) ? g_wih1 : g_wih2;
    const float* bias = (L == 1) ? g_b1 : g_b2;

    extern __shared__ float smem[];
    const unsigned smem_u32 = (unsigned)__cvta_generic_to_shared(smem);

    const int tid = threadIdx.x;
    const int lane = tid & 31;
    const int warp = tid >> 5;
    const int wm = (warp >> 1) << 5;   // 0,32,64,96
    const int wn = (warp & 1) << 6;    // 0,64
    const int lr = lane >> 2, lc = lane & 3;
    const int m0 = blockIdx.y * 128;
    const int n0 = blockIdx.x * 128;
    const int frow = tid >> 3, fqc = (tid & 7) << 2;

    float acc[2][8][4];
#pragma unroll
    for (int i = 0; i < 2; i++)
#pragma unroll
        for (int j = 0; j < 8; j++)
#pragma unroll
            for (int k = 0; k < 4; k++) acc[i][j][k] = 0.f;

    const float* Abase = Ag + (size_t)(m0 + frow) * Ii + fqc;
    const float* Bbase = Wg + (size_t)(n0 + frow) * Ii + fqc;
    const unsigned doff = (unsigned)(frow * LDSW + fqc) * 4;

#pragma unroll
    for (int pc = 0; pc < 2; pc++) {
        unsigned sa = smem_u32 + (pc * 2 * GXS) * 4 + doff;
        unsigned sb = smem_u32 + (pc * 2 * GXS + GXS) * 4 + doff;
#pragma unroll
        for (int i = 0; i < 4; i++) {
            cpa16(sa + (unsigned)(i * 32 * LDSW) * 4, Abase + (size_t)(i * 32) * Ii + pc * 32);
            cpa16(sb + (unsigned)(i * 32 * LDSW) * 4, Bbase + (size_t)(i * 32) * Ii + pc * 32);
        }
        asm volatile("cp.async.commit_group;\n" ::: "memory");
    }

    for (int kc = 0; kc < 64; kc++) {
        if (kc < 62) {
            asm volatile("cp.async.wait_group 1;\n" ::: "memory");
        } else {
            asm volatile("cp.async.wait_group 0;\n" ::: "memory");
        }
        __syncthreads();   // also separates compute(kc-1) reads from cp below

        if (kc < 62) {
            int nc = kc + 2;
            int st = nc % 3;
            unsigned sa = smem_u32 + (st * 2 * GXS) * 4 + doff;
            unsigned sb = smem_u32 + (st * 2 * GXS + GXS) * 4 + doff;
#pragma unroll
            for (int i = 0; i < 4; i++) {
                cpa16(sa + (unsigned)(i * 32 * LDSW) * 4, Abase + (size_t)(i * 32) * Ii + nc * 32);
                cpa16(sb + (unsigned)(i * 32 * LDSW) * 4, Bbase + (size_t)(i * 32) * Ii + nc * 32);
            }
            asm volatile("cp.async.commit_group;\n" ::: "memory");
        }

        const float* Ast = smem + (kc % 3) * 2 * GXS;
        const float* Bst = Ast + GXS;

        unsigned a[4][8];
#pragma unroll
        for (int i = 0; i < 4; i++) {
            int r = wm + ((i >> 1) << 4) + ((i & 1) << 3) + lr;
            const float4* p = (const float4*)&Ast[r * LDSW + lc * 8];
            float4 v0 = p[0], v1 = p[1];
            a[i][0] = __float_as_uint(v0.x); a[i][1] = __float_as_uint(v0.y);
            a[i][2] = __float_as_uint(v0.z); a[i][3] = __float_as_uint(v0.w);
            a[i][4] = __float_as_uint(v1.x); a[i][5] = __float_as_uint(v1.y);
            a[i][6] = __float_as_uint(v1.z); a[i][7] = __float_as_uint(v1.w);
        }

#pragma unroll
        for (int nt2 = 0; nt2 < 4; nt2++) {
            unsigned b0[8], b1[8];
            {
                int rb = wn + (2 * nt2) * 8 + lr;
                const float4* p = (const float4*)&Bst[rb * LDSW + lc * 8];
                float4 v0 = p[0], v1 = p[1];
                b0[0] = __float_as_uint(v0.x); b0[1] = __float_as_uint(v0.y);
                b0[2] = __float_as_uint(v0.z); b0[3] = __float_as_uint(v0.w);
                b0[4] = __float_as_uint(v1.x); b0[5] = __float_as_uint(v1.y);
                b0[6] = __float_as_uint(v1.z); b0[7] = __float_as_uint(v1.w);
            }
            {
                int rb = wn + (2 * nt2 + 1) * 8 + lr;
                const float4* p = (const float4*)&Bst[rb * LDSW + lc * 8];
                float4 v0 = p[0], v1 = p[1];
                b1[0] = __float_as_uint(v0.x); b1[1] = __float_as_uint(v0.y);
                b1[2] = __float_as_uint(v0.z); b1[3] = __float_as_uint(v0.w);
                b1[4] = __float_as_uint(v1.x); b1[5] = __float_as_uint(v1.y);
                b1[6] = __float_as_uint(v1.z); b1[7] = __float_as_uint(v1.w);
            }
#pragma unroll
            for (int kk = 0; kk < 4; kk++) {
                unsigned afr0[4] = {a[0][2 * kk], a[1][2 * kk],
                                    a[0][2 * kk + 1], a[1][2 * kk + 1]};
                unsigned afr1[4] = {a[2][2 * kk], a[3][2 * kk],
                                    a[2][2 * kk + 1], a[3][2 * kk + 1]};
                unsigned bfr0[2] = {b0[2 * kk], b0[2 * kk + 1]};
                unsigned bfr1[2] = {b1[2 * kk], b1[2 * kk + 1]};
                mma_tf32(acc[0][2 * nt2], afr0, bfr0);
                mma_tf32(acc[0][2 * nt2 + 1], afr0, bfr1);
                mma_tf32(acc[1][2 * nt2], afr1, bfr0);
                mma_tf32(acc[1][2 * nt2 + 1], afr1, bfr1);
            }
        }
    }

#pragma unroll
    for (int mt = 0; mt < 2; mt++) {
        int r = m0 + wm + mt * 16 + lr;
#pragma unroll
        for (int nt = 0; nt < 8; nt++) {
            int c = n0 + wn + nt * 8 + 2 * lc;
            float2 bv = *(const float2*)&bias[c];
            float2 v0 = make_float2(acc[mt][nt][0] + bv.x, acc[mt][nt][1] + bv.y);
            float2 v1 = make_float2(acc[mt][nt][2] + bv.x, acc[mt][nt][3] + bv.y);
            *(float2*)&g_xp[(size_t)r * G4 + c] = v0;
            *(float2*)&g_xp[(size_t)(r + 8) * G4 + c] = v1;
        }
    }
}

// -------------------- persistent recurrent layer --------------------
// 128 CTAs x 512 threads (16 warps). CTA owns 32 gate-cols (8 hidden units).
// 4-way k-split: warp = 32 batch rows x 32 gate cols x 256 k.
// Hierarchical sync: per-quarter release-atomic arrive + per-warp acquire
// poll. HW-tanh epilogue: 5 MUFU/element (was 10) — epilogue was the
// MUFU-throughput-bound critical-path term (~11.5us/step).
#define SM3_WS_LD 1028                  // 1028 % 32 == 4 -> conflict-free frags
#define SM3_WS_SZ (32 * SM3_WS_LD)      // 32896 floats
#define SM3_LDSG 36                     // Gs row stride (144 B, 16B-aligned)
#define SM3_GS_STRIDE (128 * SM3_LDSG)  // 4608 floats per Gs buffer
#define SM3_LDSX 32                     // xp row stride (128 B, 16B-aligned)
#define SM3_XS_OFF (SM3_WS_SZ + 4 * SM3_GS_STRIDE)      // 51328
#define SM3_FL (SM3_XS_OFF + 128 * SM3_LDSX)            // 55424 fl = 221696 B

template <int L>
__global__ void __launch_bounds__(512, 1)
lstm_layer(float* __restrict__ dout) {
    extern __shared__ float smem[];
    float* Ws = smem;
    float* Gs = smem + SM3_WS_SZ;
    float* Xs = smem + SM3_XS_OFF;
    const unsigned smem_u32 = (unsigned)__cvta_generic_to_shared(smem);

    const int tid = threadIdx.x;
    const int bid = blockIdx.x;
    const int lane = tid & 31;
    const int warp = tid >> 5;         // 0..15
    const int mq = warp >> 2;          // m-group 0..3 (32 batch rows each)
    const int kq = warp & 3;           // k-quarter 0..3 (256 k each)
    const int wm = mq << 5;            // batch row base
    const int kb = kq << 8;            // k base
    const int lr = lane >> 2, lc = lane & 3;
    const int n0 = bid * 32;           // gate-col base
    float* GsW = Gs + kq * SM3_GS_STRIDE;

    const float* Wg = (L == 1) ? g_whh1 : g_whh2;

    // load W slice into smem with per-chunk column permutation
    for (int idx = tid; idx < 32 * 1024; idx += 512) {
        int n = idx >> 10;
        int k = idx & 1023;
        int kc = (k & ~31) + qperm(k & 31);
        Ws[n * SM3_WS_LD + kc] = Wg[(size_t)(n0 + n) * Hh + k];
    }
    // prefetch xp tile for t=0
    {
        unsigned xb = smem_u32 + SM3_XS_OFF * 4;
#pragma unroll
        for (int i = 0; i < 2; i++) {
            int u = tid + (i << 9);
            int b = u >> 3, q = u & 7;
            cpa16(xb + (unsigned)(b * SM3_LDSX + q * 4) * 4,
                  g_xp + (size_t)b * G4 + n0 + q * 4);
        }
        asm volatile("cp.async.commit_group;\n" ::: "memory");
    }
    __syncthreads();

    float creg[2];
    creg[0] = 0.f; creg[1] = 0.f;

    for (int t = 0; t < Tt; t++) {
        float acc[2][4][4];
#pragma unroll
        for (int i = 0; i < 2; i++)
#pragma unroll
            for (int j = 0; j < 4; j++)
#pragma unroll
                for (int k = 0; k < 4; k++) acc[i][j][k] = 0.f;

        if (t > 0) {
            // ---- per-warp acquire-wait on this k-quarter's 32 producers ----
            if (lane == 0) {
                const unsigned* cp = &g_syncq[kq];
                unsigned v;
                for (;;) {
                    asm volatile("ld.acquire.gpu.global.u32 %0, [%1];"
                                 : "=r"(v) : "l"(cp) : "memory");
                    if (v >= (unsigned)(32 * t)) break;
                    __nanosleep(32);
                }
            }
            __syncwarp();

            const float* hp = g_hperm[(t - 1) & 1];
            const float* rp0 = hp + (size_t)(wm + lr) * Hh + kb + lc * 8;
            const float* rp1 = hp + (size_t)(wm + 8 + lr) * Hh + kb + lc * 8;
            const float* rp2 = hp + (size_t)(wm + 16 + lr) * Hh + kb + lc * 8;
            const float* rp3 = hp + (size_t)(wm + 24 + lr) * Hh + kb + lc * 8;
#define AOFF(c) (((c) >> 1) * 32 + ((c) & 1) * 4)
            float4 A0[4], A1[4];
            A0[0] = __ldcg((const float4*)(rp0 + AOFF(0)));
            A0[1] = __ldcg((const float4*)(rp1 + AOFF(0)));
            A0[2] = __ldcg((const float4*)(rp2 + AOFF(0)));
            A0[3] = __ldcg((const float4*)(rp3 + AOFF(0)));
            A1[0] = __ldcg((const float4*)(rp0 + AOFF(1)));
            A1[1] = __ldcg((const float4*)(rp1 + AOFF(1)));
            A1[2] = __ldcg((const float4*)(rp2 + AOFF(1)));
            A1[3] = __ldcg((const float4*)(rp3 + AOFF(1)));

#pragma unroll
            for (int c = 0; c < 16; c++) {
                float4 An[4];
                if (c < 14) {
                    int o = AOFF(c + 2);
                    An[0] = __ldcg((const float4*)(rp0 + o));
                    An[1] = __ldcg((const float4*)(rp1 + o));
                    An[2] = __ldcg((const float4*)(rp2 + o));
                    An[3] = __ldcg((const float4*)(rp3 + o));
                }
                unsigned ax[4][4];
#pragma unroll
                for (int i = 0; i < 4; i++) {
                    ax[i][0] = __float_as_uint(A0[i].x);
                    ax[i][1] = __float_as_uint(A0[i].y);
                    ax[i][2] = __float_as_uint(A0[i].z);
                    ax[i][3] = __float_as_uint(A0[i].w);
                }
#pragma unroll
                for (int np = 0; np < 2; np++) {
                    const int boff = kb + AOFF(c) + lc * 8;
                    float4 Bv0 = *(const float4*)
                        &Ws[((2 * np) * 8 + lr) * SM3_WS_LD + boff];
                    float4 Bv1 = *(const float4*)
                        &Ws[((2 * np + 1) * 8 + lr) * SM3_WS_LD + boff];
                    unsigned b0[4] = {__float_as_uint(Bv0.x), __float_as_uint(Bv0.y),
                                      __float_as_uint(Bv0.z), __float_as_uint(Bv0.w)};
                    unsigned b1[4] = {__float_as_uint(Bv1.x), __float_as_uint(Bv1.y),
                                      __float_as_uint(Bv1.z), __float_as_uint(Bv1.w)};
#pragma unroll
                    for (int kk = 0; kk < 2; kk++) {
#pragma unroll
                        for (int mt = 0; mt < 2; mt++) {
                            unsigned afr[4] = {ax[2 * mt][2 * kk], ax[2 * mt + 1][2 * kk],
                                               ax[2 * mt][2 * kk + 1], ax[2 * mt + 1][2 * kk + 1]};
                            unsigned bfr0[2] = {b0[2 * kk], b0[2 * kk + 1]};
                            unsigned bfr1[2] = {b1[2 * kk], b1[2 * kk + 1]};
                            mma_tf32(acc[mt][2 * np], afr, bfr0);
                            mma_tf32(acc[mt][2 * np + 1], afr, bfr1);
                        }
                    }
                }
#pragma unroll
                for (int i = 0; i < 4; i++) { A0[i] = A1[i]; A1[i] = An[i]; }
            }
#undef AOFF
        }

        // stash partial gates to this k-quarter's buffer (32 rows per warp)
#pragma unroll
        for (int mt = 0; mt < 2; mt++) {
#pragma unroll
            for (int nt = 0; nt < 4; nt++) {
                int c = nt * 8 + 2 * lc;
                *(float2*)&GsW[(wm + mt * 16 + lr) * SM3_LDSG + c] =
                    make_float2(acc[mt][nt][0], acc[mt][nt][1]);
                *(float2*)&GsW[(wm + mt * 16 + 8 + lr) * SM3_LDSG + c] =
                    make_float2(acc[mt][nt][2], acc[mt][nt][3]);
            }
        }
        asm volatile("cp.async.wait_group 0;\n" ::: "memory");  // xp(t) resident
        __syncthreads();

        // ---- epilogue phase A: cell update + hperm write (critical path) ----
        float* hpw = g_hperm[t & 1];
        float hv_s[2];
        int b_s[2], j_s[2];
#pragma unroll
        for (int i = 0; i < 2; i++) {
            int u = tid + (i << 9);
            int b = u >> 3;
            int jl = u & 7;
            float4 x4 = *(const float4*)&Xs[b * SM3_LDSX + (jl << 2)];
            float4 p0 = *(const float4*)&Gs[b * SM3_LDSG + (jl << 2)];
            float4 p1 = *(const float4*)&Gs[SM3_GS_STRIDE + b * SM3_LDSG + (jl << 2)];
            float4 p2 = *(const float4*)&Gs[2 * SM3_GS_STRIDE + b * SM3_LDSG + (jl << 2)];
            float4 p3 = *(const float4*)&Gs[3 * SM3_GS_STRIDE + b * SM3_LDSG + (jl << 2)];
            float gi = (p0.x + p1.x) + (p2.x + p3.x) + x4.x;
            float gf = (p0.y + p1.y) + (p2.y + p3.y) + x4.y;
            float gg = (p0.z + p1.z) + (p2.z + p3.z) + x4.z;
            float go = (p0.w + p1.w) + (p2.w + p3.w) + x4.w;
            float iv = fsigmoid(gi);
            float fv = fsigmoid(gf);
            float gv = ftanh(gg);
            float ov = fsigmoid(go);
            float cv = fv * creg[i] + iv * gv;
            creg[i] = cv;
            float hv = ov * ftanh(cv);
            int j = (n0 >> 2) + jl;
            int kc = (j & ~31) + qperm(j & 31);
            hpw[b * Hh + kc] = __uint_as_float(f2tf(hv));
            hv_s[i] = hv; b_s[i] = b; j_s[i] = j;
        }

        // ---- arrive: one release-atomic on this CTA's quarter counter ----
        // (the __syncthreads also orders all xp(t) reads before the
        //  xp(t+1) prefetch below reuses the single Xs buffer)
        if (t < Tt - 1) {
            __syncthreads();           // all hperm writes issued, xp reads done
            if (tid == 0) {
                asm volatile("red.release.gpu.global.add.u32 [%0], %1;"
                             :: "l"(&g_syncq[bid >> 5]), "r"(1u) : "memory");
            }

            // xp(t+1) prefetch: maximize cp.async lead time
            const float* xpn = g_xp + (size_t)(t + 1) * Bb * G4;
            unsigned xb = smem_u32 + SM3_XS_OFF * 4;
#pragma unroll
            for (int i = 0; i < 2; i++) {
                int u = tid + (i << 9);
                int b = u >> 3, q = u & 7;
                cpa16(xb + (unsigned)(b * SM3_LDSX + q * 4) * 4,
                      xpn + (size_t)b * G4 + n0 + q * 4);
            }
            asm volatile("cp.async.commit_group;\n" ::: "memory");
        }

        // ---- phase B: non-critical writes (streaming stores, overlap) ----
#pragma unroll
        for (int i = 0; i < 2; i++) {
            int b = b_s[i], j = j_s[i];
            float hv = hv_s[i];
            size_t hi = (size_t)t * Bb * Hh + b * Hh + j;
            if (L == 1) {
                __stcs(&g_h1[hi], hv);                           // residual source
                int kc = (j & ~31) + qperm(j & 31);
                __stcs(&g_aperm2[(size_t)(t * Bb + b) * Ii + kc],
                       __uint_as_float(f2tf(hv)));               // layer-2 GEMM A
            } else {
                float o11 = hv + g_h1[hi];
                __stcs(&dout[(size_t)TB * Hh + hi], o11);                            // out11
                __stcs(&dout[(size_t)2 * TB * Hh + ((size_t)(t * Bb + b)) * 2 * Hh + j],
                       o11);                                                          // out14[:,:H]
            }
        }
        // no tail barrier: next iteration's per-warp quarter-wait gates the GEMM
    }
}

// -------------------- launch --------------------
extern "C" void kernel_launch(void* const* d_in, const int* in_sizes, int n_in,
                              void* d_out, int out_size) {
    const float* input4 = (const float*)d_in[0];
    const float* input0 = (const float*)d_in[1];
    const float* w_ih6  = (const float*)d_in[2];
    const float* w_hh6  = (const float*)d_in[3];
    const float* b_ih6  = (const float*)d_in[4];
    const float* b_hh6  = (const float*)d_in[5];
    const float* w_ih10 = (const float*)d_in[6];
    const float* w_hh10 = (const float*)d_in[7];
    const float* b_ih10 = (const float*)d_in[8];
    const float* b_hh10 = (const float*)d_in[9];
    float* out = (float*)d_out;

    cudaFuncSetAttribute(lstm_layer<1>, cudaFuncAttributeMaxDynamicSharedMemorySize,
                         SM3_FL * 4);
    cudaFuncSetAttribute(lstm_layer<2>, cudaFuncAttributeMaxDynamicSharedMemorySize,
                         SM3_FL * 4);
    cudaFuncSetAttribute(gemm_xp<1>, cudaFuncAttributeMaxDynamicSharedMemorySize,
                         GEMM_SMEM_FL * 4);
    cudaFuncSetAttribute(gemm_xp<2>, cudaFuncAttributeMaxDynamicSharedMemorySize,
                         GEMM_SMEM_FL * 4);

    dim3 gx(G4 / 128, TB / 128);  // n-tile fastest -> A reuse in L2
    const int PW_GRID = (G4 * (Ii + Hh + 1)) / 256;  // 49168

    // launch order arranged so ncu's capture window lands on lstm_layer<1> (idx 3)
    permute_l<1><<<PW_GRID, 256>>>(w_ih6, w_hh6, b_ih6, b_hh6);      // 0
    prepA<<<(TB * Ii) / 256, 256>>>(input0, input4);                  // 1 (+ctr reset)
    gemm_xp<1><<<gx, 256, GEMM_SMEM_FL * 4>>>();                      // 2
    lstm_layer<1><<<NBLK, 512, SM3_FL * 4>>>(out);                    // 3 <- profile me
    permute_l<2><<<PW_GRID, 256>>>(w_ih10, w_hh10, b_ih10, b_hh10);   // 4 (+ctr reset)
    gemm_xp<2><<<gx, 256, GEMM_SMEM_FL * 4>>>();                      // 5
    lstm_layer<2><<<NBLK, 512, SM3_FL * 4>>>(out);                    // 6
    copy_out1<<<(TB * Hh / 4) / 256, 256>>>(input4, out);             // 7
}

// round 16
// speedup vs baseline: 1.4912x; 1.1897x over previous
#include <cuda_runtime.h>
#include <cuda_fp16.h>
#include <cstdint>

// ---------------------------------------------------------------------------
// Stage3 LSTM stack: out1 = input4
//                    out7 = LSTM1(concat(input0, input4))
//                    out11 = LSTM2(concat(out7, input4)) + out7
//                    out14 = concat(out11, input4)
// Outputs concatenated: [out1 (T*B*H)] [out11 (T*B*H)] [out14 (T*B*2H)]
// ---------------------------------------------------------------------------

#define Tt 128
#define Bb 128
#define Hh 1024
#define Ii 2048
#define G4 4096            // 4*H
#define TB 16384           // T*B
#define LDSW 36            // smem row stride in floats (32 + 4 pad)
#define NBLK 128           // persistent blocks (1 per SM)

// -------------------- device scratch (no allocs allowed) --------------------
__device__ float g_wih1[G4 * Ii];   // gate-interleaved rows + k-qperm cols, tf32
__device__ float g_whh1[G4 * Hh];   // gate-interleaved rows, natural cols, tf32
__device__ float g_b1[G4];
__device__ float g_wih2[G4 * Ii];
__device__ float g_whh2[G4 * Hh];
__device__ float g_b2[G4];
__device__ float g_aperm1[(size_t)TB * Ii];  // layer-1 A: [input0|input4], permuted+tf32
__device__ float g_aperm2[(size_t)TB * Ii];  // layer-2 A: [h1|input4], permuted+tf32
__device__ float g_xp[(size_t)TB * G4];      // input projection for current layer
__device__ float g_h1[(size_t)TB * Hh];      // layer-1 h (natural layout, = out7)
__device__ __align__(16) __half g_hperm[2][Bb * Hh];  // ping-pong h, fp16, f16-perm
__device__ unsigned g_syncq[4];              // per-k-quarter arrival counters

// -------------------- helpers --------------------
static __device__ __forceinline__ unsigned f2tf(float x) {
    unsigned u;
    asm("cvt.rna.tf32.f32 %0, %1;" : "=r"(u) : "f"(x));
    return u;
}

static __device__ __forceinline__ void mma_tf32(float c[4], const unsigned a[4],
                                                const unsigned b[2]) {
    asm volatile(
        "mma.sync.aligned.m16n8k8.row.col.f32.tf32.tf32.f32 "
        "{%0,%1,%2,%3}, {%4,%5,%6,%7}, {%8,%9}, {%0,%1,%2,%3};\n"
        : "+f"(c[0]), "+f"(c[1]), "+f"(c[2]), "+f"(c[3])
        : "r"(a[0]), "r"(a[1]), "r"(a[2]), "r"(a[3]), "r"(b[0]), "r"(b[1]));
}

// fp16 mma m16n8k16, fp32 accumulate
static __device__ __forceinline__ void mma_f16(float c[4], unsigned a0, unsigned a1,
                                               unsigned a2, unsigned a3,
                                               unsigned b0, unsigned b1) {
    asm volatile(
        "mma.sync.aligned.m16n8k16.row.col.f32.f16.f16.f32 "
        "{%0,%1,%2,%3}, {%4,%5,%6,%7}, {%8,%9}, {%0,%1,%2,%3};\n"
        : "+f"(c[0]), "+f"(c[1]), "+f"(c[2]), "+f"(c[3])
        : "r"(a0), "r"(a1), "r"(a2), "r"(a3), "r"(b0), "r"(b1));
}

// fp32-path column permutation within a 32-wide K chunk (big GEMM)
static __device__ __forceinline__ int qperm(int kl) {
    return ((kl & 3) << 3) + (kl >> 2);
}

// fp16-path permutation within a 32-wide K block: thread lc's 8 halves
// {2lc,2lc+1,2lc+8,2lc+9, +16 same} land contiguous -> one uint4 per load.
static __device__ __forceinline__ int hperm16(int k) {
    int c = (k >> 4) & 1, k4 = k & 15;
    int r = k4 & 1, cc = (k4 >> 1) & 3, s = (k4 >> 3) & 1;
    return (k & ~31) | (cc << 3) | (c << 2) | (s << 1) | r;
}

static __device__ __forceinline__ void cpa16(unsigned dst, const float* src) {
    asm volatile("cp.async.cg.shared.global [%0], [%1], 16;\n" :: "r"(dst), "l"(src));
}

// HW tanh (sm_75+ MUFU.TANH)
static __device__ __forceinline__ float htanh(float x) {
    float y;
    asm("tanh.approx.f32 %0, %1;" : "=f"(y) : "f"(x));
    return y;
}
static __device__ __forceinline__ float fsigmoid(float x) {
    return fmaf(htanh(0.5f * x), 0.5f, 0.5f);
}
static __device__ __forceinline__ float ftanh(float x) { return htanh(x); }

// -------------------- fused per-layer weight/bias permutation ----------------
template <int L>
__global__ void permute_l(const float* __restrict__ wih, const float* __restrict__ whh,
                          const float* __restrict__ bih, const float* __restrict__ bhh) {
    int idx = blockIdx.x * 256 + threadIdx.x;
    float* wo = (L == 1) ? g_wih1 : g_wih2;
    float* ho = (L == 1) ? g_whh1 : g_whh2;
    float* bo = (L == 1) ? g_b1 : g_b2;
    if (idx < G4 * Ii) {
        int n = idx >> 11, k = idx & 2047;
        int j = n >> 2, g = n & 3;
        float v = wih[((g * Hh + j) << 11) + k];
        int kp = (k & ~31) | qperm(k & 31);
        wo[(n << 11) | kp] = __uint_as_float(f2tf(v));
    } else if (idx < G4 * Ii + G4 * Hh) {
        int i2 = idx - G4 * Ii;
        int n = i2 >> 10, k = i2 & 1023;
        int j = n >> 2, g = n & 3;
        ho[(n << 10) + k] = __uint_as_float(f2tf(whh[((g * Hh + j) << 10) + k]));
    } else {
        int n = idx - G4 * Ii - G4 * Hh;
        int j = n >> 2, g = n & 3;
        bo[n] = bih[g * Hh + j] + bhh[g * Hh + j];
        if (L == 2 && n < 4) g_syncq[n] = 0;   // reset counters for layer-2 pass
    }
}

// -------------------- A prepass: permuted + tf32-rounded ---------------------
__global__ void prepA(const float* __restrict__ in0, const float* __restrict__ in4) {
    int idx = blockIdx.x * 256 + threadIdx.x;
    if (idx < 4) g_syncq[idx] = 0;  // reset counters for layer-1 pass
    int row = idx >> 11;
    int k = idx & 2047;
    int kp = (k & ~31) | qperm(k & 31);
    float v = (k < 1024) ? in0[(size_t)row * Hh + k]
                         : in4[(size_t)row * Hh + (k - 1024)];
    float tv = __uint_as_float(f2tf(v));
    g_aperm1[(size_t)row * Ii + kp] = tv;
    if (k >= 1024) g_aperm2[(size_t)row * Ii + kp] = tv;
}

// -------------------- out1 + out14 second-half copy --------------------
__global__ void copy_out1(const float* __restrict__ in4, float* __restrict__ out) {
    size_t i4 = (size_t)blockIdx.x * 256 + threadIdx.x;
    size_t e = i4 * 4;
    float4 v = *(const float4*)(in4 + e);
    *(float4*)(out + e) = v;                       // out1
    size_t tb = e >> 10;
    size_t j = e & (Hh - 1);
    *(float4*)(out + (size_t)2 * TB * Hh + tb * 2 * Hh + Hh + j) = v;  // out14[:,H:]
}

// -------------------- big GEMM: xp = Aperm @ W'^T + bias' -------------------
// 3-stage cp.async pipeline, ONE __syncthreads per k-iteration.
#define GXS 4608                       // floats per stage per operand (128*LDSW)
#define GEMM_SMEM_FL (6 * GXS)         // 3 stages x (A,B) = 110592 bytes

template <int L>
__global__ void __launch_bounds__(256, 2)
gemm_xp() {
    const float* Ag = (L == 1) ? g_aperm1 : g_aperm2;
    const float* Wg = (L == 1) ? g_wih1 : g_wih2;
    const float* bias = (L == 1) ? g_b1 : g_b2;

    extern __shared__ float smem[];
    const unsigned smem_u32 = (unsigned)__cvta_generic_to_shared(smem);

    const int tid = threadIdx.x;
    const int lane = tid & 31;
    const int warp = tid >> 5;
    const int wm = (warp >> 1) << 5;   // 0,32,64,96
    const int wn = (warp & 1) << 6;    // 0,64
    const int lr = lane >> 2, lc = lane & 3;
    const int m0 = blockIdx.y * 128;
    const int n0 = blockIdx.x * 128;
    const int frow = tid >> 3, fqc = (tid & 7) << 2;

    float acc[2][8][4];
#pragma unroll
    for (int i = 0; i < 2; i++)
#pragma unroll
        for (int j = 0; j < 8; j++)
#pragma unroll
            for (int k = 0; k < 4; k++) acc[i][j][k] = 0.f;

    const float* Abase = Ag + (size_t)(m0 + frow) * Ii + fqc;
    const float* Bbase = Wg + (size_t)(n0 + frow) * Ii + fqc;
    const unsigned doff = (unsigned)(frow * LDSW + fqc) * 4;

#pragma unroll
    for (int pc = 0; pc < 2; pc++) {
        unsigned sa = smem_u32 + (pc * 2 * GXS) * 4 + doff;
        unsigned sb = smem_u32 + (pc * 2 * GXS + GXS) * 4 + doff;
#pragma unroll
        for (int i = 0; i < 4; i++) {
            cpa16(sa + (unsigned)(i * 32 * LDSW) * 4, Abase + (size_t)(i * 32) * Ii + pc * 32);
            cpa16(sb + (unsigned)(i * 32 * LDSW) * 4, Bbase + (size_t)(i * 32) * Ii + pc * 32);
        }
        asm volatile("cp.async.commit_group;\n" ::: "memory");
    }

    for (int kc = 0; kc < 64; kc++) {
        if (kc < 62) {
            asm volatile("cp.async.wait_group 1;\n" ::: "memory");
        } else {
            asm volatile("cp.async.wait_group 0;\n" ::: "memory");
        }
        __syncthreads();   // also separates compute(kc-1) reads from cp below

        if (kc < 62) {
            int nc = kc + 2;
            int st = nc % 3;
            unsigned sa = smem_u32 + (st * 2 * GXS) * 4 + doff;
            unsigned sb = smem_u32 + (st * 2 * GXS + GXS) * 4 + doff;
#pragma unroll
            for (int i = 0; i < 4; i++) {
                cpa16(sa + (unsigned)(i * 32 * LDSW) * 4, Abase + (size_t)(i * 32) * Ii + nc * 32);
                cpa16(sb + (unsigned)(i * 32 * LDSW) * 4, Bbase + (size_t)(i * 32) * Ii + nc * 32);
            }
            asm volatile("cp.async.commit_group;\n" ::: "memory");
        }

        const float* Ast = smem + (kc % 3) * 2 * GXS;
        const float* Bst = Ast + GXS;

        unsigned a[4][8];
#pragma unroll
        for (int i = 0; i < 4; i++) {
            int r = wm + ((i >> 1) << 4) + ((i & 1) << 3) + lr;
            const float4* p = (const float4*)&Ast[r * LDSW + lc * 8];
            float4 v0 = p[0], v1 = p[1];
            a[i][0] = __float_as_uint(v0.x); a[i][1] = __float_as_uint(v0.y);
            a[i][2] = __float_as_uint(v0.z); a[i][3] = __float_as_uint(v0.w);
            a[i][4] = __float_as_uint(v1.x); a[i][5] = __float_as_uint(v1.y);
            a[i][6] = __float_as_uint(v1.z); a[i][7] = __float_as_uint(v1.w);
        }

#pragma unroll
        for (int nt2 = 0; nt2 < 4; nt2++) {
            unsigned b0[8], b1[8];
            {
                int rb = wn + (2 * nt2) * 8 + lr;
                const float4* p = (const float4*)&Bst[rb * LDSW + lc * 8];
                float4 v0 = p[0], v1 = p[1];
                b0[0] = __float_as_uint(v0.x); b0[1] = __float_as_uint(v0.y);
                b0[2] = __float_as_uint(v0.z); b0[3] = __float_as_uint(v0.w);
                b0[4] = __float_as_uint(v1.x); b0[5] = __float_as_uint(v1.y);
                b0[6] = __float_as_uint(v1.z); b0[7] = __float_as_uint(v1.w);
            }
            {
                int rb = wn + (2 * nt2 + 1) * 8 + lr;
                const float4* p = (const float4*)&Bst[rb * LDSW + lc * 8];
                float4 v0 = p[0], v1 = p[1];
                b1[0] = __float_as_uint(v0.x); b1[1] = __float_as_uint(v0.y);
                b1[2] = __float_as_uint(v0.z); b1[3] = __float_as_uint(v0.w);
                b1[4] = __float_as_uint(v1.x); b1[5] = __float_as_uint(v1.y);
                b1[6] = __float_as_uint(v1.z); b1[7] = __float_as_uint(v1.w);
            }
#pragma unroll
            for (int kk = 0; kk < 4; kk++) {
                unsigned afr0[4] = {a[0][2 * kk], a[1][2 * kk],
                                    a[0][2 * kk + 1], a[1][2 * kk + 1]};
                unsigned afr1[4] = {a[2][2 * kk], a[3][2 * kk],
                                    a[2][2 * kk + 1], a[3][2 * kk + 1]};
                unsigned bfr0[2] = {b0[2 * kk], b0[2 * kk + 1]};
                unsigned bfr1[2] = {b1[2 * kk], b1[2 * kk + 1]};
                mma_tf32(acc[0][2 * nt2], afr0, bfr0);
                mma_tf32(acc[0][2 * nt2 + 1], afr0, bfr1);
                mma_tf32(acc[1][2 * nt2], afr1, bfr0);
                mma_tf32(acc[1][2 * nt2 + 1], afr1, bfr1);
            }
        }
    }

#pragma unroll
    for (int mt = 0; mt < 2; mt++) {
        int r = m0 + wm + mt * 16 + lr;
#pragma unroll
        for (int nt = 0; nt < 8; nt++) {
            int c = n0 + wn + nt * 8 + 2 * lc;
            float2 bv = *(const float2*)&bias[c];
            float2 v0 = make_float2(acc[mt][nt][0] + bv.x, acc[mt][nt][1] + bv.y);
            float2 v1 = make_float2(acc[mt][nt][2] + bv.x, acc[mt][nt][3] + bv.y);
            *(float2*)&g_xp[(size_t)r * G4 + c] = v0;
            *(float2*)&g_xp[(size_t)(r + 8) * G4 + c] = v1;
        }
    }
}

// -------------------- persistent recurrent layer (fp16 operands) -----------
// 128 CTAs x 512 threads (16 warps). CTA owns 32 gate-cols (8 hidden units).
// 4-way k-split: warp = 32 batch rows x 32 gate cols x 256 k.
// fp16 h + fp16 W_hh, fp32 accumulate via mma.m16n8k16 (same 10-bit mantissa
// as tf32; h in (-1,1), W small -> no range issues). Halves L2 broadcast,
// smem traffic, and mma count. 32-k blocks: one uint4 per row per block.
#define SM4_WS_LDH 1056                 // Ws row stride halves (2112B, %128B==64)
#define SM4_WS_B   (32 * SM4_WS_LDH * 2)        // 67584 bytes
#define SM4_LDSG 36                     // Gs row stride (floats)
#define SM4_GS_STRIDE (128 * SM4_LDSG)  // 4608 floats per Gs buffer
#define SM4_GS_OFF_B SM4_WS_B                   // 67584 (16B-aligned)
#define SM4_LDSX 32                     // xp row stride (floats)
#define SM4_XS_OFF_B (SM4_GS_OFF_B + 4 * SM4_GS_STRIDE * 4)   // 141312
#define SM4_TOTAL_B (SM4_XS_OFF_B + 128 * SM4_LDSX * 4)       // 157696 bytes

template <int L>
__global__ void __launch_bounds__(512, 1)
lstm_layer(float* __restrict__ dout) {
    extern __shared__ char smraw[];
    __half* Ws = (__half*)smraw;
    float* Gs = (float*)(smraw + SM4_GS_OFF_B);
    float* Xs = (float*)(smraw + SM4_XS_OFF_B);
    const unsigned smem_u32 = (unsigned)__cvta_generic_to_shared(smraw);

    const int tid = threadIdx.x;
    const int bid = blockIdx.x;
    const int lane = tid & 31;
    const int warp = tid >> 5;         // 0..15
    const int mq = warp >> 2;          // m-group 0..3 (32 batch rows each)
    const int kq = warp & 3;           // k-quarter 0..3 (256 k each)
    const int wm = mq << 5;            // batch row base
    const int kb = kq << 8;            // k base
    const int lr = lane >> 2, lc = lane & 3;
    const int n0 = bid * 32;           // gate-col base
    float* GsW = Gs + kq * SM4_GS_STRIDE;

    const float* Wg = (L == 1) ? g_whh1 : g_whh2;

    // load W slice into smem as fp16 with the f16 block permutation
    for (int idx = tid; idx < 32 * 1024; idx += 512) {
        int n = idx >> 10;
        int k = idx & 1023;
        Ws[n * SM4_WS_LDH + hperm16(k)] =
            __float2half_rn(Wg[(size_t)(n0 + n) * Hh + k]);
    }
    // prefetch xp tile for t=0
    {
        unsigned xb = smem_u32 + SM4_XS_OFF_B;
#pragma unroll
        for (int i = 0; i < 2; i++) {
            int u = tid + (i << 9);
            int b = u >> 3, q = u & 7;
            cpa16(xb + (unsigned)(b * SM4_LDSX + q * 4) * 4,
                  g_xp + (size_t)b * G4 + n0 + q * 4);
        }
        asm volatile("cp.async.commit_group;\n" ::: "memory");
    }
    __syncthreads();

    float creg[2];
    creg[0] = 0.f; creg[1] = 0.f;

    for (int t = 0; t < Tt; t++) {
        float acc[2][4][4];
#pragma unroll
        for (int i = 0; i < 2; i++)
#pragma unroll
            for (int j = 0; j < 4; j++)
#pragma unroll
                for (int k = 0; k < 4; k++) acc[i][j][k] = 0.f;

        if (t > 0) {
            // ---- per-warp acquire-wait on this k-quarter's 32 producers ----
            if (lane == 0) {
                const unsigned* cp = &g_syncq[kq];
                unsigned v;
                for (;;) {
                    asm volatile("ld.acquire.gpu.global.u32 %0, [%1];"
                                 : "=r"(v) : "l"(cp) : "memory");
                    if (v >= (unsigned)(32 * t)) break;
                    __nanosleep(32);
                }
            }
            __syncwarp();

            const __half* hp = g_hperm[(t - 1) & 1];
            // per-row uint4 pointers; block c -> index 4c (+lc base)
            const uint4* r0p = (const uint4*)(hp + (size_t)(wm + lr) * Hh + kb) + lc;
            const uint4* r1p = (const uint4*)(hp + (size_t)(wm + 8 + lr) * Hh + kb) + lc;
            const uint4* r2p = (const uint4*)(hp + (size_t)(wm + 16 + lr) * Hh + kb) + lc;
            const uint4* r3p = (const uint4*)(hp + (size_t)(wm + 24 + lr) * Hh + kb) + lc;

            uint4 A0[4], A1[4];
            A0[0] = __ldcg(r0p); A0[1] = __ldcg(r1p);
            A0[2] = __ldcg(r2p); A0[3] = __ldcg(r3p);

#pragma unroll
            for (int c = 0; c < 8; c++) {
                if (c < 7) {
                    A1[0] = __ldcg(r0p + 4 * (c + 1));
                    A1[1] = __ldcg(r1p + 4 * (c + 1));
                    A1[2] = __ldcg(r2p + 4 * (c + 1));
                    A1[3] = __ldcg(r3p + 4 * (c + 1));
                }
                // B fragments: one uint4 per n-tile (covers both 16k chunks)
                uint4 bb[4];
#pragma unroll
                for (int nt = 0; nt < 4; nt++) {
                    bb[nt] = *(const uint4*)(Ws + (size_t)(nt * 8 + lr) * SM4_WS_LDH
                                             + kb + c * 32 + 8 * lc);
                }
                // chunk 0 (x,y components)
#pragma unroll
                for (int nt = 0; nt < 4; nt++) {
                    mma_f16(acc[0][nt], A0[0].x, A0[1].x, A0[0].y, A0[1].y,
                            bb[nt].x, bb[nt].y);
                    mma_f16(acc[1][nt], A0[2].x, A0[3].x, A0[2].y, A0[3].y,
                            bb[nt].x, bb[nt].y);
                }
                // chunk 1 (z,w components)
#pragma unroll
                for (int nt = 0; nt < 4; nt++) {
                    mma_f16(acc[0][nt], A0[0].z, A0[1].z, A0[0].w, A0[1].w,
                            bb[nt].z, bb[nt].w);
                    mma_f16(acc[1][nt], A0[2].z, A0[3].z, A0[2].w, A0[3].w,
                            bb[nt].z, bb[nt].w);
                }
#pragma unroll
                for (int i = 0; i < 4; i++) A0[i] = A1[i];
            }
        }

        // stash partial gates to this k-quarter's buffer (32 rows per warp)
#pragma unroll
        for (int mt = 0; mt < 2; mt++) {
#pragma unroll
            for (int nt = 0; nt < 4; nt++) {
                int c = nt * 8 + 2 * lc;
                *(float2*)&GsW[(wm + mt * 16 + lr) * SM4_LDSG + c] =
                    make_float2(acc[mt][nt][0], acc[mt][nt][1]);
                *(float2*)&GsW[(wm + mt * 16 + 8 + lr) * SM4_LDSG + c] =
                    make_float2(acc[mt][nt][2], acc[mt][nt][3]);
            }
        }
        asm volatile("cp.async.wait_group 0;\n" ::: "memory");  // xp(t) resident
        __syncthreads();

        // ---- epilogue phase A: cell update + hperm write (critical path) ----
        __half* hpw = g_hperm[t & 1];
        float hv_s[2];
        int b_s[2], j_s[2];
#pragma unroll
        for (int i = 0; i < 2; i++) {
            int u = tid + (i << 9);
            int b = u >> 3;
            int jl = u & 7;
            float4 x4 = *(const float4*)&Xs[b * SM4_LDSX + (jl << 2)];
            float4 p0 = *(const float4*)&Gs[b * SM4_LDSG + (jl << 2)];
            float4 p1 = *(const float4*)&Gs[SM4_GS_STRIDE + b * SM4_LDSG + (jl << 2)];
            float4 p2 = *(const float4*)&Gs[2 * SM4_GS_STRIDE + b * SM4_LDSG + (jl << 2)];
            float4 p3 = *(const float4*)&Gs[3 * SM4_GS_STRIDE + b * SM4_LDSG + (jl << 2)];
            float gi = (p0.x + p1.x) + (p2.x + p3.x) + x4.x;
            float gf = (p0.y + p1.y) + (p2.y + p3.y) + x4.y;
            float gg = (p0.z + p1.z) + (p2.z + p3.z) + x4.z;
            float go = (p0.w + p1.w) + (p2.w + p3.w) + x4.w;
            float iv = fsigmoid(gi);
            float fv = fsigmoid(gf);
            float gv = ftanh(gg);
            float ov = fsigmoid(go);
            float cv = fv * creg[i] + iv * gv;
            creg[i] = cv;
            float hv = ov * ftanh(cv);
            int j = (n0 >> 2) + jl;
            hpw[b * Hh + hperm16(j)] = __float2half_rn(hv);
            hv_s[i] = hv; b_s[i] = b; j_s[i] = j;
        }

        // ---- arrive: one release-atomic on this CTA's quarter counter ----
        if (t < Tt - 1) {
            __syncthreads();           // all hperm writes issued, xp reads done
            if (tid == 0) {
                asm volatile("red.release.gpu.global.add.u32 [%0], %1;"
                             :: "l"(&g_syncq[bid >> 5]), "r"(1u) : "memory");
            }

            // xp(t+1) prefetch: maximize cp.async lead time
            const float* xpn = g_xp + (size_t)(t + 1) * Bb * G4;
            unsigned xb = smem_u32 + SM4_XS_OFF_B;
#pragma unroll
            for (int i = 0; i < 2; i++) {
                int u = tid + (i << 9);
                int b = u >> 3, q = u & 7;
                cpa16(xb + (unsigned)(b * SM4_LDSX + q * 4) * 4,
                      xpn + (size_t)b * G4 + n0 + q * 4);
            }
            asm volatile("cp.async.commit_group;\n" ::: "memory");
        }

        // ---- phase B: non-critical writes (streaming stores, overlap) ----
#pragma unroll
        for (int i = 0; i < 2; i++) {
            int b = b_s[i], j = j_s[i];
            float hv = hv_s[i];
            size_t hi = (size_t)t * Bb * Hh + b * Hh + j;
            if (L == 1) {
                __stcs(&g_h1[hi], hv);                           // residual source
                int kc = (j & ~31) + qperm(j & 31);
                __stcs(&g_aperm2[(size_t)(t * Bb + b) * Ii + kc],
                       __uint_as_float(f2tf(hv)));               // layer-2 GEMM A
            } else {
                float o11 = hv + g_h1[hi];
                __stcs(&dout[(size_t)TB * Hh + hi], o11);                            // out11
                __stcs(&dout[(size_t)2 * TB * Hh + ((size_t)(t * Bb + b)) * 2 * Hh + j],
                       o11);                                                          // out14[:,:H]
            }
        }
        // no tail barrier: next iteration's per-warp quarter-wait gates the GEMM
    }
}

// -------------------- launch --------------------
extern "C" void kernel_launch(void* const* d_in, const int* in_sizes, int n_in,
                              void* d_out, int out_size) {
    const float* input4 = (const float*)d_in[0];
    const float* input0 = (const float*)d_in[1];
    const float* w_ih6  = (const float*)d_in[2];
    const float* w_hh6  = (const float*)d_in[3];
    const float* b_ih6  = (const float*)d_in[4];
    const float* b_hh6  = (const float*)d_in[5];
    const float* w_ih10 = (const float*)d_in[6];
    const float* w_hh10 = (const float*)d_in[7];
    const float* b_ih10 = (const float*)d_in[8];
    const float* b_hh10 = (const float*)d_in[9];
    float* out = (float*)d_out;

    cudaFuncSetAttribute(lstm_layer<1>, cudaFuncAttributeMaxDynamicSharedMemorySize,
                         SM4_TOTAL_B);
    cudaFuncSetAttribute(lstm_layer<2>, cudaFuncAttributeMaxDynamicSharedMemorySize,
                         SM4_TOTAL_B);
    cudaFuncSetAttribute(gemm_xp<1>, cudaFuncAttributeMaxDynamicSharedMemorySize,
                         GEMM_SMEM_FL * 4);
    cudaFuncSetAttribute(gemm_xp<2>, cudaFuncAttributeMaxDynamicSharedMemorySize,
                         GEMM_SMEM_FL * 4);

    dim3 gx(G4 / 128, TB / 128);  // n-tile fastest -> A reuse in L2
    const int PW_GRID = (G4 * (Ii + Hh + 1)) / 256;  // 49168

    // launch order arranged so ncu's capture window lands on lstm_layer<1> (idx 3)
    permute_l<1><<<PW_GRID, 256>>>(w_ih6, w_hh6, b_ih6, b_hh6);      // 0
    prepA<<<(TB * Ii) / 256, 256>>>(input0, input4);                  // 1 (+ctr reset)
    gemm_xp<1><<<gx, 256, GEMM_SMEM_FL * 4>>>();                      // 2
    lstm_layer<1><<<NBLK, 512, SM4_TOTAL_B>>>(out);                   // 3 <- profile me
    permute_l<2><<<PW_GRID, 256>>>(w_ih10, w_hh10, b_ih10, b_hh10);   // 4 (+ctr reset)
    gemm_xp<2><<<gx, 256, GEMM_SMEM_FL * 4>>>();                      // 5
    lstm_layer<2><<<NBLK, 512, SM4_TOTAL_B>>>(out);                   // 6
    copy_out1<<<(TB * Hh / 4) / 256, 256>>>(input4, out);             // 7
}

// round 17
// speedup vs baseline: 1.8385x; 1.2329x over previous
#include <cuda_runtime.h>
#include <cuda_fp16.h>
#include <cstdint>

// ---------------------------------------------------------------------------
// Stage3 LSTM stack: out1 = input4
//                    out7 = LSTM1(concat(input0, input4))
//                    out11 = LSTM2(concat(out7, input4)) + out7
//                    out14 = concat(out11, input4)
// Outputs concatenated: [out1 (T*B*H)] [out11 (T*B*H)] [out14 (T*B*2H)]
// ---------------------------------------------------------------------------

#define Tt 128
#define Bb 128
#define Hh 1024
#define Ii 2048
#define G4 4096            // 4*H
#define TB 16384           // T*B
#define NBLK 128           // persistent blocks (1 per SM)

// -------------------- device scratch (no allocs allowed) --------------------
__device__ float g_whh1[G4 * Hh];   // gate-interleaved rows, natural cols, fp32
__device__ float g_whh2[G4 * Hh];
__device__ float g_b1[G4];
__device__ float g_b2[G4];
__device__ __align__(16) __half g_wih1h[G4 * Ii];  // gate-interleaved + hperm16, fp16
__device__ __align__(16) __half g_wih2h[G4 * Ii];
__device__ __align__(16) __half g_aperm1h[(size_t)TB * Ii];  // [in0|in4] fp16 hperm16
__device__ __align__(16) __half g_aperm2h[(size_t)TB * Ii];  // [h1|in4] fp16 hperm16
__device__ float g_xp[(size_t)TB * G4];      // input projection (fp32)
__device__ float g_h1[(size_t)TB * Hh];      // layer-1 h (natural layout, = out7)
__device__ __align__(16) __half g_hperm[2][Bb * Hh];  // ping-pong h, fp16, hperm16
__device__ unsigned g_syncq[4];              // per-k-quarter arrival counters

// -------------------- helpers --------------------
// fp16 mma m16n8k16, fp32 accumulate
static __device__ __forceinline__ void mma_f16(float c[4], unsigned a0, unsigned a1,
                                               unsigned a2, unsigned a3,
                                               unsigned b0, unsigned b1) {
    asm volatile(
        "mma.sync.aligned.m16n8k16.row.col.f32.f16.f16.f32 "
        "{%0,%1,%2,%3}, {%4,%5,%6,%7}, {%8,%9}, {%0,%1,%2,%3};\n"
        : "+f"(c[0]), "+f"(c[1]), "+f"(c[2]), "+f"(c[3])
        : "r"(a0), "r"(a1), "r"(a2), "r"(a3), "r"(b0), "r"(b1));
}

// fp16 permutation within a 32-wide K block: thread lc's 8 halves
// {2lc,2lc+1,2lc+8,2lc+9, +16 same} land contiguous -> one uint4 per load.
static __device__ __forceinline__ int hperm16(int k) {
    int c = (k >> 4) & 1, k4 = k & 15;
    int r = k4 & 1, cc = (k4 >> 1) & 3, s = (k4 >> 3) & 1;
    return (k & ~31) | (cc << 3) | (c << 2) | (s << 1) | r;
}

static __device__ __forceinline__ void cpa16(unsigned dst, const void* src) {
    asm volatile("cp.async.cg.shared.global [%0], [%1], 16;\n" :: "r"(dst), "l"(src));
}

// HW tanh (sm_75+ MUFU.TANH)
static __device__ __forceinline__ float htanh(float x) {
    float y;
    asm("tanh.approx.f32 %0, %1;" : "=f"(y) : "f"(x));
    return y;
}
static __device__ __forceinline__ float fsigmoid(float x) {
    return fmaf(htanh(0.5f * x), 0.5f, 0.5f);
}
static __device__ __forceinline__ float ftanh(float x) { return htanh(x); }

// -------------------- fused per-layer weight/bias permutation ----------------
template <int L>
__global__ void permute_l(const float* __restrict__ wih, const float* __restrict__ whh,
                          const float* __restrict__ bih, const float* __restrict__ bhh) {
    int idx = blockIdx.x * 256 + threadIdx.x;
    __half* wo = (L == 1) ? g_wih1h : g_wih2h;
    float* ho = (L == 1) ? g_whh1 : g_whh2;
    float* bo = (L == 1) ? g_b1 : g_b2;
    if (idx < G4 * Ii) {
        int n = idx >> 11, k = idx & 2047;
        int j = n >> 2, g = n & 3;
        float v = wih[((g * Hh + j) << 11) + k];
        wo[(n << 11) | hperm16(k)] = __float2half_rn(v);
    } else if (idx < G4 * Ii + G4 * Hh) {
        int i2 = idx - G4 * Ii;
        int n = i2 >> 10, k = i2 & 1023;
        int j = n >> 2, g = n & 3;
        ho[(n << 10) + k] = whh[((g * Hh + j) << 10) + k];
    } else {
        int n = idx - G4 * Ii - G4 * Hh;
        int j = n >> 2, g = n & 3;
        bo[n] = bih[g * Hh + j] + bhh[g * Hh + j];
        if (L == 2 && n < 4) g_syncq[n] = 0;   // reset counters for layer-2 pass
    }
}

// -------------------- A prepass: fp16 + hperm16 ------------------------------
__global__ void prepA(const float* __restrict__ in0, const float* __restrict__ in4) {
    int idx = blockIdx.x * 256 + threadIdx.x;
    if (idx < 4) g_syncq[idx] = 0;  // reset counters for layer-1 pass
    int row = idx >> 11;
    int k = idx & 2047;
    float v = (k < 1024) ? in0[(size_t)row * Hh + k]
                         : in4[(size_t)row * Hh + (k - 1024)];
    __half hv = __float2half_rn(v);
    int kp = hperm16(k);
    g_aperm1h[(size_t)row * Ii + kp] = hv;
    if (k >= 1024) g_aperm2h[(size_t)row * Ii + kp] = hv;
}

// -------------------- out1 + out14 second-half copy --------------------
__global__ void copy_out1(const float* __restrict__ in4, float* __restrict__ out) {
    size_t i4 = (size_t)blockIdx.x * 256 + threadIdx.x;
    size_t e = i4 * 4;
    float4 v = *(const float4*)(in4 + e);
    *(float4*)(out + e) = v;                       // out1
    size_t tb = e >> 10;
    size_t j = e & (Hh - 1);
    *(float4*)(out + (size_t)2 * TB * Hh + tb * 2 * Hh + Hh + j) = v;  // out14[:,H:]
}

// -------------------- big GEMM (fp16): xp = Aperm @ W'^T + bias' ------------
// Block tile 128x128x32(halves), 8 warps (4x2), warp tile 32x64.
// 3-stage cp.async pipeline, ONE __syncthreads per k-iteration.
// Row stride 40 halves (80B, 16B-aligned).
#define GH_LD 40                        // halves per smem row
#define GH_STG (128 * GH_LD)            // 5120 halves per stage per operand
#define GEMM_SMEM_B (6 * GH_STG * 2)    // 3 stages x (A,B) = 61440 bytes

template <int L>
__global__ void __launch_bounds__(256, 2)
gemm_xp() {
    const __half* Ah = (L == 1) ? g_aperm1h : g_aperm2h;
    const __half* Wh = (L == 1) ? g_wih1h : g_wih2h;
    const float* bias = (L == 1) ? g_b1 : g_b2;

    extern __shared__ __half smemh[];
    const unsigned smem_u32 = (unsigned)__cvta_generic_to_shared(smemh);

    const int tid = threadIdx.x;
    const int lane = tid & 31;
    const int warp = tid >> 5;
    const int wm = (warp >> 1) << 5;   // 0,32,64,96
    const int wn = (warp & 1) << 6;    // 0,64
    const int lr = lane >> 2, lc = lane & 3;
    const int m0 = blockIdx.y * 128;
    const int n0 = blockIdx.x * 128;

    float acc[2][8][4];
#pragma unroll
    for (int i = 0; i < 2; i++)
#pragma unroll
        for (int j = 0; j < 8; j++)
#pragma unroll
            for (int k = 0; k < 4; k++) acc[i][j][k] = 0.f;

    // cp.async fill coords: 512 16B-chunks per operand per stage;
    // idx -> row = idx>>2, ch = idx&3 (16B chunk within the 64B row)
    const int f0 = tid, f1 = tid + 256;
    const int r0 = f0 >> 2, c0 = f0 & 3;
    const int r1 = f1 >> 2, c1 = f1 & 3;
    const __half* Ag0 = Ah + (size_t)(m0 + r0) * Ii + c0 * 8;
    const __half* Ag1 = Ah + (size_t)(m0 + r1) * Ii + c1 * 8;
    const __half* Bg0 = Wh + (size_t)(n0 + r0) * Ii + c0 * 8;
    const __half* Bg1 = Wh + (size_t)(n0 + r1) * Ii + c1 * 8;
    const unsigned dA0 = (unsigned)(r0 * GH_LD + c0 * 8) * 2;
    const unsigned dA1 = (unsigned)(r1 * GH_LD + c1 * 8) * 2;

#pragma unroll
    for (int pc = 0; pc < 2; pc++) {
        unsigned sa = smem_u32 + (pc * 2 * GH_STG) * 2;
        unsigned sb = smem_u32 + (pc * 2 * GH_STG + GH_STG) * 2;
        cpa16(sa + dA0, Ag0 + pc * 32);
        cpa16(sa + dA1, Ag1 + pc * 32);
        cpa16(sb + dA0, Bg0 + pc * 32);
        cpa16(sb + dA1, Bg1 + pc * 32);
        asm volatile("cp.async.commit_group;\n" ::: "memory");
    }

    for (int kc = 0; kc < 64; kc++) {
        if (kc < 62) {
            asm volatile("cp.async.wait_group 1;\n" ::: "memory");
        } else {
            asm volatile("cp.async.wait_group 0;\n" ::: "memory");
        }
        __syncthreads();   // also separates compute(kc-1) reads from cp below

        if (kc < 62) {
            int nc = kc + 2;
            int st = nc % 3;
            unsigned sa = smem_u32 + (st * 2 * GH_STG) * 2;
            unsigned sb = smem_u32 + (st * 2 * GH_STG + GH_STG) * 2;
            cpa16(sa + dA0, Ag0 + nc * 32);
            cpa16(sa + dA1, Ag1 + nc * 32);
            cpa16(sb + dA0, Bg0 + nc * 32);
            cpa16(sb + dA1, Bg1 + nc * 32);
            asm volatile("cp.async.commit_group;\n" ::: "memory");
        }

        const __half* Ast = smemh + (kc % 3) * 2 * GH_STG;
        const __half* Bst = Ast + GH_STG;

        // A fragments: 2 m-tiles x 2 row-groups -> 4 uint4
        uint4 av[4];
#pragma unroll
        for (int mt = 0; mt < 2; mt++) {
            av[2 * mt]     = *(const uint4*)(Ast + (wm + mt * 16 + lr) * GH_LD + lc * 8);
            av[2 * mt + 1] = *(const uint4*)(Ast + (wm + mt * 16 + 8 + lr) * GH_LD + lc * 8);
        }

        // B in nt-pairs
#pragma unroll
        for (int nt2 = 0; nt2 < 4; nt2++) {
            uint4 bv0 = *(const uint4*)(Bst + (wn + (2 * nt2) * 8 + lr) * GH_LD + lc * 8);
            uint4 bv1 = *(const uint4*)(Bst + (wn + (2 * nt2 + 1) * 8 + lr) * GH_LD + lc * 8);
#pragma unroll
            for (int mt = 0; mt < 2; mt++) {
                // k-chunk 0 (.x,.y), k-chunk 1 (.z,.w)
                mma_f16(acc[mt][2 * nt2], av[2 * mt].x, av[2 * mt + 1].x,
                        av[2 * mt].y, av[2 * mt + 1].y, bv0.x, bv0.y);
                mma_f16(acc[mt][2 * nt2 + 1], av[2 * mt].x, av[2 * mt + 1].x,
                        av[2 * mt].y, av[2 * mt + 1].y, bv1.x, bv1.y);
                mma_f16(acc[mt][2 * nt2], av[2 * mt].z, av[2 * mt + 1].z,
                        av[2 * mt].w, av[2 * mt + 1].w, bv0.z, bv0.w);
                mma_f16(acc[mt][2 * nt2 + 1], av[2 * mt].z, av[2 * mt + 1].z,
                        av[2 * mt].w, av[2 * mt + 1].w, bv1.z, bv1.w);
            }
        }
    }

#pragma unroll
    for (int mt = 0; mt < 2; mt++) {
        int r = m0 + wm + mt * 16 + lr;
#pragma unroll
        for (int nt = 0; nt < 8; nt++) {
            int c = n0 + wn + nt * 8 + 2 * lc;
            float2 bv = *(const float2*)&bias[c];
            float2 v0 = make_float2(acc[mt][nt][0] + bv.x, acc[mt][nt][1] + bv.y);
            float2 v1 = make_float2(acc[mt][nt][2] + bv.x, acc[mt][nt][3] + bv.y);
            *(float2*)&g_xp[(size_t)r * G4 + c] = v0;
            *(float2*)&g_xp[(size_t)(r + 8) * G4 + c] = v1;
        }
    }
}

// -------------------- persistent recurrent layer (fp16 operands) -----------
#define SM4_WS_LDH 1056                 // Ws row stride halves (2112B, %128B==64)
#define SM4_WS_B   (32 * SM4_WS_LDH * 2)        // 67584 bytes
#define SM4_LDSG 36                     // Gs row stride (floats)
#define SM4_GS_STRIDE (128 * SM4_LDSG)  // 4608 floats per Gs buffer
#define SM4_GS_OFF_B SM4_WS_B                   // 67584 (16B-aligned)
#define SM4_LDSX 32                     // xp row stride (floats)
#define SM4_XS_OFF_B (SM4_GS_OFF_B + 4 * SM4_GS_STRIDE * 4)   // 141312
#define SM4_TOTAL_B (SM4_XS_OFF_B + 128 * SM4_LDSX * 4)       // 157696 bytes

template <int L>
__global__ void __launch_bounds__(512, 1)
lstm_layer(float* __restrict__ dout) {
    extern __shared__ char smraw[];
    __half* Ws = (__half*)smraw;
    float* Gs = (float*)(smraw + SM4_GS_OFF_B);
    float* Xs = (float*)(smraw + SM4_XS_OFF_B);
    const unsigned smem_u32 = (unsigned)__cvta_generic_to_shared(smraw);

    const int tid = threadIdx.x;
    const int bid = blockIdx.x;
    const int lane = tid & 31;
    const int warp = tid >> 5;         // 0..15
    const int mq = warp >> 2;          // m-group 0..3 (32 batch rows each)
    const int kq = warp & 3;           // k-quarter 0..3 (256 k each)
    const int wm = mq << 5;            // batch row base
    const int kb = kq << 8;            // k base
    const int lr = lane >> 2, lc = lane & 3;
    const int n0 = bid * 32;           // gate-col base
    float* GsW = Gs + kq * SM4_GS_STRIDE;

    const float* Wg = (L == 1) ? g_whh1 : g_whh2;

    // load W slice into smem as fp16 with the f16 block permutation
    for (int idx = tid; idx < 32 * 1024; idx += 512) {
        int n = idx >> 10;
        int k = idx & 1023;
        Ws[n * SM4_WS_LDH + hperm16(k)] =
            __float2half_rn(Wg[(size_t)(n0 + n) * Hh + k]);
    }
    // prefetch xp tile for t=0
    {
        unsigned xb = smem_u32 + SM4_XS_OFF_B;
#pragma unroll
        for (int i = 0; i < 2; i++) {
            int u = tid + (i << 9);
            int b = u >> 3, q = u & 7;
            cpa16(xb + (unsigned)(b * SM4_LDSX + q * 4) * 4,
                  g_xp + (size_t)b * G4 + n0 + q * 4);
        }
        asm volatile("cp.async.commit_group;\n" ::: "memory");
    }
    __syncthreads();

    float creg[2];
    creg[0] = 0.f; creg[1] = 0.f;

    for (int t = 0; t < Tt; t++) {
        float acc[2][4][4];
#pragma unroll
        for (int i = 0; i < 2; i++)
#pragma unroll
            for (int j = 0; j < 4; j++)
#pragma unroll
                for (int k = 0; k < 4; k++) acc[i][j][k] = 0.f;

        if (t > 0) {
            // ---- per-warp acquire-wait on this k-quarter's 32 producers ----
            if (lane == 0) {
                const unsigned* cp = &g_syncq[kq];
                unsigned v;
                for (;;) {
                    asm volatile("ld.acquire.gpu.global.u32 %0, [%1];"
                                 : "=r"(v) : "l"(cp) : "memory");
                    if (v >= (unsigned)(32 * t)) break;
                    __nanosleep(32);
                }
            }
            __syncwarp();

            const __half* hp = g_hperm[(t - 1) & 1];
            const uint4* r0p = (const uint4*)(hp + (size_t)(wm + lr) * Hh + kb) + lc;
            const uint4* r1p = (const uint4*)(hp + (size_t)(wm + 8 + lr) * Hh + kb) + lc;
            const uint4* r2p = (const uint4*)(hp + (size_t)(wm + 16 + lr) * Hh + kb) + lc;
            const uint4* r3p = (const uint4*)(hp + (size_t)(wm + 24 + lr) * Hh + kb) + lc;

            uint4 A0[4], A1[4];
            A0[0] = __ldcg(r0p); A0[1] = __ldcg(r1p);
            A0[2] = __ldcg(r2p); A0[3] = __ldcg(r3p);

#pragma unroll
            for (int c = 0; c < 8; c++) {
                if (c < 7) {
                    A1[0] = __ldcg(r0p + 4 * (c + 1));
                    A1[1] = __ldcg(r1p + 4 * (c + 1));
                    A1[2] = __ldcg(r2p + 4 * (c + 1));
                    A1[3] = __ldcg(r3p + 4 * (c + 1));
                }
                uint4 bb[4];
#pragma unroll
                for (int nt = 0; nt < 4; nt++) {
                    bb[nt] = *(const uint4*)(Ws + (size_t)(nt * 8 + lr) * SM4_WS_LDH
                                             + kb + c * 32 + 8 * lc);
                }
#pragma unroll
                for (int nt = 0; nt < 4; nt++) {
                    mma_f16(acc[0][nt], A0[0].x, A0[1].x, A0[0].y, A0[1].y,
                            bb[nt].x, bb[nt].y);
                    mma_f16(acc[1][nt], A0[2].x, A0[3].x, A0[2].y, A0[3].y,
                            bb[nt].x, bb[nt].y);
                }
#pragma unroll
                for (int nt = 0; nt < 4; nt++) {
                    mma_f16(acc[0][nt], A0[0].z, A0[1].z, A0[0].w, A0[1].w,
                            bb[nt].z, bb[nt].w);
                    mma_f16(acc[1][nt], A0[2].z, A0[3].z, A0[2].w, A0[3].w,
                            bb[nt].z, bb[nt].w);
                }
#pragma unroll
                for (int i = 0; i < 4; i++) A0[i] = A1[i];
            }
        }

        // stash partial gates to this k-quarter's buffer (32 rows per warp)
#pragma unroll
        for (int mt = 0; mt < 2; mt++) {
#pragma unroll
            for (int nt = 0; nt < 4; nt++) {
                int c = nt * 8 + 2 * lc;
                *(float2*)&GsW[(wm + mt * 16 + lr) * SM4_LDSG + c] =
                    make_float2(acc[mt][nt][0], acc[mt][nt][1]);
                *(float2*)&GsW[(wm + mt * 16 + 8 + lr) * SM4_LDSG + c] =
                    make_float2(acc[mt][nt][2], acc[mt][nt][3]);
            }
        }
        asm volatile("cp.async.wait_group 0;\n" ::: "memory");  // xp(t) resident
        __syncthreads();

        // ---- epilogue phase A: cell update + hperm write (critical path) ----
        __half* hpw = g_hperm[t & 1];
        float hv_s[2];
        int b_s[2], j_s[2];
#pragma unroll
        for (int i = 0; i < 2; i++) {
            int u = tid + (i << 9);
            int b = u >> 3;
            int jl = u & 7;
            float4 x4 = *(const float4*)&Xs[b * SM4_LDSX + (jl << 2)];
            float4 p0 = *(const float4*)&Gs[b * SM4_LDSG + (jl << 2)];
            float4 p1 = *(const float4*)&Gs[SM4_GS_STRIDE + b * SM4_LDSG + (jl << 2)];
            float4 p2 = *(const float4*)&Gs[2 * SM4_GS_STRIDE + b * SM4_LDSG + (jl << 2)];
            float4 p3 = *(const float4*)&Gs[3 * SM4_GS_STRIDE + b * SM4_LDSG + (jl << 2)];
            float gi = (p0.x + p1.x) + (p2.x + p3.x) + x4.x;
            float gf = (p0.y + p1.y) + (p2.y + p3.y) + x4.y;
            float gg = (p0.z + p1.z) + (p2.z + p3.z) + x4.z;
            float go = (p0.w + p1.w) + (p2.w + p3.w) + x4.w;
            float iv = fsigmoid(gi);
            float fv = fsigmoid(gf);
            float gv = ftanh(gg);
            float ov = fsigmoid(go);
            float cv = fv * creg[i] + iv * gv;
            creg[i] = cv;
            float hv = ov * ftanh(cv);
            int j = (n0 >> 2) + jl;
            hpw[b * Hh + hperm16(j)] = __float2half_rn(hv);
            hv_s[i] = hv; b_s[i] = b; j_s[i] = j;
        }

        // ---- arrive: one release-atomic on this CTA's quarter counter ----
        if (t < Tt - 1) {
            __syncthreads();           // all hperm writes issued, xp reads done
            if (tid == 0) {
                asm volatile("red.release.gpu.global.add.u32 [%0], %1;"
                             :: "l"(&g_syncq[bid >> 5]), "r"(1u) : "memory");
            }

            // xp(t+1) prefetch: maximize cp.async lead time
            const float* xpn = g_xp + (size_t)(t + 1) * Bb * G4;
            unsigned xb = smem_u32 + SM4_XS_OFF_B;
#pragma unroll
            for (int i = 0; i < 2; i++) {
                int u = tid + (i << 9);
                int b = u >> 3, q = u & 7;
                cpa16(xb + (unsigned)(b * SM4_LDSX + q * 4) * 4,
                      xpn + (size_t)b * G4 + n0 + q * 4);
            }
            asm volatile("cp.async.commit_group;\n" ::: "memory");
        }

        // ---- phase B: non-critical writes (streaming stores, overlap) ----
#pragma unroll
        for (int i = 0; i < 2; i++) {
            int b = b_s[i], j = j_s[i];
            float hv = hv_s[i];
            size_t hi = (size_t)t * Bb * Hh + b * Hh + j;
            if (L == 1) {
                __stcs(&g_h1[hi], hv);                           // residual source
                // layer-2 GEMM A operand (h half), fp16 hperm16 layout
                g_aperm2h[(size_t)(t * Bb + b) * Ii + hperm16(j)] =
                    __float2half_rn(hv);
            } else {
                float o11 = hv + g_h1[hi];
                __stcs(&dout[(size_t)TB * Hh + hi], o11);                            // out11
                __stcs(&dout[(size_t)2 * TB * Hh + ((size_t)(t * Bb + b)) * 2 * Hh + j],
                       o11);                                                          // out14[:,:H]
            }
        }
        // no tail barrier: next iteration's per-warp quarter-wait gates the GEMM
    }
}

// -------------------- launch --------------------
extern "C" void kernel_launch(void* const* d_in, const int* in_sizes, int n_in,
                              void* d_out, int out_size) {
    const float* input4 = (const float*)d_in[0];
    const float* input0 = (const float*)d_in[1];
    const float* w_ih6  = (const float*)d_in[2];
    const float* w_hh6  = (const float*)d_in[3];
    const float* b_ih6  = (const float*)d_in[4];
    const float* b_hh6  = (const float*)d_in[5];
    const float* w_ih10 = (const float*)d_in[6];
    const float* w_hh10 = (const float*)d_in[7];
    const float* b_ih10 = (const float*)d_in[8];
    const float* b_hh10 = (const float*)d_in[9];
    float* out = (float*)d_out;

    cudaFuncSetAttribute(lstm_layer<1>, cudaFuncAttributeMaxDynamicSharedMemorySize,
                         SM4_TOTAL_B);
    cudaFuncSetAttribute(lstm_layer<2>, cudaFuncAttributeMaxDynamicSharedMemorySize,
                         SM4_TOTAL_B);
    cudaFuncSetAttribute(gemm_xp<1>, cudaFuncAttributeMaxDynamicSharedMemorySize,
                         GEMM_SMEM_B);
    cudaFuncSetAttribute(gemm_xp<2>, cudaFuncAttributeMaxDynamicSharedMemorySize,
                         GEMM_SMEM_B);

    dim3 gx(G4 / 128, TB / 128);  // n-tile fastest -> A reuse in L2
    const int PW_GRID = (G4 * (Ii + Hh + 1)) / 256;  // 49168

    // launch order arranged so ncu's capture window lands on lstm_layer<1> (idx 3)
    permute_l<1><<<PW_GRID, 256>>>(w_ih6, w_hh6, b_ih6, b_hh6);      // 0
    prepA<<<(TB * Ii) / 256, 256>>>(input0, input4);                  // 1 (+ctr reset)
    gemm_xp<1><<<gx, 256, GEMM_SMEM_B>>>();                           // 2
    lstm_layer<1><<<NBLK, 512, SM4_TOTAL_B>>>(out);                   // 3 <- profile me
    permute_l<2><<<PW_GRID, 256>>>(w_ih10, w_hh10, b_ih10, b_hh10);   // 4 (+ctr reset)
    gemm_xp<2><<<gx, 256, GEMM_SMEM_B>>>();                           // 5
    lstm_layer<2><<<NBLK, 512, SM4_TOTAL_B>>>(out);                   // 6
    copy_out1<<<(TB * Hh / 4) / 256, 256>>>(input4, out);             // 7
}